// round 3
// baseline (speedup 1.0000x reference)
#include <cuda_runtime.h>

#define N_NODES 50000
#define N_EDGES 500000
#define D 128
#define EPB 4   // edges (or nodes) per block

// scratch for segment-summed messages m_i  (25.6 MB, static device global: allowed)
__device__ float g_mi[N_NODES * D];

__device__ __forceinline__ float silu(float x) { return x / (1.0f + __expf(-x)); }

// ---------------------------------------------------------------------------
__global__ void zero_mi_kernel() {
    int i = blockIdx.x * blockDim.x + threadIdx.x;
    if (i < N_NODES * D / 4)
        reinterpret_cast<float4*>(g_mi)[i] = make_float4(0.f, 0.f, 0.f, 0.f);
}

// ---------------------------------------------------------------------------
// vel_weights MLP + coord_out base = coord + vel * vw
__global__ __launch_bounds__(128) void node_pre_kernel(
    const float* __restrict__ h, const float* __restrict__ coord,
    const float* __restrict__ vel,
    const float* __restrict__ Wv1, const float* __restrict__ bv1,
    const float* __restrict__ Wv2, const float* __restrict__ bv2,
    float* __restrict__ coord_out)
{
    __shared__ __align__(16) float s_h[EPB][D];
    __shared__ float s_red[4][EPB];
    __shared__ float s_vw[EPB];
    int t = threadIdx.x;
    int lane = t & 31, wid = t >> 5;
    int n0 = blockIdx.x * EPB;

    #pragma unroll
    for (int e = 0; e < EPB; e++) s_h[e][t] = h[(n0 + e) * D + t];
    __syncthreads();

    float acc[EPB];
    { float b = bv1[t];
      #pragma unroll
      for (int e = 0; e < EPB; e++) acc[e] = b; }
    for (int kg = 0; kg < D / 4; kg++) {
        float w0 = Wv1[(4 * kg + 0) * D + t];
        float w1 = Wv1[(4 * kg + 1) * D + t];
        float w2 = Wv1[(4 * kg + 2) * D + t];
        float w3 = Wv1[(4 * kg + 3) * D + t];
        #pragma unroll
        for (int e = 0; e < EPB; e++) {
            float4 x = *reinterpret_cast<const float4*>(&s_h[e][4 * kg]);
            acc[e] = fmaf(x.x, w0, acc[e]);
            acc[e] = fmaf(x.y, w1, acc[e]);
            acc[e] = fmaf(x.z, w2, acc[e]);
            acc[e] = fmaf(x.w, w3, acc[e]);
        }
    }
    float wc = Wv2[t];
    float part[EPB];
    #pragma unroll
    for (int e = 0; e < EPB; e++) part[e] = silu(acc[e]) * wc;
    #pragma unroll
    for (int off = 16; off > 0; off >>= 1) {
        #pragma unroll
        for (int e = 0; e < EPB; e++)
            part[e] += __shfl_down_sync(0xffffffffu, part[e], off);
    }
    if (lane == 0) {
        #pragma unroll
        for (int e = 0; e < EPB; e++) s_red[wid][e] = part[e];
    }
    __syncthreads();
    if (t < EPB)
        s_vw[t] = s_red[0][t] + s_red[1][t] + s_red[2][t] + s_red[3][t] + bv2[0];
    __syncthreads();
    if (t < EPB * 3) {
        int e = t / 3, i = t % 3;
        int idx = (n0 + e) * 3 + i;
        coord_out[idx] = coord[idx] + vel[idx] * s_vw[e];
    }
}

// ---------------------------------------------------------------------------
// per-edge: gather, 3-layer MLP chain, scatter (coords + messages)
__global__ __launch_bounds__(128) void edge_kernel(
    const float* __restrict__ h, const float* __restrict__ coord,
    const int* __restrict__ ei,
    const float* __restrict__ We1, const float* __restrict__ be1,
    const float* __restrict__ We2, const float* __restrict__ be2,
    const float* __restrict__ Wc1, const float* __restrict__ bc1,
    const float* __restrict__ Wc2, const float* __restrict__ bc2,
    float* __restrict__ coord_out)
{
    __shared__ __align__(16) float s_in[EPB][260];   // [h_r | h_c | rad | pad]
    __shared__ __align__(16) float s_a[EPB][D];
    __shared__ float s_red[4][EPB];
    __shared__ float s_diff[EPB][3];
    __shared__ int   s_r[EPB];
    int t = threadIdx.x;
    int lane = t & 31, wid = t >> 5;
    int e0 = blockIdx.x * EPB;

    int r[EPB], c[EPB];
    #pragma unroll
    for (int e = 0; e < EPB; e++) {
        r[e] = ei[e0 + e];
        c[e] = ei[N_EDGES + e0 + e];
    }
    #pragma unroll
    for (int e = 0; e < EPB; e++) {
        s_in[e][t]     = h[r[e] * D + t];
        s_in[e][D + t] = h[c[e] * D + t];
    }
    if (t < EPB) {
        int e = t;
        float dx = coord[r[e] * 3 + 0] - coord[c[e] * 3 + 0];
        float dy = coord[r[e] * 3 + 1] - coord[c[e] * 3 + 1];
        float dz = coord[r[e] * 3 + 2] - coord[c[e] * 3 + 2];
        float rad = dx * dx + dy * dy + dz * dz;
        float inv = 1.0f / (sqrtf(rad) + 1e-8f);
        s_in[e][256] = rad;
        s_in[e][257] = 0.f; s_in[e][258] = 0.f; s_in[e][259] = 0.f;
        s_diff[e][0] = dx * inv; s_diff[e][1] = dy * inv; s_diff[e][2] = dz * inv;
        s_r[e] = r[e];
    }
    __syncthreads();

    // --- layer 1: edge_in[257] @ We1 -> silu -> s_a ---
    float acc[EPB];
    { float b = be1[t];
      #pragma unroll
      for (int e = 0; e < EPB; e++) acc[e] = b; }
    for (int kg = 0; kg < 64; kg++) {
        float w0 = We1[(4 * kg + 0) * D + t];
        float w1 = We1[(4 * kg + 1) * D + t];
        float w2 = We1[(4 * kg + 2) * D + t];
        float w3 = We1[(4 * kg + 3) * D + t];
        #pragma unroll
        for (int e = 0; e < EPB; e++) {
            float4 x = *reinterpret_cast<const float4*>(&s_in[e][4 * kg]);
            acc[e] = fmaf(x.x, w0, acc[e]);
            acc[e] = fmaf(x.y, w1, acc[e]);
            acc[e] = fmaf(x.z, w2, acc[e]);
            acc[e] = fmaf(x.w, w3, acc[e]);
        }
    }
    { float w = We1[256 * D + t];   // rad term (k = 256)
      #pragma unroll
      for (int e = 0; e < EPB; e++) acc[e] = fmaf(s_in[e][256], w, acc[e]); }
    #pragma unroll
    for (int e = 0; e < EPB; e++) s_a[e][t] = silu(acc[e]);
    __syncthreads();

    // --- layer 2: s_a @ We2 -> silu -> m_ij ---
    float m[EPB];
    { float b = be2[t];
      #pragma unroll
      for (int e = 0; e < EPB; e++) acc[e] = b; }
    for (int kg = 0; kg < 32; kg++) {
        float w0 = We2[(4 * kg + 0) * D + t];
        float w1 = We2[(4 * kg + 1) * D + t];
        float w2 = We2[(4 * kg + 2) * D + t];
        float w3 = We2[(4 * kg + 3) * D + t];
        #pragma unroll
        for (int e = 0; e < EPB; e++) {
            float4 x = *reinterpret_cast<const float4*>(&s_a[e][4 * kg]);
            acc[e] = fmaf(x.x, w0, acc[e]);
            acc[e] = fmaf(x.y, w1, acc[e]);
            acc[e] = fmaf(x.z, w2, acc[e]);
            acc[e] = fmaf(x.w, w3, acc[e]);
        }
    }
    #pragma unroll
    for (int e = 0; e < EPB; e++) m[e] = silu(acc[e]);
    __syncthreads();                      // everyone done reading layer-1 s_a
    #pragma unroll
    for (int e = 0; e < EPB; e++) s_a[e][t] = m[e];   // m_ij into smem
    __syncthreads();

    // --- layer 3: m_ij @ Wc1 -> silu -> dot with Wc2 (scalar weight) ---
    { float b = bc1[t];
      #pragma unroll
      for (int e = 0; e < EPB; e++) acc[e] = b; }
    for (int kg = 0; kg < 32; kg++) {
        float w0 = Wc1[(4 * kg + 0) * D + t];
        float w1 = Wc1[(4 * kg + 1) * D + t];
        float w2 = Wc1[(4 * kg + 2) * D + t];
        float w3 = Wc1[(4 * kg + 3) * D + t];
        #pragma unroll
        for (int e = 0; e < EPB; e++) {
            float4 x = *reinterpret_cast<const float4*>(&s_a[e][4 * kg]);
            acc[e] = fmaf(x.x, w0, acc[e]);
            acc[e] = fmaf(x.y, w1, acc[e]);
            acc[e] = fmaf(x.z, w2, acc[e]);
            acc[e] = fmaf(x.w, w3, acc[e]);
        }
    }
    float wc = Wc2[t];
    float part[EPB];
    #pragma unroll
    for (int e = 0; e < EPB; e++) part[e] = silu(acc[e]) * wc;
    #pragma unroll
    for (int off = 16; off > 0; off >>= 1) {
        #pragma unroll
        for (int e = 0; e < EPB; e++)
            part[e] += __shfl_down_sync(0xffffffffu, part[e], off);
    }
    if (lane == 0) {
        #pragma unroll
        for (int e = 0; e < EPB; e++) s_red[wid][e] = part[e];
    }
    __syncthreads();
    if (t < EPB) {
        int e = t;
        float wgt = s_red[0][e] + s_red[1][e] + s_red[2][e] + s_red[3][e] + bc2[0];
        int rr = s_r[e];
        atomicAdd(&coord_out[rr * 3 + 0], s_diff[e][0] * wgt);
        atomicAdd(&coord_out[rr * 3 + 1], s_diff[e][1] * wgt);
        atomicAdd(&coord_out[rr * 3 + 2], s_diff[e][2] * wgt);
    }
    // m_i segment sum
    #pragma unroll
    for (int e = 0; e < EPB; e++) atomicAdd(&g_mi[r[e] * D + t], m[e]);
}

// ---------------------------------------------------------------------------
// node_op: [h, m_i] @ Wn1 -> silu -> @ Wn2  (no final activation)
__global__ __launch_bounds__(128) void node_post_kernel(
    const float* __restrict__ h,
    const float* __restrict__ Wn1, const float* __restrict__ bn1,
    const float* __restrict__ Wn2, const float* __restrict__ bn2,
    float* __restrict__ h_out)
{
    __shared__ __align__(16) float s_in[EPB][2 * D];
    __shared__ __align__(16) float s_a[EPB][D];
    int t = threadIdx.x;
    int n0 = blockIdx.x * EPB;

    #pragma unroll
    for (int e = 0; e < EPB; e++) {
        s_in[e][t]     = h[(n0 + e) * D + t];
        s_in[e][D + t] = g_mi[(n0 + e) * D + t];
    }
    __syncthreads();

    float acc[EPB];
    { float b = bn1[t];
      #pragma unroll
      for (int e = 0; e < EPB; e++) acc[e] = b; }
    for (int kg = 0; kg < 64; kg++) {
        float w0 = Wn1[(4 * kg + 0) * D + t];
        float w1 = Wn1[(4 * kg + 1) * D + t];
        float w2 = Wn1[(4 * kg + 2) * D + t];
        float w3 = Wn1[(4 * kg + 3) * D + t];
        #pragma unroll
        for (int e = 0; e < EPB; e++) {
            float4 x = *reinterpret_cast<const float4*>(&s_in[e][4 * kg]);
            acc[e] = fmaf(x.x, w0, acc[e]);
            acc[e] = fmaf(x.y, w1, acc[e]);
            acc[e] = fmaf(x.z, w2, acc[e]);
            acc[e] = fmaf(x.w, w3, acc[e]);
        }
    }
    #pragma unroll
    for (int e = 0; e < EPB; e++) s_a[e][t] = silu(acc[e]);
    __syncthreads();

    { float b = bn2[t];
      #pragma unroll
      for (int e = 0; e < EPB; e++) acc[e] = b; }
    for (int kg = 0; kg < 32; kg++) {
        float w0 = Wn2[(4 * kg + 0) * D + t];
        float w1 = Wn2[(4 * kg + 1) * D + t];
        float w2 = Wn2[(4 * kg + 2) * D + t];
        float w3 = Wn2[(4 * kg + 3) * D + t];
        #pragma unroll
        for (int e = 0; e < EPB; e++) {
            float4 x = *reinterpret_cast<const float4*>(&s_a[e][4 * kg]);
            acc[e] = fmaf(x.x, w0, acc[e]);
            acc[e] = fmaf(x.y, w1, acc[e]);
            acc[e] = fmaf(x.z, w2, acc[e]);
            acc[e] = fmaf(x.w, w3, acc[e]);
        }
    }
    #pragma unroll
    for (int e = 0; e < EPB; e++) h_out[(n0 + e) * D + t] = acc[e];
}

// ---------------------------------------------------------------------------
extern "C" void kernel_launch(void* const* d_in, const int* in_sizes, int n_in,
                              void* d_out, int out_size)
{
    const float* h     = (const float*)d_in[0];
    const float* coord = (const float*)d_in[1];
    const float* vel   = (const float*)d_in[2];
    const int*   ei    = (const int*)  d_in[3];
    const float* We1 = (const float*)d_in[4];  const float* be1 = (const float*)d_in[5];
    const float* We2 = (const float*)d_in[6];  const float* be2 = (const float*)d_in[7];
    const float* Wc1 = (const float*)d_in[8];  const float* bc1 = (const float*)d_in[9];
    const float* Wc2 = (const float*)d_in[10]; const float* bc2 = (const float*)d_in[11];
    const float* Wv1 = (const float*)d_in[12]; const float* bv1 = (const float*)d_in[13];
    const float* Wv2 = (const float*)d_in[14]; const float* bv2 = (const float*)d_in[15];
    const float* Wn1 = (const float*)d_in[16]; const float* bn1 = (const float*)d_in[17];
    const float* Wn2 = (const float*)d_in[18]; const float* bn2 = (const float*)d_in[19];

    float* h_out     = (float*)d_out;                  // [N, 128]
    float* coord_out = (float*)d_out + N_NODES * D;    // [N, 3]

    zero_mi_kernel<<<(N_NODES * D / 4 + 255) / 256, 256>>>();
    node_pre_kernel<<<N_NODES / EPB, 128>>>(h, coord, vel, Wv1, bv1, Wv2, bv2, coord_out);
    edge_kernel<<<N_EDGES / EPB, 128>>>(h, coord, ei,
                                        We1, be1, We2, be2,
                                        Wc1, bc1, Wc2, bc2,
                                        coord_out);
    node_post_kernel<<<N_NODES / EPB, 128>>>(h, Wn1, bn1, Wn2, bn2, h_out);
}

// round 4
// speedup vs baseline: 1.0006x; 1.0006x over previous
#include <cuda_runtime.h>

#define N_NODES 50000
#define N_EDGES 500000
#define D 128
#define EPB 4   // edges (or nodes) per block

// scratch for segment-summed messages m_i  (25.6 MB, static device global: allowed)
__device__ float g_mi[N_NODES * D];

__device__ __forceinline__ float silu(float x) { return x / (1.0f + __expf(-x)); }

// ---------------------------------------------------------------------------
__global__ void zero_mi_kernel() {
    int i = blockIdx.x * blockDim.x + threadIdx.x;
    if (i < N_NODES * D / 4)
        reinterpret_cast<float4*>(g_mi)[i] = make_float4(0.f, 0.f, 0.f, 0.f);
}

// ---------------------------------------------------------------------------
// vel_weights MLP + coord_out base = coord + vel * vw
__global__ __launch_bounds__(128) void node_pre_kernel(
    const float* __restrict__ h, const float* __restrict__ coord,
    const float* __restrict__ vel,
    const float* __restrict__ Wv1, const float* __restrict__ bv1,
    const float* __restrict__ Wv2, const float* __restrict__ bv2,
    float* __restrict__ coord_out)
{
    __shared__ __align__(16) float s_h[EPB][D];
    __shared__ float s_red[4][EPB];
    __shared__ float s_vw[EPB];
    int t = threadIdx.x;
    int lane = t & 31, wid = t >> 5;
    int n0 = blockIdx.x * EPB;

    #pragma unroll
    for (int e = 0; e < EPB; e++) s_h[e][t] = h[(n0 + e) * D + t];
    __syncthreads();

    float acc[EPB];
    { float b = bv1[t];
      #pragma unroll
      for (int e = 0; e < EPB; e++) acc[e] = b; }
    for (int kg = 0; kg < D / 4; kg++) {
        float w0 = Wv1[(4 * kg + 0) * D + t];
        float w1 = Wv1[(4 * kg + 1) * D + t];
        float w2 = Wv1[(4 * kg + 2) * D + t];
        float w3 = Wv1[(4 * kg + 3) * D + t];
        #pragma unroll
        for (int e = 0; e < EPB; e++) {
            float4 x = *reinterpret_cast<const float4*>(&s_h[e][4 * kg]);
            acc[e] = fmaf(x.x, w0, acc[e]);
            acc[e] = fmaf(x.y, w1, acc[e]);
            acc[e] = fmaf(x.z, w2, acc[e]);
            acc[e] = fmaf(x.w, w3, acc[e]);
        }
    }
    float wc = Wv2[t];
    float part[EPB];
    #pragma unroll
    for (int e = 0; e < EPB; e++) part[e] = silu(acc[e]) * wc;
    #pragma unroll
    for (int off = 16; off > 0; off >>= 1) {
        #pragma unroll
        for (int e = 0; e < EPB; e++)
            part[e] += __shfl_down_sync(0xffffffffu, part[e], off);
    }
    if (lane == 0) {
        #pragma unroll
        for (int e = 0; e < EPB; e++) s_red[wid][e] = part[e];
    }
    __syncthreads();
    if (t < EPB)
        s_vw[t] = s_red[0][t] + s_red[1][t] + s_red[2][t] + s_red[3][t] + bv2[0];
    __syncthreads();
    if (t < EPB * 3) {
        int e = t / 3, i = t % 3;
        int idx = (n0 + e) * 3 + i;
        coord_out[idx] = coord[idx] + vel[idx] * s_vw[e];
    }
}

// ---------------------------------------------------------------------------
// per-edge: gather, 3-layer MLP chain, scatter (coords + messages)
__global__ __launch_bounds__(128) void edge_kernel(
    const float* __restrict__ h, const float* __restrict__ coord,
    const int* __restrict__ ei,
    const float* __restrict__ We1, const float* __restrict__ be1,
    const float* __restrict__ We2, const float* __restrict__ be2,
    const float* __restrict__ Wc1, const float* __restrict__ bc1,
    const float* __restrict__ Wc2, const float* __restrict__ bc2,
    float* __restrict__ coord_out)
{
    __shared__ __align__(16) float s_in[EPB][260];   // [h_r | h_c | rad | pad]
    __shared__ __align__(16) float s_a[EPB][D];
    __shared__ float s_red[4][EPB];
    __shared__ float s_diff[EPB][3];
    __shared__ int   s_r[EPB];
    int t = threadIdx.x;
    int lane = t & 31, wid = t >> 5;
    int e0 = blockIdx.x * EPB;

    int r[EPB], c[EPB];
    #pragma unroll
    for (int e = 0; e < EPB; e++) {
        r[e] = ei[e0 + e];
        c[e] = ei[N_EDGES + e0 + e];
    }
    #pragma unroll
    for (int e = 0; e < EPB; e++) {
        s_in[e][t]     = h[r[e] * D + t];
        s_in[e][D + t] = h[c[e] * D + t];
    }
    if (t < EPB) {
        int e = t;
        float dx = coord[r[e] * 3 + 0] - coord[c[e] * 3 + 0];
        float dy = coord[r[e] * 3 + 1] - coord[c[e] * 3 + 1];
        float dz = coord[r[e] * 3 + 2] - coord[c[e] * 3 + 2];
        float rad = dx * dx + dy * dy + dz * dz;
        float inv = 1.0f / (sqrtf(rad) + 1e-8f);
        s_in[e][256] = rad;
        s_in[e][257] = 0.f; s_in[e][258] = 0.f; s_in[e][259] = 0.f;
        s_diff[e][0] = dx * inv; s_diff[e][1] = dy * inv; s_diff[e][2] = dz * inv;
        s_r[e] = r[e];
    }
    __syncthreads();

    // --- layer 1: edge_in[257] @ We1 -> silu -> s_a ---
    float acc[EPB];
    { float b = be1[t];
      #pragma unroll
      for (int e = 0; e < EPB; e++) acc[e] = b; }
    for (int kg = 0; kg < 64; kg++) {
        float w0 = We1[(4 * kg + 0) * D + t];
        float w1 = We1[(4 * kg + 1) * D + t];
        float w2 = We1[(4 * kg + 2) * D + t];
        float w3 = We1[(4 * kg + 3) * D + t];
        #pragma unroll
        for (int e = 0; e < EPB; e++) {
            float4 x = *reinterpret_cast<const float4*>(&s_in[e][4 * kg]);
            acc[e] = fmaf(x.x, w0, acc[e]);
            acc[e] = fmaf(x.y, w1, acc[e]);
            acc[e] = fmaf(x.z, w2, acc[e]);
            acc[e] = fmaf(x.w, w3, acc[e]);
        }
    }
    { float w = We1[256 * D + t];   // rad term (k = 256)
      #pragma unroll
      for (int e = 0; e < EPB; e++) acc[e] = fmaf(s_in[e][256], w, acc[e]); }
    #pragma unroll
    for (int e = 0; e < EPB; e++) s_a[e][t] = silu(acc[e]);
    __syncthreads();

    // --- layer 2: s_a @ We2 -> silu -> m_ij ---
    float m[EPB];
    { float b = be2[t];
      #pragma unroll
      for (int e = 0; e < EPB; e++) acc[e] = b; }
    for (int kg = 0; kg < 32; kg++) {
        float w0 = We2[(4 * kg + 0) * D + t];
        float w1 = We2[(4 * kg + 1) * D + t];
        float w2 = We2[(4 * kg + 2) * D + t];
        float w3 = We2[(4 * kg + 3) * D + t];
        #pragma unroll
        for (int e = 0; e < EPB; e++) {
            float4 x = *reinterpret_cast<const float4*>(&s_a[e][4 * kg]);
            acc[e] = fmaf(x.x, w0, acc[e]);
            acc[e] = fmaf(x.y, w1, acc[e]);
            acc[e] = fmaf(x.z, w2, acc[e]);
            acc[e] = fmaf(x.w, w3, acc[e]);
        }
    }
    #pragma unroll
    for (int e = 0; e < EPB; e++) m[e] = silu(acc[e]);
    __syncthreads();                      // everyone done reading layer-1 s_a
    #pragma unroll
    for (int e = 0; e < EPB; e++) s_a[e][t] = m[e];   // m_ij into smem
    __syncthreads();

    // --- layer 3: m_ij @ Wc1 -> silu -> dot with Wc2 (scalar weight) ---
    { float b = bc1[t];
      #pragma unroll
      for (int e = 0; e < EPB; e++) acc[e] = b; }
    for (int kg = 0; kg < 32; kg++) {
        float w0 = Wc1[(4 * kg + 0) * D + t];
        float w1 = Wc1[(4 * kg + 1) * D + t];
        float w2 = Wc1[(4 * kg + 2) * D + t];
        float w3 = Wc1[(4 * kg + 3) * D + t];
        #pragma unroll
        for (int e = 0; e < EPB; e++) {
            float4 x = *reinterpret_cast<const float4*>(&s_a[e][4 * kg]);
            acc[e] = fmaf(x.x, w0, acc[e]);
            acc[e] = fmaf(x.y, w1, acc[e]);
            acc[e] = fmaf(x.z, w2, acc[e]);
            acc[e] = fmaf(x.w, w3, acc[e]);
        }
    }
    float wc = Wc2[t];
    float part[EPB];
    #pragma unroll
    for (int e = 0; e < EPB; e++) part[e] = silu(acc[e]) * wc;
    #pragma unroll
    for (int off = 16; off > 0; off >>= 1) {
        #pragma unroll
        for (int e = 0; e < EPB; e++)
            part[e] += __shfl_down_sync(0xffffffffu, part[e], off);
    }
    if (lane == 0) {
        #pragma unroll
        for (int e = 0; e < EPB; e++) s_red[wid][e] = part[e];
    }
    __syncthreads();
    if (t < EPB) {
        int e = t;
        float wgt = s_red[0][e] + s_red[1][e] + s_red[2][e] + s_red[3][e] + bc2[0];
        int rr = s_r[e];
        atomicAdd(&coord_out[rr * 3 + 0], s_diff[e][0] * wgt);
        atomicAdd(&coord_out[rr * 3 + 1], s_diff[e][1] * wgt);
        atomicAdd(&coord_out[rr * 3 + 2], s_diff[e][2] * wgt);
    }
    // m_i segment sum
    #pragma unroll
    for (int e = 0; e < EPB; e++) atomicAdd(&g_mi[r[e] * D + t], m[e]);
}

// ---------------------------------------------------------------------------
// node_op: [h, m_i] @ Wn1 -> silu -> @ Wn2  (no final activation)
__global__ __launch_bounds__(128) void node_post_kernel(
    const float* __restrict__ h,
    const float* __restrict__ Wn1, const float* __restrict__ bn1,
    const float* __restrict__ Wn2, const float* __restrict__ bn2,
    float* __restrict__ h_out)
{
    __shared__ __align__(16) float s_in[EPB][2 * D];
    __shared__ __align__(16) float s_a[EPB][D];
    int t = threadIdx.x;
    int n0 = blockIdx.x * EPB;

    #pragma unroll
    for (int e = 0; e < EPB; e++) {
        s_in[e][t]     = h[(n0 + e) * D + t];
        s_in[e][D + t] = g_mi[(n0 + e) * D + t];
    }
    __syncthreads();

    float acc[EPB];
    { float b = bn1[t];
      #pragma unroll
      for (int e = 0; e < EPB; e++) acc[e] = b; }
    for (int kg = 0; kg < 64; kg++) {
        float w0 = Wn1[(4 * kg + 0) * D + t];
        float w1 = Wn1[(4 * kg + 1) * D + t];
        float w2 = Wn1[(4 * kg + 2) * D + t];
        float w3 = Wn1[(4 * kg + 3) * D + t];
        #pragma unroll
        for (int e = 0; e < EPB; e++) {
            float4 x = *reinterpret_cast<const float4*>(&s_in[e][4 * kg]);
            acc[e] = fmaf(x.x, w0, acc[e]);
            acc[e] = fmaf(x.y, w1, acc[e]);
            acc[e] = fmaf(x.z, w2, acc[e]);
            acc[e] = fmaf(x.w, w3, acc[e]);
        }
    }
    #pragma unroll
    for (int e = 0; e < EPB; e++) s_a[e][t] = silu(acc[e]);
    __syncthreads();

    { float b = bn2[t];
      #pragma unroll
      for (int e = 0; e < EPB; e++) acc[e] = b; }
    for (int kg = 0; kg < 32; kg++) {
        float w0 = Wn2[(4 * kg + 0) * D + t];
        float w1 = Wn2[(4 * kg + 1) * D + t];
        float w2 = Wn2[(4 * kg + 2) * D + t];
        float w3 = Wn2[(4 * kg + 3) * D + t];
        #pragma unroll
        for (int e = 0; e < EPB; e++) {
            float4 x = *reinterpret_cast<const float4*>(&s_a[e][4 * kg]);
            acc[e] = fmaf(x.x, w0, acc[e]);
            acc[e] = fmaf(x.y, w1, acc[e]);
            acc[e] = fmaf(x.z, w2, acc[e]);
            acc[e] = fmaf(x.w, w3, acc[e]);
        }
    }
    #pragma unroll
    for (int e = 0; e < EPB; e++) h_out[(n0 + e) * D + t] = acc[e];
}

// ---------------------------------------------------------------------------
extern "C" void kernel_launch(void* const* d_in, const int* in_sizes, int n_in,
                              void* d_out, int out_size)
{
    const float* h     = (const float*)d_in[0];
    const float* coord = (const float*)d_in[1];
    const float* vel   = (const float*)d_in[2];
    const int*   ei    = (const int*)  d_in[3];
    const float* We1 = (const float*)d_in[4];  const float* be1 = (const float*)d_in[5];
    const float* We2 = (const float*)d_in[6];  const float* be2 = (const float*)d_in[7];
    const float* Wc1 = (const float*)d_in[8];  const float* bc1 = (const float*)d_in[9];
    const float* Wc2 = (const float*)d_in[10]; const float* bc2 = (const float*)d_in[11];
    const float* Wv1 = (const float*)d_in[12]; const float* bv1 = (const float*)d_in[13];
    const float* Wv2 = (const float*)d_in[14]; const float* bv2 = (const float*)d_in[15];
    const float* Wn1 = (const float*)d_in[16]; const float* bn1 = (const float*)d_in[17];
    const float* Wn2 = (const float*)d_in[18]; const float* bn2 = (const float*)d_in[19];

    float* h_out     = (float*)d_out;                  // [N, 128]
    float* coord_out = (float*)d_out + N_NODES * D;    // [N, 3]

    zero_mi_kernel<<<(N_NODES * D / 4 + 255) / 256, 256>>>();
    node_pre_kernel<<<N_NODES / EPB, 128>>>(h, coord, vel, Wv1, bv1, Wv2, bv2, coord_out);
    edge_kernel<<<N_EDGES / EPB, 128>>>(h, coord, ei,
                                        We1, be1, We2, be2,
                                        Wc1, bc1, Wc2, bc2,
                                        coord_out);
    node_post_kernel<<<N_NODES / EPB, 128>>>(h, Wn1, bn1, Wn2, bn2, h_out);
}

// round 5
// speedup vs baseline: 1.8660x; 1.8649x over previous
#include <cuda_runtime.h>

#define N_NODES 50000
#define N_EDGES 500000
#define D 128
#define EPB 4    // nodes per block (node kernels)

#define E_EPB 32        // edges per block (edge kernel)
#define PITCH 36        // floats per transposed smem row (144B: 16B-aligned rows)

// scratch for segment-summed messages m_i  (25.6 MB, static device global: allowed)
__device__ float g_mi[N_NODES * D];

typedef unsigned long long ull;

__device__ __forceinline__ float silu(float x) { return x / (1.0f + __expf(-x)); }

__device__ __forceinline__ ull dup2(float v) {
    ull r;
    asm("mov.b64 %0, {%1, %1};" : "=l"(r) : "f"(v));
    return r;
}
__device__ __forceinline__ void fma2(ull& acc, ull a, ull b) {
    asm("fma.rn.f32x2 %0, %1, %2, %0;" : "+l"(acc) : "l"(a), "l"(b));
}
__device__ __forceinline__ float2 unpack2(ull v) {
    float2 f;
    asm("mov.b64 {%0, %1}, %2;" : "=f"(f.x), "=f"(f.y) : "l"(v));
    return f;
}

// ---------------------------------------------------------------------------
__global__ void zero_mi_kernel() {
    int i = blockIdx.x * blockDim.x + threadIdx.x;
    if (i < N_NODES * D / 4)
        reinterpret_cast<float4*>(g_mi)[i] = make_float4(0.f, 0.f, 0.f, 0.f);
}

// ---------------------------------------------------------------------------
// vel_weights MLP + coord_out base = coord + vel * vw   (unchanged, correct)
__global__ __launch_bounds__(128) void node_pre_kernel(
    const float* __restrict__ h, const float* __restrict__ coord,
    const float* __restrict__ vel,
    const float* __restrict__ Wv1, const float* __restrict__ bv1,
    const float* __restrict__ Wv2, const float* __restrict__ bv2,
    float* __restrict__ coord_out)
{
    __shared__ __align__(16) float s_h[EPB][D];
    __shared__ float s_red[4][EPB];
    __shared__ float s_vw[EPB];
    int t = threadIdx.x;
    int lane = t & 31, wid = t >> 5;
    int n0 = blockIdx.x * EPB;

    #pragma unroll
    for (int e = 0; e < EPB; e++) s_h[e][t] = h[(n0 + e) * D + t];
    __syncthreads();

    float acc[EPB];
    { float b = bv1[t];
      #pragma unroll
      for (int e = 0; e < EPB; e++) acc[e] = b; }
    for (int kg = 0; kg < D / 4; kg++) {
        float w0 = Wv1[(4 * kg + 0) * D + t];
        float w1 = Wv1[(4 * kg + 1) * D + t];
        float w2 = Wv1[(4 * kg + 2) * D + t];
        float w3 = Wv1[(4 * kg + 3) * D + t];
        #pragma unroll
        for (int e = 0; e < EPB; e++) {
            float4 x = *reinterpret_cast<const float4*>(&s_h[e][4 * kg]);
            acc[e] = fmaf(x.x, w0, acc[e]);
            acc[e] = fmaf(x.y, w1, acc[e]);
            acc[e] = fmaf(x.z, w2, acc[e]);
            acc[e] = fmaf(x.w, w3, acc[e]);
        }
    }
    float wc = Wv2[t];
    float part[EPB];
    #pragma unroll
    for (int e = 0; e < EPB; e++) part[e] = silu(acc[e]) * wc;
    #pragma unroll
    for (int off = 16; off > 0; off >>= 1) {
        #pragma unroll
        for (int e = 0; e < EPB; e++)
            part[e] += __shfl_down_sync(0xffffffffu, part[e], off);
    }
    if (lane == 0) {
        #pragma unroll
        for (int e = 0; e < EPB; e++) s_red[wid][e] = part[e];
    }
    __syncthreads();
    if (t < EPB)
        s_vw[t] = s_red[0][t] + s_red[1][t] + s_red[2][t] + s_red[3][t] + bv2[0];
    __syncthreads();
    if (t < EPB * 3) {
        int e = t / 3, i = t % 3;
        int idx = (n0 + e) * 3 + i;
        coord_out[idx] = coord[idx] + vel[idx] * s_vw[e];
    }
}

// ---------------------------------------------------------------------------
// Packed-f32x2 GEMV layer: thread (g = t&31, eg = t>>5) computes features
// {g, g+32, g+64, g+96} for 8 edges (4 edge-pairs) = warp eg's edges.
// xT rows are [k][edge] (transposed), so one LDS.128 = 4 packed edge-pairs.
__device__ __forceinline__ void mlp_layer(
    const float* __restrict__ W,    // [K][128] row-major
    const float* __restrict__ bias, // [128]
    const float (*xT)[PITCH], int xbase, int K,
    int g, int eg, ull acc[4][4])
{
    #pragma unroll
    for (int f = 0; f < 4; f++) {
        ull bb = dup2(bias[g + 32 * f]);
        #pragma unroll
        for (int p = 0; p < 4; p++) acc[f][p] = bb;
    }
    #pragma unroll 4
    for (int k = 0; k < K; k++) {
        const float* wr = W + k * D + g;
        ull w0 = dup2(wr[0]);
        ull w1 = dup2(wr[32]);
        ull w2 = dup2(wr[64]);
        ull w3 = dup2(wr[96]);
        const float* xr = xT[xbase + k] + 8 * eg;
        ulonglong2 xa = *reinterpret_cast<const ulonglong2*>(xr);
        ulonglong2 xb = *reinterpret_cast<const ulonglong2*>(xr + 4);
        fma2(acc[0][0], xa.x, w0); fma2(acc[0][1], xa.y, w0);
        fma2(acc[0][2], xb.x, w0); fma2(acc[0][3], xb.y, w0);
        fma2(acc[1][0], xa.x, w1); fma2(acc[1][1], xa.y, w1);
        fma2(acc[1][2], xb.x, w1); fma2(acc[1][3], xb.y, w1);
        fma2(acc[2][0], xa.x, w2); fma2(acc[2][1], xa.y, w2);
        fma2(acc[2][2], xb.x, w2); fma2(acc[2][3], xb.y, w2);
        fma2(acc[3][0], xa.x, w3); fma2(acc[3][1], xa.y, w3);
        fma2(acc[3][2], xb.x, w3); fma2(acc[3][3], xb.y, w3);
    }
}

// store silu(acc) transposed into xT rows [obase + feature][edge]
__device__ __forceinline__ void store_act_silu(
    float (*xT)[PITCH], int obase, int g, int eg, const ull acc[4][4])
{
    #pragma unroll
    for (int f = 0; f < 4; f++) {
        float* row = xT[obase + g + 32 * f] + 8 * eg;
        #pragma unroll
        for (int p = 0; p < 4; p++) {
            float2 v = unpack2(acc[f][p]);
            row[2 * p]     = silu(v.x);
            row[2 * p + 1] = silu(v.y);
        }
    }
}

// ---------------------------------------------------------------------------
// per-edge: gather, 3-layer MLP chain (packed f32x2), scatter coords + messages
__global__ __launch_bounds__(128) void edge_kernel(
    const float* __restrict__ h, const float* __restrict__ coord,
    const int* __restrict__ ei,
    const float* __restrict__ We1, const float* __restrict__ be1,
    const float* __restrict__ We2, const float* __restrict__ be2,
    const float* __restrict__ Wc1, const float* __restrict__ bc1,
    const float* __restrict__ Wc2, const float* __restrict__ bc2,
    float* __restrict__ coord_out)
{
    // transposed feature buffer: rows 0..255 = [h_r; h_c], row 256 = rad.
    // act1 overlays rows 129..256 after layer 1; m_ij overlays rows 0..127;
    // act3 overlays rows 129..256 again.
    __shared__ __align__(16) float s_xT[257][PITCH];
    __shared__ int   s_r[E_EPB], s_c[E_EPB];
    __shared__ float s_diff[E_EPB][3];
    __shared__ float s_w[E_EPB];

    int t = threadIdx.x;
    int g = t & 31, eg = t >> 5;
    int e0 = blockIdx.x * E_EPB;

    if (t < E_EPB) {
        s_r[t] = ei[e0 + t];
        s_c[t] = ei[N_EDGES + e0 + t];
    }
    __syncthreads();

    // gather h rows (transposed): s_xT[k][e]
    #pragma unroll 4
    for (int e = 0; e < E_EPB; e++) {
        s_xT[t][e]       = h[s_r[e] * D + t];
        s_xT[128 + t][e] = h[s_c[e] * D + t];
    }
    if (t < E_EPB) {
        int e = t;
        float dx = coord[s_r[e] * 3 + 0] - coord[s_c[e] * 3 + 0];
        float dy = coord[s_r[e] * 3 + 1] - coord[s_c[e] * 3 + 1];
        float dz = coord[s_r[e] * 3 + 2] - coord[s_c[e] * 3 + 2];
        float rad = dx * dx + dy * dy + dz * dz;
        float inv = 1.0f / (sqrtf(rad) + 1e-8f);
        s_xT[256][e] = rad;
        s_diff[e][0] = dx * inv; s_diff[e][1] = dy * inv; s_diff[e][2] = dz * inv;
    }
    __syncthreads();

    ull acc[4][4];

    // --- layer 1: [h_r|h_c|rad] (K=257) @ We1 -> silu -> rows 129..256 ---
    mlp_layer(We1, be1, s_xT, 0, 257, g, eg, acc);
    __syncthreads();
    store_act_silu(s_xT, 129, g, eg, acc);
    __syncthreads();

    // --- layer 2: act1 @ We2 -> silu = m_ij -> rows 0..127, + m_i atomics ---
    mlp_layer(We2, be2, s_xT, 129, 128, g, eg, acc);
    __syncthreads();
    #pragma unroll
    for (int f = 0; f < 4; f++) {
        int fi = g + 32 * f;
        float* row = s_xT[fi] + 8 * eg;
        #pragma unroll
        for (int p = 0; p < 4; p++) {
            float2 v = unpack2(acc[f][p]);
            float a0 = silu(v.x), a1 = silu(v.y);
            int e = 8 * eg + 2 * p;
            row[2 * p]     = a0;
            row[2 * p + 1] = a1;
            atomicAdd(&g_mi[s_r[e] * D + fi], a0);
            atomicAdd(&g_mi[s_r[e + 1] * D + fi], a1);
        }
    }
    __syncthreads();

    // --- layer 3: m_ij @ Wc1 -> silu -> dot Wc2 (per-edge scalar weight) ---
    mlp_layer(Wc1, bc1, s_xT, 0, 128, g, eg, acc);

    float wc[4];
    #pragma unroll
    for (int f = 0; f < 4; f++) wc[f] = Wc2[g + 32 * f];
    float ps[8];
    #pragma unroll
    for (int i = 0; i < 8; i++) ps[i] = 0.f;
    #pragma unroll
    for (int f = 0; f < 4; f++) {
        #pragma unroll
        for (int p = 0; p < 4; p++) {
            float2 v = unpack2(acc[f][p]);
            ps[2 * p]     = fmaf(silu(v.x), wc[f], ps[2 * p]);
            ps[2 * p + 1] = fmaf(silu(v.y), wc[f], ps[2 * p + 1]);
        }
    }
    #pragma unroll
    for (int off = 16; off > 0; off >>= 1) {
        #pragma unroll
        for (int i = 0; i < 8; i++)
            ps[i] += __shfl_down_sync(0xffffffffu, ps[i], off);
    }
    if (g == 0) {
        float b = bc2[0];
        #pragma unroll
        for (int i = 0; i < 8; i++) s_w[8 * eg + i] = ps[i] + b;
    }
    __syncthreads();

    if (t < E_EPB * 3) {
        int e = t / 3, ax = t % 3;
        atomicAdd(&coord_out[s_r[e] * 3 + ax], s_diff[e][ax] * s_w[e]);
    }
}

// ---------------------------------------------------------------------------
// node_op: [h, m_i] @ Wn1 -> silu -> @ Wn2   (unchanged, correct)
__global__ __launch_bounds__(128) void node_post_kernel(
    const float* __restrict__ h,
    const float* __restrict__ Wn1, const float* __restrict__ bn1,
    const float* __restrict__ Wn2, const float* __restrict__ bn2,
    float* __restrict__ h_out)
{
    __shared__ __align__(16) float s_in[EPB][2 * D];
    __shared__ __align__(16) float s_a[EPB][D];
    int t = threadIdx.x;
    int n0 = blockIdx.x * EPB;

    #pragma unroll
    for (int e = 0; e < EPB; e++) {
        s_in[e][t]     = h[(n0 + e) * D + t];
        s_in[e][D + t] = g_mi[(n0 + e) * D + t];
    }
    __syncthreads();

    float acc[EPB];
    { float b = bn1[t];
      #pragma unroll
      for (int e = 0; e < EPB; e++) acc[e] = b; }
    for (int kg = 0; kg < 64; kg++) {
        float w0 = Wn1[(4 * kg + 0) * D + t];
        float w1 = Wn1[(4 * kg + 1) * D + t];
        float w2 = Wn1[(4 * kg + 2) * D + t];
        float w3 = Wn1[(4 * kg + 3) * D + t];
        #pragma unroll
        for (int e = 0; e < EPB; e++) {
            float4 x = *reinterpret_cast<const float4*>(&s_in[e][4 * kg]);
            acc[e] = fmaf(x.x, w0, acc[e]);
            acc[e] = fmaf(x.y, w1, acc[e]);
            acc[e] = fmaf(x.z, w2, acc[e]);
            acc[e] = fmaf(x.w, w3, acc[e]);
        }
    }
    #pragma unroll
    for (int e = 0; e < EPB; e++) s_a[e][t] = silu(acc[e]);
    __syncthreads();

    { float b = bn2[t];
      #pragma unroll
      for (int e = 0; e < EPB; e++) acc[e] = b; }
    for (int kg = 0; kg < 32; kg++) {
        float w0 = Wn2[(4 * kg + 0) * D + t];
        float w1 = Wn2[(4 * kg + 1) * D + t];
        float w2 = Wn2[(4 * kg + 2) * D + t];
        float w3 = Wn2[(4 * kg + 3) * D + t];
        #pragma unroll
        for (int e = 0; e < EPB; e++) {
            float4 x = *reinterpret_cast<const float4*>(&s_a[e][4 * kg]);
            acc[e] = fmaf(x.x, w0, acc[e]);
            acc[e] = fmaf(x.y, w1, acc[e]);
            acc[e] = fmaf(x.z, w2, acc[e]);
            acc[e] = fmaf(x.w, w3, acc[e]);
        }
    }
    #pragma unroll
    for (int e = 0; e < EPB; e++) h_out[(n0 + e) * D + t] = acc[e];
}

// ---------------------------------------------------------------------------
extern "C" void kernel_launch(void* const* d_in, const int* in_sizes, int n_in,
                              void* d_out, int out_size)
{
    const float* h     = (const float*)d_in[0];
    const float* coord = (const float*)d_in[1];
    const float* vel   = (const float*)d_in[2];
    const int*   ei    = (const int*)  d_in[3];
    const float* We1 = (const float*)d_in[4];  const float* be1 = (const float*)d_in[5];
    const float* We2 = (const float*)d_in[6];  const float* be2 = (const float*)d_in[7];
    const float* Wc1 = (const float*)d_in[8];  const float* bc1 = (const float*)d_in[9];
    const float* Wc2 = (const float*)d_in[10]; const float* bc2 = (const float*)d_in[11];
    const float* Wv1 = (const float*)d_in[12]; const float* bv1 = (const float*)d_in[13];
    const float* Wv2 = (const float*)d_in[14]; const float* bv2 = (const float*)d_in[15];
    const float* Wn1 = (const float*)d_in[16]; const float* bn1 = (const float*)d_in[17];
    const float* Wn2 = (const float*)d_in[18]; const float* bn2 = (const float*)d_in[19];

    float* h_out     = (float*)d_out;                  // [N, 128]
    float* coord_out = (float*)d_out + N_NODES * D;    // [N, 3]

    zero_mi_kernel<<<(N_NODES * D / 4 + 255) / 256, 256>>>();
    node_pre_kernel<<<N_NODES / EPB, 128>>>(h, coord, vel, Wv1, bv1, Wv2, bv2, coord_out);
    edge_kernel<<<N_EDGES / E_EPB, 128>>>(h, coord, ei,
                                          We1, be1, We2, be2,
                                          Wc1, bc1, Wc2, bc2,
                                          coord_out);
    node_post_kernel<<<N_NODES / EPB, 128>>>(h, Wn1, bn1, Wn2, bn2, h_out);
}

// round 6
// speedup vs baseline: 2.1000x; 1.1254x over previous
#include <cuda_runtime.h>

#define N_NODES 50000
#define N_EDGES 500000
#define D 128

#define E_EPB 32        // edges per block (edge kernel)
#define NPB   32        // nodes per block (node kernels)
#define PITCH 36        // floats per transposed smem row (144B: 16B-aligned rows)

// scratch for segment-summed messages m_i  (25.6 MB, static device global: allowed)
__device__ float g_mi[N_NODES * D];

typedef unsigned long long ull;

__device__ __forceinline__ float silu(float x) { return x / (1.0f + __expf(-x)); }

__device__ __forceinline__ ull dup2(float v) {
    ull r;
    asm("mov.b64 %0, {%1, %1};" : "=l"(r) : "f"(v));
    return r;
}
__device__ __forceinline__ void fma2(ull& acc, ull a, ull b) {
    asm("fma.rn.f32x2 %0, %1, %2, %0;" : "+l"(acc) : "l"(a), "l"(b));
}
__device__ __forceinline__ float2 unpack2(ull v) {
    float2 f;
    asm("mov.b64 {%0, %1}, %2;" : "=f"(f.x), "=f"(f.y) : "l"(v));
    return f;
}

// ---------------------------------------------------------------------------
__global__ void zero_mi_kernel() {
    int i = blockIdx.x * blockDim.x + threadIdx.x;
    if (i < N_NODES * D / 4)
        reinterpret_cast<float4*>(g_mi)[i] = make_float4(0.f, 0.f, 0.f, 0.f);
}

// ---------------------------------------------------------------------------
// Packed-f32x2 GEMV layer.
// Thread (g = t&31, eg = t>>5) computes features {4g..4g+3} for 8 items
// (4 packed pairs) owned by warp eg. xT rows are [k][item] (transposed):
// one LDS.128 (warp-uniform broadcast) delivers 4 item-pairs' x_k.
// Weights for one k arrive as a single coalesced LDG.128 per thread.
__device__ __forceinline__ void mlp_layer(
    const float* __restrict__ W,    // [K][128] row-major
    const float* __restrict__ bias, // [128]
    const float (*xT)[PITCH], int xbase, int K,
    int g, int eg, ull acc[4][4])
{
    float4 b4 = *reinterpret_cast<const float4*>(bias + 4 * g);
    {
        ull b0 = dup2(b4.x), b1 = dup2(b4.y), b2 = dup2(b4.z), b3 = dup2(b4.w);
        #pragma unroll
        for (int p = 0; p < 4; p++) {
            acc[0][p] = b0; acc[1][p] = b1; acc[2][p] = b2; acc[3][p] = b3;
        }
    }
    #pragma unroll 4
    for (int k = 0; k < K; k++) {
        float4 w = *reinterpret_cast<const float4*>(W + k * D + 4 * g);
        ull w0 = dup2(w.x), w1 = dup2(w.y), w2 = dup2(w.z), w3 = dup2(w.w);
        const float* xr = xT[xbase + k] + 8 * eg;
        ulonglong2 xa = *reinterpret_cast<const ulonglong2*>(xr);
        ulonglong2 xb = *reinterpret_cast<const ulonglong2*>(xr + 4);
        fma2(acc[0][0], xa.x, w0); fma2(acc[0][1], xa.y, w0);
        fma2(acc[0][2], xb.x, w0); fma2(acc[0][3], xb.y, w0);
        fma2(acc[1][0], xa.x, w1); fma2(acc[1][1], xa.y, w1);
        fma2(acc[1][2], xb.x, w1); fma2(acc[1][3], xb.y, w1);
        fma2(acc[2][0], xa.x, w2); fma2(acc[2][1], xa.y, w2);
        fma2(acc[2][2], xb.x, w2); fma2(acc[2][3], xb.y, w2);
        fma2(acc[3][0], xa.x, w3); fma2(acc[3][1], xa.y, w3);
        fma2(acc[3][2], xb.x, w3); fma2(acc[3][3], xb.y, w3);
    }
}

// store silu(acc) transposed into xT rows [obase + 4g + f][item]
__device__ __forceinline__ void store_act_silu(
    float (*xT)[PITCH], int obase, int g, int eg, const ull acc[4][4])
{
    #pragma unroll
    for (int f = 0; f < 4; f++) {
        float* row = xT[obase + 4 * g + f] + 8 * eg;
        #pragma unroll
        for (int p = 0; p < 4; p++) {
            float2 v = unpack2(acc[f][p]);
            row[2 * p]     = silu(v.x);
            row[2 * p + 1] = silu(v.y);
        }
    }
}

// ---------------------------------------------------------------------------
// vel_weights MLP + coord_out base = coord + vel * vw   (f32x2 version)
__global__ __launch_bounds__(128) void node_pre_kernel(
    const float* __restrict__ h, const float* __restrict__ coord,
    const float* __restrict__ vel,
    const float* __restrict__ Wv1, const float* __restrict__ bv1,
    const float* __restrict__ Wv2, const float* __restrict__ bv2,
    float* __restrict__ coord_out)
{
    __shared__ __align__(16) float s_xT[D][PITCH];
    __shared__ float s_vw[NPB];
    int t = threadIdx.x;
    int g = t & 31, eg = t >> 5;
    int n0 = blockIdx.x * NPB;

    #pragma unroll 4
    for (int e = 0; e < NPB; e++) {
        int n = n0 + e; if (n >= N_NODES) n = N_NODES - 1;
        s_xT[t][e] = h[n * D + t];
    }
    __syncthreads();

    ull acc[4][4];
    mlp_layer(Wv1, bv1, s_xT, 0, D, g, eg, acc);

    float4 wv = *reinterpret_cast<const float4*>(Wv2 + 4 * g);
    float wc[4] = {wv.x, wv.y, wv.z, wv.w};
    float ps[8];
    #pragma unroll
    for (int i = 0; i < 8; i++) ps[i] = 0.f;
    #pragma unroll
    for (int f = 0; f < 4; f++) {
        #pragma unroll
        for (int p = 0; p < 4; p++) {
            float2 v = unpack2(acc[f][p]);
            ps[2 * p]     = fmaf(silu(v.x), wc[f], ps[2 * p]);
            ps[2 * p + 1] = fmaf(silu(v.y), wc[f], ps[2 * p + 1]);
        }
    }
    #pragma unroll
    for (int off = 16; off > 0; off >>= 1) {
        #pragma unroll
        for (int i = 0; i < 8; i++)
            ps[i] += __shfl_down_sync(0xffffffffu, ps[i], off);
    }
    if (g == 0) {
        float b = bv2[0];
        #pragma unroll
        for (int i = 0; i < 8; i++) s_vw[8 * eg + i] = ps[i] + b;
    }
    __syncthreads();
    if (t < NPB * 3) {
        int e = t / 3, i = t % 3;
        int n = n0 + e;
        if (n < N_NODES) {
            int idx = n * 3 + i;
            coord_out[idx] = coord[idx] + vel[idx] * s_vw[e];
        }
    }
}

// ---------------------------------------------------------------------------
// per-edge: gather, 3-layer MLP chain (packed f32x2), scatter coords + messages
__global__ __launch_bounds__(128) void edge_kernel(
    const float* __restrict__ h, const float* __restrict__ coord,
    const int* __restrict__ ei,
    const float* __restrict__ We1, const float* __restrict__ be1,
    const float* __restrict__ We2, const float* __restrict__ be2,
    const float* __restrict__ Wc1, const float* __restrict__ bc1,
    const float* __restrict__ Wc2, const float* __restrict__ bc2,
    float* __restrict__ coord_out)
{
    // transposed feature buffer: rows 0..255 = [h_r; h_c], row 256 = rad.
    // act1 overlays rows 129..256 after layer 1; m_ij overlays rows 0..127.
    __shared__ __align__(16) float s_xT[257][PITCH];
    __shared__ int   s_r[E_EPB], s_c[E_EPB];
    __shared__ float s_diff[E_EPB][3];
    __shared__ float s_w[E_EPB];

    int t = threadIdx.x;
    int g = t & 31, eg = t >> 5;
    int e0 = blockIdx.x * E_EPB;

    if (t < E_EPB) {
        s_r[t] = ei[e0 + t];
        s_c[t] = ei[N_EDGES + e0 + t];
    }
    __syncthreads();

    // gather h rows (transposed): s_xT[k][e]
    #pragma unroll 4
    for (int e = 0; e < E_EPB; e++) {
        s_xT[t][e]       = h[s_r[e] * D + t];
        s_xT[128 + t][e] = h[s_c[e] * D + t];
    }
    if (t < E_EPB) {
        int e = t;
        float dx = coord[s_r[e] * 3 + 0] - coord[s_c[e] * 3 + 0];
        float dy = coord[s_r[e] * 3 + 1] - coord[s_c[e] * 3 + 1];
        float dz = coord[s_r[e] * 3 + 2] - coord[s_c[e] * 3 + 2];
        float rad = dx * dx + dy * dy + dz * dz;
        float inv = 1.0f / (sqrtf(rad) + 1e-8f);
        s_xT[256][e] = rad;
        s_diff[e][0] = dx * inv; s_diff[e][1] = dy * inv; s_diff[e][2] = dz * inv;
    }
    __syncthreads();

    ull acc[4][4];

    // --- layer 1: [h_r|h_c|rad] (K=257) @ We1 -> silu -> rows 129..256 ---
    mlp_layer(We1, be1, s_xT, 0, 257, g, eg, acc);
    __syncthreads();
    store_act_silu(s_xT, 129, g, eg, acc);
    __syncthreads();

    // --- layer 2: act1 @ We2 -> silu = m_ij -> rows 0..127, + m_i atomics ---
    mlp_layer(We2, be2, s_xT, 129, 128, g, eg, acc);
    __syncthreads();
    #pragma unroll
    for (int f = 0; f < 4; f++) {
        int fi = 4 * g + f;
        float* row = s_xT[fi] + 8 * eg;
        #pragma unroll
        for (int p = 0; p < 4; p++) {
            float2 v = unpack2(acc[f][p]);
            float a0 = silu(v.x), a1 = silu(v.y);
            int e = 8 * eg + 2 * p;
            row[2 * p]     = a0;
            row[2 * p + 1] = a1;
            atomicAdd(&g_mi[s_r[e] * D + fi], a0);
            atomicAdd(&g_mi[s_r[e + 1] * D + fi], a1);
        }
    }
    __syncthreads();

    // --- layer 3: m_ij @ Wc1 -> silu -> dot Wc2 (per-edge scalar weight) ---
    mlp_layer(Wc1, bc1, s_xT, 0, 128, g, eg, acc);

    float4 wv = *reinterpret_cast<const float4*>(Wc2 + 4 * g);
    float wc[4] = {wv.x, wv.y, wv.z, wv.w};
    float ps[8];
    #pragma unroll
    for (int i = 0; i < 8; i++) ps[i] = 0.f;
    #pragma unroll
    for (int f = 0; f < 4; f++) {
        #pragma unroll
        for (int p = 0; p < 4; p++) {
            float2 v = unpack2(acc[f][p]);
            ps[2 * p]     = fmaf(silu(v.x), wc[f], ps[2 * p]);
            ps[2 * p + 1] = fmaf(silu(v.y), wc[f], ps[2 * p + 1]);
        }
    }
    #pragma unroll
    for (int off = 16; off > 0; off >>= 1) {
        #pragma unroll
        for (int i = 0; i < 8; i++)
            ps[i] += __shfl_down_sync(0xffffffffu, ps[i], off);
    }
    if (g == 0) {
        float b = bc2[0];
        #pragma unroll
        for (int i = 0; i < 8; i++) s_w[8 * eg + i] = ps[i] + b;
    }
    __syncthreads();

    if (t < E_EPB * 3) {
        int e = t / 3, ax = t % 3;
        atomicAdd(&coord_out[s_r[e] * 3 + ax], s_diff[e][ax] * s_w[e]);
    }
}

// ---------------------------------------------------------------------------
// node_op: [h, m_i] @ Wn1 -> silu -> @ Wn2   (f32x2 version)
__global__ __launch_bounds__(128) void node_post_kernel(
    const float* __restrict__ h,
    const float* __restrict__ Wn1, const float* __restrict__ bn1,
    const float* __restrict__ Wn2, const float* __restrict__ bn2,
    float* __restrict__ h_out)
{
    // rows 0..127 = h, rows 128..255 = m_i; act1 overlays rows 0..127.
    __shared__ __align__(16) float s_xT[2 * D][PITCH];
    int t = threadIdx.x;
    int g = t & 31, eg = t >> 5;
    int n0 = blockIdx.x * NPB;

    #pragma unroll 4
    for (int e = 0; e < NPB; e++) {
        int n = n0 + e; if (n >= N_NODES) n = N_NODES - 1;
        s_xT[t][e]       = h[n * D + t];
        s_xT[128 + t][e] = g_mi[n * D + t];
    }
    __syncthreads();

    ull acc[4][4];

    // layer 1: K=256 -> silu -> rows 0..127
    mlp_layer(Wn1, bn1, s_xT, 0, 2 * D, g, eg, acc);
    __syncthreads();
    store_act_silu(s_xT, 0, g, eg, acc);
    __syncthreads();

    // layer 2: K=128, write h_out (no activation)
    mlp_layer(Wn2, bn2, s_xT, 0, D, g, eg, acc);

    #pragma unroll
    for (int p = 0; p < 4; p++) {
        float2 v0 = unpack2(acc[0][p]);
        float2 v1 = unpack2(acc[1][p]);
        float2 v2 = unpack2(acc[2][p]);
        float2 v3 = unpack2(acc[3][p]);
        int e = 8 * eg + 2 * p;
        if (n0 + e < N_NODES) {
            float4 o = make_float4(v0.x, v1.x, v2.x, v3.x);
            *reinterpret_cast<float4*>(&h_out[(n0 + e) * D + 4 * g]) = o;
        }
        if (n0 + e + 1 < N_NODES) {
            float4 o = make_float4(v0.y, v1.y, v2.y, v3.y);
            *reinterpret_cast<float4*>(&h_out[(n0 + e + 1) * D + 4 * g]) = o;
        }
    }
}

// ---------------------------------------------------------------------------
extern "C" void kernel_launch(void* const* d_in, const int* in_sizes, int n_in,
                              void* d_out, int out_size)
{
    const float* h     = (const float*)d_in[0];
    const float* coord = (const float*)d_in[1];
    const float* vel   = (const float*)d_in[2];
    const int*   ei    = (const int*)  d_in[3];
    const float* We1 = (const float*)d_in[4];  const float* be1 = (const float*)d_in[5];
    const float* We2 = (const float*)d_in[6];  const float* be2 = (const float*)d_in[7];
    const float* Wc1 = (const float*)d_in[8];  const float* bc1 = (const float*)d_in[9];
    const float* Wc2 = (const float*)d_in[10]; const float* bc2 = (const float*)d_in[11];
    const float* Wv1 = (const float*)d_in[12]; const float* bv1 = (const float*)d_in[13];
    const float* Wv2 = (const float*)d_in[14]; const float* bv2 = (const float*)d_in[15];
    const float* Wn1 = (const float*)d_in[16]; const float* bn1 = (const float*)d_in[17];
    const float* Wn2 = (const float*)d_in[18]; const float* bn2 = (const float*)d_in[19];

    float* h_out     = (float*)d_out;                  // [N, 128]
    float* coord_out = (float*)d_out + N_NODES * D;    // [N, 3]

    int node_blocks = (N_NODES + NPB - 1) / NPB;

    zero_mi_kernel<<<(N_NODES * D / 4 + 255) / 256, 256>>>();
    node_pre_kernel<<<node_blocks, 128>>>(h, coord, vel, Wv1, bv1, Wv2, bv2, coord_out);
    edge_kernel<<<N_EDGES / E_EPB, 128>>>(h, coord, ei,
                                          We1, be1, We2, be2,
                                          Wc1, bc1, Wc2, bc2,
                                          coord_out);
    node_post_kernel<<<node_blocks, 128>>>(h, Wn1, bn1, Wn2, bn2, h_out);
}

// round 8
// speedup vs baseline: 3.0322x; 1.4439x over previous
#include <cuda_runtime.h>
#include <cuda_bf16.h>
#include <cstdint>
#include <cstring>

#define N_NODES 50000
#define N_EDGES 500000
#define D 128
#define NPB   32
#define PITCH 36     // node-kernel transposed smem pitch (floats)

#define PITCHA 136   // edge-kernel activation plane pitch (bf16 elements)
#define PLANE  (128 * PITCHA)

// ---------------- scratch (static device globals: allowed) ----------------
__device__ float g_mi[N_NODES * D];
// fragment-ordered weight image: 32 ktile-slots x 16 ntiles x 32 lanes x uint4
__device__ uint4 g_bimg[32 * 16 * 32];

typedef unsigned long long ull;

__device__ __forceinline__ float silu(float x) { return x / (1.0f + __expf(-x)); }

__device__ __forceinline__ ull dup2(float v) {
    ull r; asm("mov.b64 %0, {%1, %1};" : "=l"(r) : "f"(v)); return r;
}
__device__ __forceinline__ void fma2(ull& acc, ull a, ull b) {
    asm("fma.rn.f32x2 %0, %1, %2, %0;" : "+l"(acc) : "l"(a), "l"(b));
}
__device__ __forceinline__ float2 unpack2(ull v) {
    float2 f; asm("mov.b64 {%0, %1}, %2;" : "=f"(f.x), "=f"(f.y) : "l"(v)); return f;
}

__device__ __forceinline__ uint32_t bf2_as_u32(__nv_bfloat162 v) {
    uint32_t u; memcpy(&u, &v, 4); return u;
}

// bf16 mma: D(f32) += A(bf16,row) x B(bf16,col), m16n8k16
__device__ __forceinline__ void mma_bf16(
    float* c, uint32_t a0, uint32_t a1, uint32_t a2, uint32_t a3,
    uint32_t b0, uint32_t b1)
{
    asm volatile(
        "mma.sync.aligned.m16n8k16.row.col.f32.bf16.bf16.f32 "
        "{%0,%1,%2,%3}, {%4,%5,%6,%7}, {%8,%9}, {%0,%1,%2,%3};"
        : "+f"(c[0]), "+f"(c[1]), "+f"(c[2]), "+f"(c[3])
        : "r"(a0), "r"(a1), "r"(a2), "r"(a3), "r"(b0), "r"(b1));
}

// split x,y into bf16 hi pair + lo pair
__device__ __forceinline__ void split_pair(
    float x, float y, __nv_bfloat162& hi, __nv_bfloat162& lo)
{
    hi = __floats2bfloat162_rn(x, y);
    lo = __floats2bfloat162_rn(x - __low2float(hi), y - __high2float(hi));
}

// ---------------------------------------------------------------------------
__global__ void zero_mi_kernel() {
    int i = blockIdx.x * blockDim.x + threadIdx.x;
    if (i < N_NODES * D / 4)
        reinterpret_cast<float4*>(g_mi)[i] = make_float4(0.f, 0.f, 0.f, 0.f);
}

// ---------------------------------------------------------------------------
// Build fragment-ordered B image.
// slot s (0..31): 0-7 We1 rows 0..127; 8-15 We1 rows 128..255; 16-23 We2; 24-31 Wc1.
// entry[(s*16+nt)*32+lane] = {b0hi, b1hi, b0lo, b1lo} for mma.m16n8k16 col-major B.
__global__ void prep_bimg_kernel(
    const float* __restrict__ We1, const float* __restrict__ We2,
    const float* __restrict__ Wc1)
{
    int idx = blockIdx.x * 256 + threadIdx.x;
    if (idx >= 32 * 16 * 32) return;
    int lane = idx & 31;
    int nt = (idx >> 5) & 15;
    int s = idx >> 9;
    int col = nt * 8 + (lane >> 2);
    int kloc = 2 * (lane & 3);
    const float* W; int kr;
    if (s < 8)       { W = We1; kr = s * 16 + kloc; }
    else if (s < 16) { W = We1; kr = 128 + (s - 8) * 16 + kloc; }
    else if (s < 24) { W = We2; kr = (s - 16) * 16 + kloc; }
    else             { W = Wc1; kr = (s - 24) * 16 + kloc; }
    float f00 = W[kr * D + col];
    float f01 = W[(kr + 1) * D + col];
    float f10 = W[(kr + 8) * D + col];
    float f11 = W[(kr + 9) * D + col];
    __nv_bfloat162 h0, l0, h1, l1;
    split_pair(f00, f01, h0, l0);
    split_pair(f10, f11, h1, l1);
    uint4 v;
    v.x = bf2_as_u32(h0); v.y = bf2_as_u32(h1);
    v.z = bf2_as_u32(l0); v.w = bf2_as_u32(l1);
    g_bimg[idx] = v;
}

// ---------------------------------------------------------------------------
// edge kernel: 128 edges/block, 256 threads (8 warps x 16 rows), HMMA mainloop
#define EDGE_SMEM 75776

__global__ __launch_bounds__(256, 2) void edge_kernel(
    const float* __restrict__ h, const float* __restrict__ coord,
    const int* __restrict__ ei,
    const float* __restrict__ be1, const float* __restrict__ be2,
    const float* __restrict__ bc1,
    const float* __restrict__ Wc2, const float* __restrict__ bc2,
    const float* __restrict__ We1,
    float* __restrict__ coord_out)
{
    extern __shared__ __align__(16) char smem[];
    __nv_bfloat16* aHi = (__nv_bfloat16*)smem;              // 34816 B
    __nv_bfloat16* aLo = aHi + PLANE;                       // 34816 B
    float* s_be1  = (float*)(smem + 69632);
    float* s_be2  = s_be1 + 128;
    float* s_bc1  = s_be2 + 128;
    float* s_wc2  = s_bc1 + 128;
    float* s_w256 = s_wc2 + 128;
    int*   s_r    = (int*)(smem + 72192);
    int*   s_c    = (int*)(smem + 72704);
    float* s_rad  = (float*)(smem + 73216);
    float* s_diff = (float*)(smem + 73728);
    float* s_w    = (float*)(smem + 75264);

    int t = threadIdx.x;
    int lane = t & 31, wid = t >> 5;
    int e0 = blockIdx.x * 128;

    // --- prologue: biases, indices, geometry ---
    if (t < 128) {
        s_be1[t] = be1[t]; s_be2[t] = be2[t]; s_bc1[t] = bc1[t];
        s_wc2[t] = Wc2[t]; s_w256[t] = We1[256 * D + t];
        int e = e0 + t;
        int cl = (e < N_EDGES) ? e : (N_EDGES - 1);
        s_r[t] = ei[cl];
        s_c[t] = ei[N_EDGES + cl];
    }
    __syncthreads();
    if (t < 128) {
        int r = s_r[t], c = s_c[t];
        float dx = coord[r * 3 + 0] - coord[c * 3 + 0];
        float dy = coord[r * 3 + 1] - coord[c * 3 + 1];
        float dz = coord[r * 3 + 2] - coord[c * 3 + 2];
        float rad = dx * dx + dy * dy + dz * dz;
        float inv = 1.0f / (sqrtf(rad) + 1e-8f);
        s_rad[t] = rad;
        s_diff[t * 3 + 0] = dx * inv;
        s_diff[t * 3 + 1] = dy * inv;
        s_diff[t * 3 + 2] = dz * inv;
    }

    float c[16][4];
    #pragma unroll
    for (int nt = 0; nt < 16; nt++)
        #pragma unroll
        for (int j = 0; j < 4; j++) c[nt][j] = 0.f;

    int q = lane >> 2;                 // 0..7
    int kq = 2 * (lane & 3);           // 0,2,4,6
    int r0 = wid * 16 + q, r1 = r0 + 8;
    bool v0 = (e0 + r0) < N_EDGES, v1 = (e0 + r1) < N_EDGES;

    // staging helper (lambda): write h[idx[row]] into plane as bf16 hi/lo
    auto stage = [&](const int* idx) {
        int r = t >> 1;
        int ch = (t & 1) * 64;
        const float* src = h + idx[r] * D + ch;
        __nv_bfloat16* ph = aHi + r * PITCHA + ch;
        __nv_bfloat16* pl = aLo + r * PITCHA + ch;
        #pragma unroll
        for (int j = 0; j < 16; j++) {
            float4 v = *(const float4*)(src + 4 * j);
            __nv_bfloat162 h2a, l2a, h2b, l2b;
            split_pair(v.x, v.y, h2a, l2a);
            split_pair(v.z, v.w, h2b, l2b);
            *(__nv_bfloat162*)(ph + 4 * j)     = h2a;
            *(__nv_bfloat162*)(ph + 4 * j + 2) = h2b;
            *(__nv_bfloat162*)(pl + 4 * j)     = l2a;
            *(__nv_bfloat162*)(pl + 4 * j + 2) = l2b;
        }
    };

    // compute helper: 8 ktiles of HMMA from plane vs g_bimg slot base
    auto gemm = [&](int base) {
        #pragma unroll 2
        for (int kt = 0; kt < 8; kt++) {
            int kk = kt * 16 + kq;
            uint32_t ah0 = *(const uint32_t*)(aHi + r0 * PITCHA + kk);
            uint32_t ah1 = *(const uint32_t*)(aHi + r1 * PITCHA + kk);
            uint32_t ah2 = *(const uint32_t*)(aHi + r0 * PITCHA + kk + 8);
            uint32_t ah3 = *(const uint32_t*)(aHi + r1 * PITCHA + kk + 8);
            uint32_t al0 = *(const uint32_t*)(aLo + r0 * PITCHA + kk);
            uint32_t al1 = *(const uint32_t*)(aLo + r1 * PITCHA + kk);
            uint32_t al2 = *(const uint32_t*)(aLo + r0 * PITCHA + kk + 8);
            uint32_t al3 = *(const uint32_t*)(aLo + r1 * PITCHA + kk + 8);
            const uint4* bp = g_bimg + ((base + kt) * 16) * 32 + lane;
            #pragma unroll
            for (int nt = 0; nt < 16; nt++) {
                uint4 b = __ldg(bp + nt * 32);
                mma_bf16(c[nt], ah0, ah1, ah2, ah3, b.x, b.y);
                mma_bf16(c[nt], ah0, ah1, ah2, ah3, b.z, b.w);
                mma_bf16(c[nt], al0, al1, al2, al3, b.x, b.y);
            }
        }
    };

    // ============ LAYER 1: h_r (slots 0-7) + h_c (slots 8-15) + rad rank-1 ====
    stage(s_r);
    __syncthreads();
    gemm(0);
    __syncthreads();
    stage(s_c);
    __syncthreads();
    gemm(8);
    __syncthreads();

    // epilogue 1: act1 = silu(C + be1 + rad * w256) -> plane
    {
        float rad0 = s_rad[r0], rad1 = s_rad[r1];
        #pragma unroll
        for (int nt = 0; nt < 16; nt++) {
            int col = nt * 8 + kq;
            float b0 = s_be1[col], b1 = s_be1[col + 1];
            float w0 = s_w256[col], w1 = s_w256[col + 1];
            float v00 = silu(c[nt][0] + b0 + rad0 * w0);
            float v01 = silu(c[nt][1] + b1 + rad0 * w1);
            float v10 = silu(c[nt][2] + b0 + rad1 * w0);
            float v11 = silu(c[nt][3] + b1 + rad1 * w1);
            __nv_bfloat162 h2, l2;
            split_pair(v00, v01, h2, l2);
            *(__nv_bfloat162*)(aHi + r0 * PITCHA + col) = h2;
            *(__nv_bfloat162*)(aLo + r0 * PITCHA + col) = l2;
            split_pair(v10, v11, h2, l2);
            *(__nv_bfloat162*)(aHi + r1 * PITCHA + col) = h2;
            *(__nv_bfloat162*)(aLo + r1 * PITCHA + col) = l2;
            c[nt][0] = c[nt][1] = c[nt][2] = c[nt][3] = 0.f;
        }
    }
    __syncthreads();

    // ============ LAYER 2: act1 @ We2 (slots 16-23) -> m_ij ============
    gemm(16);
    __syncthreads();
    {
        int n0 = v0 ? s_r[r0] : 0;
        int n1 = v1 ? s_r[r1] : 0;
        #pragma unroll
        for (int nt = 0; nt < 16; nt++) {
            int col = nt * 8 + kq;
            float b0 = s_be2[col], b1 = s_be2[col + 1];
            float v00 = silu(c[nt][0] + b0);
            float v01 = silu(c[nt][1] + b1);
            float v10 = silu(c[nt][2] + b0);
            float v11 = silu(c[nt][3] + b1);
            __nv_bfloat162 h2, l2;
            split_pair(v00, v01, h2, l2);
            *(__nv_bfloat162*)(aHi + r0 * PITCHA + col) = h2;
            *(__nv_bfloat162*)(aLo + r0 * PITCHA + col) = l2;
            split_pair(v10, v11, h2, l2);
            *(__nv_bfloat162*)(aHi + r1 * PITCHA + col) = h2;
            *(__nv_bfloat162*)(aLo + r1 * PITCHA + col) = l2;
            if (v0) {
                atomicAdd(&g_mi[n0 * D + col], v00);
                atomicAdd(&g_mi[n0 * D + col + 1], v01);
            }
            if (v1) {
                atomicAdd(&g_mi[n1 * D + col], v10);
                atomicAdd(&g_mi[n1 * D + col + 1], v11);
            }
            c[nt][0] = c[nt][1] = c[nt][2] = c[nt][3] = 0.f;
        }
    }
    __syncthreads();

    // ============ LAYER 3: m_ij @ Wc1 (slots 24-31) -> per-edge weight ======
    gemm(24);
    {
        float p0 = 0.f, p1 = 0.f;
        #pragma unroll
        for (int nt = 0; nt < 16; nt++) {
            int col = nt * 8 + kq;
            float b0 = s_bc1[col], b1 = s_bc1[col + 1];
            float w0 = s_wc2[col], w1 = s_wc2[col + 1];
            p0 = fmaf(silu(c[nt][0] + b0), w0, p0);
            p0 = fmaf(silu(c[nt][1] + b1), w1, p0);
            p1 = fmaf(silu(c[nt][2] + b0), w0, p1);
            p1 = fmaf(silu(c[nt][3] + b1), w1, p1);
        }
        p0 += __shfl_xor_sync(0xffffffffu, p0, 1);
        p0 += __shfl_xor_sync(0xffffffffu, p0, 2);
        p1 += __shfl_xor_sync(0xffffffffu, p1, 1);
        p1 += __shfl_xor_sync(0xffffffffu, p1, 2);
        if ((lane & 3) == 0) { s_w[r0] = p0; s_w[r1] = p1; }
    }
    __syncthreads();

    if (t < 128 && (e0 + t) < N_EDGES) {
        float w = s_w[t] + bc2[0];
        int rr = s_r[t];
        atomicAdd(&coord_out[rr * 3 + 0], s_diff[t * 3 + 0] * w);
        atomicAdd(&coord_out[rr * 3 + 1], s_diff[t * 3 + 1] * w);
        atomicAdd(&coord_out[rr * 3 + 2], s_diff[t * 3 + 2] * w);
    }
}

// ---------------------------------------------------------------------------
// f32x2 SIMT GEMV machinery for node kernels (verified in R5/R6)
__device__ __forceinline__ void mlp_layer(
    const float* __restrict__ W, const float* __restrict__ bias,
    const float (*xT)[PITCH], int xbase, int K,
    int g, int eg, ull acc[4][4])
{
    float4 b4 = *reinterpret_cast<const float4*>(bias + 4 * g);
    {
        ull b0 = dup2(b4.x), b1 = dup2(b4.y), b2 = dup2(b4.z), b3 = dup2(b4.w);
        #pragma unroll
        for (int p = 0; p < 4; p++) { acc[0][p] = b0; acc[1][p] = b1; acc[2][p] = b2; acc[3][p] = b3; }
    }
    #pragma unroll 4
    for (int k = 0; k < K; k++) {
        float4 w = *reinterpret_cast<const float4*>(W + k * D + 4 * g);
        ull w0 = dup2(w.x), w1 = dup2(w.y), w2 = dup2(w.z), w3 = dup2(w.w);
        const float* xr = xT[xbase + k] + 8 * eg;
        ulonglong2 xa = *reinterpret_cast<const ulonglong2*>(xr);
        ulonglong2 xb = *reinterpret_cast<const ulonglong2*>(xr + 4);
        fma2(acc[0][0], xa.x, w0); fma2(acc[0][1], xa.y, w0);
        fma2(acc[0][2], xb.x, w0); fma2(acc[0][3], xb.y, w0);
        fma2(acc[1][0], xa.x, w1); fma2(acc[1][1], xa.y, w1);
        fma2(acc[1][2], xb.x, w1); fma2(acc[1][3], xb.y, w1);
        fma2(acc[2][0], xa.x, w2); fma2(acc[2][1], xa.y, w2);
        fma2(acc[2][2], xb.x, w2); fma2(acc[2][3], xb.y, w2);
        fma2(acc[3][0], xa.x, w3); fma2(acc[3][1], xa.y, w3);
        fma2(acc[3][2], xb.x, w3); fma2(acc[3][3], xb.y, w3);
    }
}

__device__ __forceinline__ void store_act_silu(
    float (*xT)[PITCH], int obase, int g, int eg, const ull acc[4][4])
{
    #pragma unroll
    for (int f = 0; f < 4; f++) {
        float* row = xT[obase + 4 * g + f] + 8 * eg;
        #pragma unroll
        for (int p = 0; p < 4; p++) {
            float2 v = unpack2(acc[f][p]);
            row[2 * p]     = silu(v.x);
            row[2 * p + 1] = silu(v.y);
        }
    }
}

__global__ __launch_bounds__(128) void node_pre_kernel(
    const float* __restrict__ h, const float* __restrict__ coord,
    const float* __restrict__ vel,
    const float* __restrict__ Wv1, const float* __restrict__ bv1,
    const float* __restrict__ Wv2, const float* __restrict__ bv2,
    float* __restrict__ coord_out)
{
    __shared__ __align__(16) float s_xT[D][PITCH];
    __shared__ float s_vw[NPB];
    int t = threadIdx.x;
    int g = t & 31, eg = t >> 5;
    int n0 = blockIdx.x * NPB;

    #pragma unroll 4
    for (int e = 0; e < NPB; e++) {
        int n = n0 + e; if (n >= N_NODES) n = N_NODES - 1;
        s_xT[t][e] = h[n * D + t];
    }
    __syncthreads();

    ull acc[4][4];
    mlp_layer(Wv1, bv1, s_xT, 0, D, g, eg, acc);

    float4 wv = *reinterpret_cast<const float4*>(Wv2 + 4 * g);
    float wc[4] = {wv.x, wv.y, wv.z, wv.w};
    float ps[8];
    #pragma unroll
    for (int i = 0; i < 8; i++) ps[i] = 0.f;
    #pragma unroll
    for (int f = 0; f < 4; f++) {
        #pragma unroll
        for (int p = 0; p < 4; p++) {
            float2 v = unpack2(acc[f][p]);
            ps[2 * p]     = fmaf(silu(v.x), wc[f], ps[2 * p]);
            ps[2 * p + 1] = fmaf(silu(v.y), wc[f], ps[2 * p + 1]);
        }
    }
    #pragma unroll
    for (int off = 16; off > 0; off >>= 1) {
        #pragma unroll
        for (int i = 0; i < 8; i++)
            ps[i] += __shfl_down_sync(0xffffffffu, ps[i], off);
    }
    if (g == 0) {
        float b = bv2[0];
        #pragma unroll
        for (int i = 0; i < 8; i++) s_vw[8 * eg + i] = ps[i] + b;
    }
    __syncthreads();
    if (t < NPB * 3) {
        int e = t / 3, i = t % 3;
        int n = n0 + e;
        if (n < N_NODES) {
            int idx = n * 3 + i;
            coord_out[idx] = coord[idx] + vel[idx] * s_vw[e];
        }
    }
}

__global__ __launch_bounds__(128) void node_post_kernel(
    const float* __restrict__ h,
    const float* __restrict__ Wn1, const float* __restrict__ bn1,
    const float* __restrict__ Wn2, const float* __restrict__ bn2,
    float* __restrict__ h_out)
{
    __shared__ __align__(16) float s_xT[2 * D][PITCH];
    int t = threadIdx.x;
    int g = t & 31, eg = t >> 5;
    int n0 = blockIdx.x * NPB;

    #pragma unroll 4
    for (int e = 0; e < NPB; e++) {
        int n = n0 + e; if (n >= N_NODES) n = N_NODES - 1;
        s_xT[t][e]       = h[n * D + t];
        s_xT[128 + t][e] = g_mi[n * D + t];
    }
    __syncthreads();

    ull acc[4][4];
    mlp_layer(Wn1, bn1, s_xT, 0, 2 * D, g, eg, acc);
    __syncthreads();
    store_act_silu(s_xT, 0, g, eg, acc);
    __syncthreads();
    mlp_layer(Wn2, bn2, s_xT, 0, D, g, eg, acc);

    #pragma unroll
    for (int p = 0; p < 4; p++) {
        float2 v0 = unpack2(acc[0][p]);
        float2 v1 = unpack2(acc[1][p]);
        float2 v2 = unpack2(acc[2][p]);
        float2 v3 = unpack2(acc[3][p]);
        int e = 8 * eg + 2 * p;
        if (n0 + e < N_NODES) {
            float4 o = make_float4(v0.x, v1.x, v2.x, v3.x);
            *reinterpret_cast<float4*>(&h_out[(n0 + e) * D + 4 * g]) = o;
        }
        if (n0 + e + 1 < N_NODES) {
            float4 o = make_float4(v0.y, v1.y, v2.y, v3.y);
            *reinterpret_cast<float4*>(&h_out[(n0 + e + 1) * D + 4 * g]) = o;
        }
    }
}

// ---------------------------------------------------------------------------
extern "C" void kernel_launch(void* const* d_in, const int* in_sizes, int n_in,
                              void* d_out, int out_size)
{
    const float* h     = (const float*)d_in[0];
    const float* coord = (const float*)d_in[1];
    const float* vel   = (const float*)d_in[2];
    const int*   ei    = (const int*)  d_in[3];
    const float* We1 = (const float*)d_in[4];  const float* be1 = (const float*)d_in[5];
    const float* We2 = (const float*)d_in[6];  const float* be2 = (const float*)d_in[7];
    const float* Wc1 = (const float*)d_in[8];  const float* bc1 = (const float*)d_in[9];
    const float* Wc2 = (const float*)d_in[10]; const float* bc2 = (const float*)d_in[11];
    const float* Wv1 = (const float*)d_in[12]; const float* bv1 = (const float*)d_in[13];
    const float* Wv2 = (const float*)d_in[14]; const float* bv2 = (const float*)d_in[15];
    const float* Wn1 = (const float*)d_in[16]; const float* bn1 = (const float*)d_in[17];
    const float* Wn2 = (const float*)d_in[18]; const float* bn2 = (const float*)d_in[19];

    float* h_out     = (float*)d_out;                  // [N, 128]
    float* coord_out = (float*)d_out + N_NODES * D;    // [N, 3]

    cudaFuncSetAttribute(edge_kernel, cudaFuncAttributeMaxDynamicSharedMemorySize, EDGE_SMEM);

    int node_blocks = (N_NODES + NPB - 1) / NPB;
    int edge_blocks = (N_EDGES + 127) / 128;

    zero_mi_kernel<<<(N_NODES * D / 4 + 255) / 256, 256>>>();
    prep_bimg_kernel<<<(32 * 16 * 32 + 255) / 256, 256>>>(We1, We2, Wc1);
    node_pre_kernel<<<node_blocks, 128>>>(h, coord, vel, Wv1, bv1, Wv2, bv2, coord_out);
    edge_kernel<<<edge_blocks, 256, EDGE_SMEM>>>(h, coord, ei,
                                                 be1, be2, bc1, Wc2, bc2, We1, coord_out);
    node_post_kernel<<<node_blocks, 128>>>(h, Wn1, bn1, Wn2, bn2, h_out);
}

// round 9
// speedup vs baseline: 3.6276x; 1.1964x over previous
#include <cuda_runtime.h>
#include <cuda_bf16.h>
#include <cstdint>
#include <cstring>

#define N_NODES 50000
#define N_EDGES 500000
#define D 128
#define NPB   32
#define PITCH 36     // node-kernel transposed smem pitch (floats)

#define PITCHA 136   // edge-kernel activation plane pitch (bf16 elements)
#define PLANE  (128 * PITCHA)

// ---------------- scratch (static device globals: allowed) ----------------
__device__ float g_mi[N_NODES * D];
// fragment-ordered weight image: 32 ktile-slots x 16 ntiles x 32 lanes x uint4
__device__ uint4 g_bimg[32 * 16 * 32];

typedef unsigned long long ull;

__device__ __forceinline__ float silu(float x) { return x / (1.0f + __expf(-x)); }

__device__ __forceinline__ ull dup2(float v) {
    ull r; asm("mov.b64 %0, {%1, %1};" : "=l"(r) : "f"(v)); return r;
}
__device__ __forceinline__ void fma2(ull& acc, ull a, ull b) {
    asm("fma.rn.f32x2 %0, %1, %2, %0;" : "+l"(acc) : "l"(a), "l"(b));
}
__device__ __forceinline__ float2 unpack2(ull v) {
    float2 f; asm("mov.b64 {%0, %1}, %2;" : "=f"(f.x), "=f"(f.y) : "l"(v)); return f;
}

__device__ __forceinline__ uint32_t bf2_as_u32(__nv_bfloat162 v) {
    uint32_t u; memcpy(&u, &v, 4); return u;
}
__device__ __forceinline__ uint32_t smem_u32(const void* p) {
    uint32_t a;
    asm("{ .reg .u64 t; cvta.to.shared.u64 t, %1; cvt.u32.u64 %0, t; }" : "=r"(a) : "l"(p));
    return a;
}

// bf16 mma: D(f32) += A(bf16,row) x B(bf16,col), m16n8k16
__device__ __forceinline__ void mma_bf16(
    float* c, uint32_t a0, uint32_t a1, uint32_t a2, uint32_t a3,
    uint32_t b0, uint32_t b1)
{
    asm volatile(
        "mma.sync.aligned.m16n8k16.row.col.f32.bf16.bf16.f32 "
        "{%0,%1,%2,%3}, {%4,%5,%6,%7}, {%8,%9}, {%0,%1,%2,%3};"
        : "+f"(c[0]), "+f"(c[1]), "+f"(c[2]), "+f"(c[3])
        : "r"(a0), "r"(a1), "r"(a2), "r"(a3), "r"(b0), "r"(b1));
}

__device__ __forceinline__ void ldsm_x4(
    uint32_t& r0, uint32_t& r1, uint32_t& r2, uint32_t& r3, uint32_t addr)
{
    asm volatile("ldmatrix.sync.aligned.m8n8.x4.shared.b16 {%0,%1,%2,%3}, [%4];"
                 : "=r"(r0), "=r"(r1), "=r"(r2), "=r"(r3) : "r"(addr));
}

// split x,y into bf16 hi pair + lo pair
__device__ __forceinline__ void split_pair(
    float x, float y, __nv_bfloat162& hi, __nv_bfloat162& lo)
{
    hi = __floats2bfloat162_rn(x, y);
    lo = __floats2bfloat162_rn(x - __low2float(hi), y - __high2float(hi));
}

// ---------------------------------------------------------------------------
__global__ void zero_mi_kernel() {
    int i = blockIdx.x * blockDim.x + threadIdx.x;
    if (i < N_NODES * D / 4)
        reinterpret_cast<float4*>(g_mi)[i] = make_float4(0.f, 0.f, 0.f, 0.f);
}

// ---------------------------------------------------------------------------
// Build fragment-ordered B image (unchanged from R7 — verified).
__global__ void prep_bimg_kernel(
    const float* __restrict__ We1, const float* __restrict__ We2,
    const float* __restrict__ Wc1)
{
    int idx = blockIdx.x * 256 + threadIdx.x;
    if (idx >= 32 * 16 * 32) return;
    int lane = idx & 31;
    int nt = (idx >> 5) & 15;
    int s = idx >> 9;
    int col = nt * 8 + (lane >> 2);
    int kloc = 2 * (lane & 3);
    const float* W; int kr;
    if (s < 8)       { W = We1; kr = s * 16 + kloc; }
    else if (s < 16) { W = We1; kr = 128 + (s - 8) * 16 + kloc; }
    else if (s < 24) { W = We2; kr = (s - 16) * 16 + kloc; }
    else             { W = Wc1; kr = (s - 24) * 16 + kloc; }
    float f00 = W[kr * D + col];
    float f01 = W[(kr + 1) * D + col];
    float f10 = W[(kr + 8) * D + col];
    float f11 = W[(kr + 9) * D + col];
    __nv_bfloat162 h0, l0, h1, l1;
    split_pair(f00, f01, h0, l0);
    split_pair(f10, f11, h1, l1);
    uint4 v;
    v.x = bf2_as_u32(h0); v.y = bf2_as_u32(h1);
    v.z = bf2_as_u32(l0); v.w = bf2_as_u32(l1);
    g_bimg[idx] = v;
}

// ---------------------------------------------------------------------------
// edge kernel: 128 edges/block, 8 warps = 2 row-groups x 4 col-groups.
// Each warp: 64 rows x 32 cols (4 mtiles x 4 ntiles), A frags via ldmatrix.
#define EDGE_SMEM 75776

__global__ __launch_bounds__(256, 2) void edge_kernel(
    const float* __restrict__ h, const float* __restrict__ coord,
    const int* __restrict__ ei,
    const float* __restrict__ be1, const float* __restrict__ be2,
    const float* __restrict__ bc1,
    const float* __restrict__ Wc2, const float* __restrict__ bc2,
    const float* __restrict__ We1,
    float* __restrict__ coord_out)
{
    extern __shared__ __align__(16) char smem[];
    __nv_bfloat16* aHi = (__nv_bfloat16*)smem;              // 34816 B
    __nv_bfloat16* aLo = aHi + PLANE;                       // 34816 B
    float* s_be1  = (float*)(smem + 69632);
    float* s_be2  = s_be1 + 128;
    float* s_bc1  = s_be2 + 128;
    float* s_wc2  = s_bc1 + 128;
    float* s_w256 = s_wc2 + 128;
    int*   s_r    = (int*)(smem + 72192);
    int*   s_c    = (int*)(smem + 72704);
    float* s_rad  = (float*)(smem + 73216);
    float* s_diff = (float*)(smem + 73728);
    // L3 partials (512 floats) alias the aHi plane after the last GEMM.
    float* s_wp   = (float*)smem;

    int t = threadIdx.x;
    int lane = t & 31, wid = t >> 5;
    int cg = wid & 3, rg = wid >> 2;
    int e0 = blockIdx.x * 128;

    uint32_t aHi_base = smem_u32(aHi);

    // --- prologue: biases, indices, geometry ---
    if (t < 128) {
        s_be1[t] = be1[t]; s_be2[t] = be2[t]; s_bc1[t] = bc1[t];
        s_wc2[t] = Wc2[t]; s_w256[t] = We1[256 * D + t];
        int e = e0 + t;
        int cl = (e < N_EDGES) ? e : (N_EDGES - 1);
        s_r[t] = ei[cl];
        s_c[t] = ei[N_EDGES + cl];
    }
    __syncthreads();
    if (t < 128) {
        int r = s_r[t], c = s_c[t];
        float dx = coord[r * 3 + 0] - coord[c * 3 + 0];
        float dy = coord[r * 3 + 1] - coord[c * 3 + 1];
        float dz = coord[r * 3 + 2] - coord[c * 3 + 2];
        float rad = dx * dx + dy * dy + dz * dz;
        float inv = 1.0f / (sqrtf(rad) + 1e-8f);
        s_rad[t] = rad;
        s_diff[t * 3 + 0] = dx * inv;
        s_diff[t * 3 + 1] = dy * inv;
        s_diff[t * 3 + 2] = dz * inv;
    }

    float c[4][4][4];   // [mtile][ntile][frag]
    #pragma unroll
    for (int mt = 0; mt < 4; mt++)
        #pragma unroll
        for (int nt = 0; nt < 4; nt++)
            #pragma unroll
            for (int j = 0; j < 4; j++) c[mt][nt][j] = 0.f;

    int q = lane >> 2;                 // 0..7
    int kq = 2 * (lane & 3);           // 0,2,4,6
    // ldmatrix source coords for this lane
    int lrow = lane & 15;
    int lcol = (lane >> 4) * 8;

    // staging helper: write h[idx[row]] into plane as bf16 hi/lo
    auto stage = [&](const int* idx) {
        int r = t >> 1;
        int ch = (t & 1) * 64;
        const float* src = h + idx[r] * D + ch;
        __nv_bfloat16* ph = aHi + r * PITCHA + ch;
        __nv_bfloat16* pl = aLo + r * PITCHA + ch;
        #pragma unroll
        for (int j = 0; j < 16; j++) {
            float4 v = *(const float4*)(src + 4 * j);
            __nv_bfloat162 h2a, l2a, h2b, l2b;
            split_pair(v.x, v.y, h2a, l2a);
            split_pair(v.z, v.w, h2b, l2b);
            *(__nv_bfloat162*)(ph + 4 * j)     = h2a;
            *(__nv_bfloat162*)(ph + 4 * j + 2) = h2b;
            *(__nv_bfloat162*)(pl + 4 * j)     = l2a;
            *(__nv_bfloat162*)(pl + 4 * j + 2) = l2b;
        }
    };

    // compute helper: 8 ktiles, 4 mtiles x 4 ntiles per warp
    auto gemm = [&](int base) {
        #pragma unroll 2
        for (int kt = 0; kt < 8; kt++) {
            uint4 b[4];
            const uint4* bp = g_bimg + ((base + kt) * 16 + cg * 4) * 32 + lane;
            #pragma unroll
            for (int nt = 0; nt < 4; nt++) b[nt] = __ldg(bp + nt * 32);
            #pragma unroll
            for (int mt = 0; mt < 4; mt++) {
                int arow = rg * 64 + mt * 16 + lrow;
                int acol = kt * 16 + lcol;
                uint32_t addr = aHi_base + (arow * PITCHA + acol) * 2;
                uint32_t ah0, ah1, ah2, ah3, al0, al1, al2, al3;
                ldsm_x4(ah0, ah1, ah2, ah3, addr);
                ldsm_x4(al0, al1, al2, al3, addr + PLANE * 2);
                #pragma unroll
                for (int nt = 0; nt < 4; nt++) {
                    mma_bf16(c[mt][nt], ah0, ah1, ah2, ah3, b[nt].x, b[nt].y);
                    mma_bf16(c[mt][nt], ah0, ah1, ah2, ah3, b[nt].z, b[nt].w);
                    mma_bf16(c[mt][nt], al0, al1, al2, al3, b[nt].x, b[nt].y);
                }
            }
        }
    };

    // ============ LAYER 1: h_r (slots 0-7) + h_c (slots 8-15) + rad rank-1 ====
    stage(s_r);
    __syncthreads();
    gemm(0);
    __syncthreads();
    stage(s_c);
    __syncthreads();
    gemm(8);
    __syncthreads();

    // epilogue 1: act1 = silu(C + be1 + rad * w256) -> plane
    #pragma unroll
    for (int mt = 0; mt < 4; mt++) {
        int row0 = rg * 64 + mt * 16 + q;
        int row1 = row0 + 8;
        float rad0 = s_rad[row0], rad1 = s_rad[row1];
        #pragma unroll
        for (int nt = 0; nt < 4; nt++) {
            int col = cg * 32 + nt * 8 + kq;
            float b0 = s_be1[col], b1 = s_be1[col + 1];
            float w0 = s_w256[col], w1 = s_w256[col + 1];
            float v00 = silu(c[mt][nt][0] + b0 + rad0 * w0);
            float v01 = silu(c[mt][nt][1] + b1 + rad0 * w1);
            float v10 = silu(c[mt][nt][2] + b0 + rad1 * w0);
            float v11 = silu(c[mt][nt][3] + b1 + rad1 * w1);
            __nv_bfloat162 h2, l2;
            split_pair(v00, v01, h2, l2);
            *(__nv_bfloat162*)(aHi + row0 * PITCHA + col) = h2;
            *(__nv_bfloat162*)(aLo + row0 * PITCHA + col) = l2;
            split_pair(v10, v11, h2, l2);
            *(__nv_bfloat162*)(aHi + row1 * PITCHA + col) = h2;
            *(__nv_bfloat162*)(aLo + row1 * PITCHA + col) = l2;
            c[mt][nt][0] = c[mt][nt][1] = c[mt][nt][2] = c[mt][nt][3] = 0.f;
        }
    }
    __syncthreads();

    // ============ LAYER 2: act1 @ We2 (slots 16-23) -> m_ij ============
    gemm(16);
    __syncthreads();
    #pragma unroll
    for (int mt = 0; mt < 4; mt++) {
        int row0 = rg * 64 + mt * 16 + q;
        int row1 = row0 + 8;
        bool v0 = (e0 + row0) < N_EDGES, v1 = (e0 + row1) < N_EDGES;
        int n0 = s_r[row0], n1 = s_r[row1];
        #pragma unroll
        for (int nt = 0; nt < 4; nt++) {
            int col = cg * 32 + nt * 8 + kq;
            float b0 = s_be2[col], b1 = s_be2[col + 1];
            float v00 = silu(c[mt][nt][0] + b0);
            float v01 = silu(c[mt][nt][1] + b1);
            float v10 = silu(c[mt][nt][2] + b0);
            float v11 = silu(c[mt][nt][3] + b1);
            __nv_bfloat162 h2, l2;
            split_pair(v00, v01, h2, l2);
            *(__nv_bfloat162*)(aHi + row0 * PITCHA + col) = h2;
            *(__nv_bfloat162*)(aLo + row0 * PITCHA + col) = l2;
            split_pair(v10, v11, h2, l2);
            *(__nv_bfloat162*)(aHi + row1 * PITCHA + col) = h2;
            *(__nv_bfloat162*)(aLo + row1 * PITCHA + col) = l2;
            if (v0) {
                atomicAdd(&g_mi[n0 * D + col], v00);
                atomicAdd(&g_mi[n0 * D + col + 1], v01);
            }
            if (v1) {
                atomicAdd(&g_mi[n1 * D + col], v10);
                atomicAdd(&g_mi[n1 * D + col + 1], v11);
            }
            c[mt][nt][0] = c[mt][nt][1] = c[mt][nt][2] = c[mt][nt][3] = 0.f;
        }
    }
    __syncthreads();

    // ============ LAYER 3: m_ij @ Wc1 (slots 24-31) -> per-edge weight ======
    gemm(24);
    __syncthreads();     // all warps done reading plane; s_wp may alias it
    #pragma unroll
    for (int mt = 0; mt < 4; mt++) {
        float p0 = 0.f, p1 = 0.f;
        #pragma unroll
        for (int nt = 0; nt < 4; nt++) {
            int col = cg * 32 + nt * 8 + kq;
            float b0 = s_bc1[col], b1 = s_bc1[col + 1];
            float w0 = s_wc2[col], w1 = s_wc2[col + 1];
            p0 = fmaf(silu(c[mt][nt][0] + b0), w0, p0);
            p0 = fmaf(silu(c[mt][nt][1] + b1), w1, p0);
            p1 = fmaf(silu(c[mt][nt][2] + b0), w0, p1);
            p1 = fmaf(silu(c[mt][nt][3] + b1), w1, p1);
        }
        p0 += __shfl_xor_sync(0xffffffffu, p0, 1);
        p0 += __shfl_xor_sync(0xffffffffu, p0, 2);
        p1 += __shfl_xor_sync(0xffffffffu, p1, 1);
        p1 += __shfl_xor_sync(0xffffffffu, p1, 2);
        if ((lane & 3) == 0) {
            int row0 = rg * 64 + mt * 16 + q;
            s_wp[row0 * 4 + cg]       = p0;
            s_wp[(row0 + 8) * 4 + cg] = p1;
        }
    }
    __syncthreads();

    if (t < 128 && (e0 + t) < N_EDGES) {
        float w = s_wp[t * 4] + s_wp[t * 4 + 1] + s_wp[t * 4 + 2] + s_wp[t * 4 + 3] + bc2[0];
        int rr = s_r[t];
        atomicAdd(&coord_out[rr * 3 + 0], s_diff[t * 3 + 0] * w);
        atomicAdd(&coord_out[rr * 3 + 1], s_diff[t * 3 + 1] * w);
        atomicAdd(&coord_out[rr * 3 + 2], s_diff[t * 3 + 2] * w);
    }
}

// ---------------------------------------------------------------------------
// f32x2 SIMT GEMV machinery for node kernels (verified in R5/R6)
__device__ __forceinline__ void mlp_layer(
    const float* __restrict__ W, const float* __restrict__ bias,
    const float (*xT)[PITCH], int xbase, int K,
    int g, int eg, ull acc[4][4])
{
    float4 b4 = *reinterpret_cast<const float4*>(bias + 4 * g);
    {
        ull b0 = dup2(b4.x), b1 = dup2(b4.y), b2 = dup2(b4.z), b3 = dup2(b4.w);
        #pragma unroll
        for (int p = 0; p < 4; p++) { acc[0][p] = b0; acc[1][p] = b1; acc[2][p] = b2; acc[3][p] = b3; }
    }
    #pragma unroll 4
    for (int k = 0; k < K; k++) {
        float4 w = *reinterpret_cast<const float4*>(W + k * D + 4 * g);
        ull w0 = dup2(w.x), w1 = dup2(w.y), w2 = dup2(w.z), w3 = dup2(w.w);
        const float* xr = xT[xbase + k] + 8 * eg;
        ulonglong2 xa = *reinterpret_cast<const ulonglong2*>(xr);
        ulonglong2 xb = *reinterpret_cast<const ulonglong2*>(xr + 4);
        fma2(acc[0][0], xa.x, w0); fma2(acc[0][1], xa.y, w0);
        fma2(acc[0][2], xb.x, w0); fma2(acc[0][3], xb.y, w0);
        fma2(acc[1][0], xa.x, w1); fma2(acc[1][1], xa.y, w1);
        fma2(acc[1][2], xb.x, w1); fma2(acc[1][3], xb.y, w1);
        fma2(acc[2][0], xa.x, w2); fma2(acc[2][1], xa.y, w2);
        fma2(acc[2][2], xb.x, w2); fma2(acc[2][3], xb.y, w2);
        fma2(acc[3][0], xa.x, w3); fma2(acc[3][1], xa.y, w3);
        fma2(acc[3][2], xb.x, w3); fma2(acc[3][3], xb.y, w3);
    }
}

__device__ __forceinline__ void store_act_silu(
    float (*xT)[PITCH], int obase, int g, int eg, const ull acc[4][4])
{
    #pragma unroll
    for (int f = 0; f < 4; f++) {
        float* row = xT[obase + 4 * g + f] + 8 * eg;
        #pragma unroll
        for (int p = 0; p < 4; p++) {
            float2 v = unpack2(acc[f][p]);
            row[2 * p]     = silu(v.x);
            row[2 * p + 1] = silu(v.y);
        }
    }
}

__global__ __launch_bounds__(128) void node_pre_kernel(
    const float* __restrict__ h, const float* __restrict__ coord,
    const float* __restrict__ vel,
    const float* __restrict__ Wv1, const float* __restrict__ bv1,
    const float* __restrict__ Wv2, const float* __restrict__ bv2,
    float* __restrict__ coord_out)
{
    __shared__ __align__(16) float s_xT[D][PITCH];
    __shared__ float s_vw[NPB];
    int t = threadIdx.x;
    int g = t & 31, eg = t >> 5;
    int n0 = blockIdx.x * NPB;

    #pragma unroll 4
    for (int e = 0; e < NPB; e++) {
        int n = n0 + e; if (n >= N_NODES) n = N_NODES - 1;
        s_xT[t][e] = h[n * D + t];
    }
    __syncthreads();

    ull acc[4][4];
    mlp_layer(Wv1, bv1, s_xT, 0, D, g, eg, acc);

    float4 wv = *reinterpret_cast<const float4*>(Wv2 + 4 * g);
    float wc[4] = {wv.x, wv.y, wv.z, wv.w};
    float ps[8];
    #pragma unroll
    for (int i = 0; i < 8; i++) ps[i] = 0.f;
    #pragma unroll
    for (int f = 0; f < 4; f++) {
        #pragma unroll
        for (int p = 0; p < 4; p++) {
            float2 v = unpack2(acc[f][p]);
            ps[2 * p]     = fmaf(silu(v.x), wc[f], ps[2 * p]);
            ps[2 * p + 1] = fmaf(silu(v.y), wc[f], ps[2 * p + 1]);
        }
    }
    #pragma unroll
    for (int off = 16; off > 0; off >>= 1) {
        #pragma unroll
        for (int i = 0; i < 8; i++)
            ps[i] += __shfl_down_sync(0xffffffffu, ps[i], off);
    }
    if (g == 0) {
        float b = bv2[0];
        #pragma unroll
        for (int i = 0; i < 8; i++) s_vw[8 * eg + i] = ps[i] + b;
    }
    __syncthreads();
    if (t < NPB * 3) {
        int e = t / 3, i = t % 3;
        int n = n0 + e;
        if (n < N_NODES) {
            int idx = n * 3 + i;
            coord_out[idx] = coord[idx] + vel[idx] * s_vw[e];
        }
    }
}

__global__ __launch_bounds__(128) void node_post_kernel(
    const float* __restrict__ h,
    const float* __restrict__ Wn1, const float* __restrict__ bn1,
    const float* __restrict__ Wn2, const float* __restrict__ bn2,
    float* __restrict__ h_out)
{
    __shared__ __align__(16) float s_xT[2 * D][PITCH];
    int t = threadIdx.x;
    int g = t & 31, eg = t >> 5;
    int n0 = blockIdx.x * NPB;

    #pragma unroll 4
    for (int e = 0; e < NPB; e++) {
        int n = n0 + e; if (n >= N_NODES) n = N_NODES - 1;
        s_xT[t][e]       = h[n * D + t];
        s_xT[128 + t][e] = g_mi[n * D + t];
    }
    __syncthreads();

    ull acc[4][4];
    mlp_layer(Wn1, bn1, s_xT, 0, 2 * D, g, eg, acc);
    __syncthreads();
    store_act_silu(s_xT, 0, g, eg, acc);
    __syncthreads();
    mlp_layer(Wn2, bn2, s_xT, 0, D, g, eg, acc);

    #pragma unroll
    for (int p = 0; p < 4; p++) {
        float2 v0 = unpack2(acc[0][p]);
        float2 v1 = unpack2(acc[1][p]);
        float2 v2 = unpack2(acc[2][p]);
        float2 v3 = unpack2(acc[3][p]);
        int e = 8 * eg + 2 * p;
        if (n0 + e < N_NODES) {
            float4 o = make_float4(v0.x, v1.x, v2.x, v3.x);
            *reinterpret_cast<float4*>(&h_out[(n0 + e) * D + 4 * g]) = o;
        }
        if (n0 + e + 1 < N_NODES) {
            float4 o = make_float4(v0.y, v1.y, v2.y, v3.y);
            *reinterpret_cast<float4*>(&h_out[(n0 + e + 1) * D + 4 * g]) = o;
        }
    }
}

// ---------------------------------------------------------------------------
extern "C" void kernel_launch(void* const* d_in, const int* in_sizes, int n_in,
                              void* d_out, int out_size)
{
    const float* h     = (const float*)d_in[0];
    const float* coord = (const float*)d_in[1];
    const float* vel   = (const float*)d_in[2];
    const int*   ei    = (const int*)  d_in[3];
    const float* We1 = (const float*)d_in[4];  const float* be1 = (const float*)d_in[5];
    const float* We2 = (const float*)d_in[6];  const float* be2 = (const float*)d_in[7];
    const float* Wc1 = (const float*)d_in[8];  const float* bc1 = (const float*)d_in[9];
    const float* Wc2 = (const float*)d_in[10]; const float* bc2 = (const float*)d_in[11];
    const float* Wv1 = (const float*)d_in[12]; const float* bv1 = (const float*)d_in[13];
    const float* Wv2 = (const float*)d_in[14]; const float* bv2 = (const float*)d_in[15];
    const float* Wn1 = (const float*)d_in[16]; const float* bn1 = (const float*)d_in[17];
    const float* Wn2 = (const float*)d_in[18]; const float* bn2 = (const float*)d_in[19];

    float* h_out     = (float*)d_out;                  // [N, 128]
    float* coord_out = (float*)d_out + N_NODES * D;    // [N, 3]

    cudaFuncSetAttribute(edge_kernel, cudaFuncAttributeMaxDynamicSharedMemorySize, EDGE_SMEM);

    int node_blocks = (N_NODES + NPB - 1) / NPB;
    int edge_blocks = (N_EDGES + 127) / 128;

    zero_mi_kernel<<<(N_NODES * D / 4 + 255) / 256, 256>>>();
    prep_bimg_kernel<<<(32 * 16 * 32 + 255) / 256, 256>>>(We1, We2, Wc1);
    node_pre_kernel<<<node_blocks, 128>>>(h, coord, vel, Wv1, bv1, Wv2, bv2, coord_out);
    edge_kernel<<<edge_blocks, 256, EDGE_SMEM>>>(h, coord, ei,
                                                 be1, be2, bc1, Wc2, bc2, We1, coord_out);
    node_post_kernel<<<node_blocks, 128>>>(h, Wn1, bn1, Wn2, bn2, h_out);
}

// round 10
// speedup vs baseline: 3.8988x; 1.0747x over previous
#include <cuda_runtime.h>
#include <cuda_bf16.h>
#include <cstdint>
#include <cstring>

#define N_NODES 50000
#define N_EDGES 500000
#define D 128
#define NPB   32
#define PITCH 36     // node_pre transposed smem pitch (floats)

#define PITCHA 136   // HMMA activation plane pitch (bf16 elements)
#define PLANE  (128 * PITCHA)

// ---------------- scratch (static device globals: allowed) ----------------
__device__ float g_mi[N_NODES * D];
// fragment-ordered weight image: 56 ktile-slots x 16 ntiles x 32 lanes x uint4
// slots 0-7 We1[0:128), 8-15 We1[128:256), 16-23 We2, 24-31 Wc1,
// slots 32-39 Wn1[0:128), 40-47 Wn1[128:256), 48-55 Wn2
__device__ uint4 g_bimg[56 * 16 * 32];

typedef unsigned long long ull;

__device__ __forceinline__ float silu(float x) { return x / (1.0f + __expf(-x)); }

__device__ __forceinline__ ull dup2(float v) {
    ull r; asm("mov.b64 %0, {%1, %1};" : "=l"(r) : "f"(v)); return r;
}
__device__ __forceinline__ void fma2(ull& acc, ull a, ull b) {
    asm("fma.rn.f32x2 %0, %1, %2, %0;" : "+l"(acc) : "l"(a), "l"(b));
}
__device__ __forceinline__ float2 unpack2(ull v) {
    float2 f; asm("mov.b64 {%0, %1}, %2;" : "=f"(f.x), "=f"(f.y) : "l"(v)); return f;
}

__device__ __forceinline__ uint32_t bf2_as_u32(__nv_bfloat162 v) {
    uint32_t u; memcpy(&u, &v, 4); return u;
}
__device__ __forceinline__ uint32_t smem_u32(const void* p) {
    uint32_t a;
    asm("{ .reg .u64 t; cvta.to.shared.u64 t, %1; cvt.u32.u64 %0, t; }" : "=r"(a) : "l"(p));
    return a;
}

__device__ __forceinline__ void mma_bf16(
    float* c, uint32_t a0, uint32_t a1, uint32_t a2, uint32_t a3,
    uint32_t b0, uint32_t b1)
{
    asm volatile(
        "mma.sync.aligned.m16n8k16.row.col.f32.bf16.bf16.f32 "
        "{%0,%1,%2,%3}, {%4,%5,%6,%7}, {%8,%9}, {%0,%1,%2,%3};"
        : "+f"(c[0]), "+f"(c[1]), "+f"(c[2]), "+f"(c[3])
        : "r"(a0), "r"(a1), "r"(a2), "r"(a3), "r"(b0), "r"(b1));
}

__device__ __forceinline__ void ldsm_x4(
    uint32_t& r0, uint32_t& r1, uint32_t& r2, uint32_t& r3, uint32_t addr)
{
    asm volatile("ldmatrix.sync.aligned.m8n8.x4.shared.b16 {%0,%1,%2,%3}, [%4];"
                 : "=r"(r0), "=r"(r1), "=r"(r2), "=r"(r3) : "r"(addr));
}

__device__ __forceinline__ void split_pair(
    float x, float y, __nv_bfloat162& hi, __nv_bfloat162& lo)
{
    hi = __floats2bfloat162_rn(x, y);
    lo = __floats2bfloat162_rn(x - __low2float(hi), y - __high2float(hi));
}

// ---------------------------------------------------------------------------
__global__ void zero_mi_kernel() {
    int i = blockIdx.x * blockDim.x + threadIdx.x;
    if (i < N_NODES * D / 4)
        reinterpret_cast<float4*>(g_mi)[i] = make_float4(0.f, 0.f, 0.f, 0.f);
}

// ---------------------------------------------------------------------------
__global__ void prep_bimg_kernel(
    const float* __restrict__ We1, const float* __restrict__ We2,
    const float* __restrict__ Wc1, const float* __restrict__ Wn1,
    const float* __restrict__ Wn2)
{
    int idx = blockIdx.x * 256 + threadIdx.x;
    if (idx >= 56 * 16 * 32) return;
    int lane = idx & 31;
    int nt = (idx >> 5) & 15;
    int s = idx >> 9;
    int col = nt * 8 + (lane >> 2);
    int kloc = 2 * (lane & 3);
    const float* W; int kr;
    if (s < 8)       { W = We1; kr = s * 16 + kloc; }
    else if (s < 16) { W = We1; kr = 128 + (s - 8) * 16 + kloc; }
    else if (s < 24) { W = We2; kr = (s - 16) * 16 + kloc; }
    else if (s < 32) { W = Wc1; kr = (s - 24) * 16 + kloc; }
    else if (s < 40) { W = Wn1; kr = (s - 32) * 16 + kloc; }
    else if (s < 48) { W = Wn1; kr = 128 + (s - 40) * 16 + kloc; }
    else             { W = Wn2; kr = (s - 48) * 16 + kloc; }
    float f00 = W[kr * D + col];
    float f01 = W[(kr + 1) * D + col];
    float f10 = W[(kr + 8) * D + col];
    float f11 = W[(kr + 9) * D + col];
    __nv_bfloat162 h0, l0, h1, l1;
    split_pair(f00, f01, h0, l0);
    split_pair(f10, f11, h1, l1);
    uint4 v;
    v.x = bf2_as_u32(h0); v.y = bf2_as_u32(h1);
    v.z = bf2_as_u32(l0); v.w = bf2_as_u32(l1);
    g_bimg[idx] = v;
}

// ---------------------------------------------------------------------------
// software-pipelined 128x128x128 warp-tile GEMM step (3-pass hi/lo bf16)
// warp computes rows [rg*64, rg*64+64) x cols [cg*32, cg*32+32)
__device__ __forceinline__ void gemm_tile(
    float (&c)[4][4][4], uint32_t aHi_addr, int base,
    int cg, int rg, int lane)
{
    int lrow = lane & 15;
    int lcol = (lane >> 4) * 8;
    const uint4* bp = g_bimg + (base * 16 + cg * 4) * 32 + lane;
    uint4 b[4], bn[4];
    #pragma unroll
    for (int nt = 0; nt < 4; nt++) b[nt] = __ldg(bp + nt * 32);
    uint32_t abase = aHi_addr + (uint32_t)(((rg * 64 + lrow) * PITCHA + lcol) * 2);
    uint32_t ah[2][4], al[2][4];
    ldsm_x4(ah[0][0], ah[0][1], ah[0][2], ah[0][3], abase);
    ldsm_x4(al[0][0], al[0][1], al[0][2], al[0][3], abase + PLANE * 2);
    #pragma unroll
    for (int kt = 0; kt < 8; kt++) {
        if (kt < 7) {
            #pragma unroll
            for (int nt = 0; nt < 4; nt++) bn[nt] = __ldg(bp + 16 * 32 + nt * 32);
        }
        #pragma unroll
        for (int mt = 0; mt < 4; mt++) {
            int cur = mt & 1, nxt = 1 - cur;
            if (mt < 3) {
                uint32_t addr = abase + (uint32_t)((((mt + 1) * 16) * PITCHA + kt * 16) * 2);
                ldsm_x4(ah[nxt][0], ah[nxt][1], ah[nxt][2], ah[nxt][3], addr);
                ldsm_x4(al[nxt][0], al[nxt][1], al[nxt][2], al[nxt][3], addr + PLANE * 2);
            } else if (kt < 7) {
                uint32_t addr = abase + (uint32_t)(((kt + 1) * 16) * 2);
                ldsm_x4(ah[nxt][0], ah[nxt][1], ah[nxt][2], ah[nxt][3], addr);
                ldsm_x4(al[nxt][0], al[nxt][1], al[nxt][2], al[nxt][3], addr + PLANE * 2);
            }
            #pragma unroll
            for (int nt = 0; nt < 4; nt++) {
                mma_bf16(c[mt][nt], ah[cur][0], ah[cur][1], ah[cur][2], ah[cur][3], b[nt].x, b[nt].y);
                mma_bf16(c[mt][nt], ah[cur][0], ah[cur][1], ah[cur][2], ah[cur][3], b[nt].z, b[nt].w);
                mma_bf16(c[mt][nt], al[cur][0], al[cur][1], al[cur][2], al[cur][3], b[nt].x, b[nt].y);
            }
        }
        #pragma unroll
        for (int nt = 0; nt < 4; nt++) b[nt] = bn[nt];
        bp += 16 * 32;
    }
}

// ---------------------------------------------------------------------------
#define EDGE_SMEM 75776

__global__ __launch_bounds__(256, 2) void edge_kernel(
    const float* __restrict__ h, const float* __restrict__ coord,
    const int* __restrict__ ei,
    const float* __restrict__ be1, const float* __restrict__ be2,
    const float* __restrict__ bc1,
    const float* __restrict__ Wc2, const float* __restrict__ bc2,
    const float* __restrict__ We1,
    float* __restrict__ coord_out)
{
    extern __shared__ __align__(16) char smem[];
    __nv_bfloat16* aHi = (__nv_bfloat16*)smem;              // 34816 B
    __nv_bfloat16* aLo = aHi + PLANE;                       // 34816 B
    float* s_be1  = (float*)(smem + 69632);
    float* s_be2  = s_be1 + 128;
    float* s_bc1  = s_be2 + 128;
    float* s_wc2  = s_bc1 + 128;
    float* s_w256 = s_wc2 + 128;
    int*   s_r    = (int*)(smem + 72192);
    int*   s_c    = (int*)(smem + 72704);
    float* s_rad  = (float*)(smem + 73216);
    float* s_diff = (float*)(smem + 73728);
    float* s_wp   = (float*)smem;   // L3 partials alias plane after last GEMM

    int t = threadIdx.x;
    int lane = t & 31, wid = t >> 5;
    int cg = wid & 3, rg = wid >> 2;
    int e0 = blockIdx.x * 128;

    uint32_t aHi_addr = smem_u32(aHi);

    if (t < 128) {
        s_be1[t] = be1[t]; s_be2[t] = be2[t]; s_bc1[t] = bc1[t];
        s_wc2[t] = Wc2[t]; s_w256[t] = We1[256 * D + t];
        int e = e0 + t;
        int cl = (e < N_EDGES) ? e : (N_EDGES - 1);
        s_r[t] = ei[cl];
        s_c[t] = ei[N_EDGES + cl];
    }
    __syncthreads();
    if (t < 128) {
        int r = s_r[t], c = s_c[t];
        float dx = coord[r * 3 + 0] - coord[c * 3 + 0];
        float dy = coord[r * 3 + 1] - coord[c * 3 + 1];
        float dz = coord[r * 3 + 2] - coord[c * 3 + 2];
        float rad = dx * dx + dy * dy + dz * dz;
        float inv = 1.0f / (sqrtf(rad) + 1e-8f);
        s_rad[t] = rad;
        s_diff[t * 3 + 0] = dx * inv;
        s_diff[t * 3 + 1] = dy * inv;
        s_diff[t * 3 + 2] = dz * inv;
    }

    float c[4][4][4];
    #pragma unroll
    for (int mt = 0; mt < 4; mt++)
        #pragma unroll
        for (int nt = 0; nt < 4; nt++)
            #pragma unroll
            for (int j = 0; j < 4; j++) c[mt][nt][j] = 0.f;

    int q = lane >> 2;
    int kq = 2 * (lane & 3);

    auto stage = [&](const int* idx) {
        int r = t >> 1;
        int ch = (t & 1) * 64;
        const float* src = h + idx[r] * D + ch;
        __nv_bfloat16* ph = aHi + r * PITCHA + ch;
        __nv_bfloat16* pl = aLo + r * PITCHA + ch;
        #pragma unroll
        for (int j = 0; j < 16; j++) {
            float4 v = *(const float4*)(src + 4 * j);
            __nv_bfloat162 h2a, l2a, h2b, l2b;
            split_pair(v.x, v.y, h2a, l2a);
            split_pair(v.z, v.w, h2b, l2b);
            *(__nv_bfloat162*)(ph + 4 * j)     = h2a;
            *(__nv_bfloat162*)(ph + 4 * j + 2) = h2b;
            *(__nv_bfloat162*)(pl + 4 * j)     = l2a;
            *(__nv_bfloat162*)(pl + 4 * j + 2) = l2b;
        }
    };

    // ============ LAYER 1 ============
    stage(s_r);
    __syncthreads();
    gemm_tile(c, aHi_addr, 0, cg, rg, lane);
    __syncthreads();
    stage(s_c);
    __syncthreads();
    gemm_tile(c, aHi_addr, 8, cg, rg, lane);
    __syncthreads();

    #pragma unroll
    for (int mt = 0; mt < 4; mt++) {
        int row0 = rg * 64 + mt * 16 + q;
        int row1 = row0 + 8;
        float rad0 = s_rad[row0], rad1 = s_rad[row1];
        #pragma unroll
        for (int nt = 0; nt < 4; nt++) {
            int col = cg * 32 + nt * 8 + kq;
            float b0 = s_be1[col], b1 = s_be1[col + 1];
            float w0 = s_w256[col], w1 = s_w256[col + 1];
            float v00 = silu(c[mt][nt][0] + b0 + rad0 * w0);
            float v01 = silu(c[mt][nt][1] + b1 + rad0 * w1);
            float v10 = silu(c[mt][nt][2] + b0 + rad1 * w0);
            float v11 = silu(c[mt][nt][3] + b1 + rad1 * w1);
            __nv_bfloat162 h2, l2;
            split_pair(v00, v01, h2, l2);
            *(__nv_bfloat162*)(aHi + row0 * PITCHA + col) = h2;
            *(__nv_bfloat162*)(aLo + row0 * PITCHA + col) = l2;
            split_pair(v10, v11, h2, l2);
            *(__nv_bfloat162*)(aHi + row1 * PITCHA + col) = h2;
            *(__nv_bfloat162*)(aLo + row1 * PITCHA + col) = l2;
            c[mt][nt][0] = c[mt][nt][1] = c[mt][nt][2] = c[mt][nt][3] = 0.f;
        }
    }
    __syncthreads();

    // ============ LAYER 2 ============
    gemm_tile(c, aHi_addr, 16, cg, rg, lane);
    __syncthreads();
    #pragma unroll
    for (int mt = 0; mt < 4; mt++) {
        int row0 = rg * 64 + mt * 16 + q;
        int row1 = row0 + 8;
        bool v0 = (e0 + row0) < N_EDGES, v1 = (e0 + row1) < N_EDGES;
        int n0 = s_r[row0], n1 = s_r[row1];
        #pragma unroll
        for (int nt = 0; nt < 4; nt++) {
            int col = cg * 32 + nt * 8 + kq;
            float b0 = s_be2[col], b1 = s_be2[col + 1];
            float v00 = silu(c[mt][nt][0] + b0);
            float v01 = silu(c[mt][nt][1] + b1);
            float v10 = silu(c[mt][nt][2] + b0);
            float v11 = silu(c[mt][nt][3] + b1);
            __nv_bfloat162 h2, l2;
            split_pair(v00, v01, h2, l2);
            *(__nv_bfloat162*)(aHi + row0 * PITCHA + col) = h2;
            *(__nv_bfloat162*)(aLo + row0 * PITCHA + col) = l2;
            split_pair(v10, v11, h2, l2);
            *(__nv_bfloat162*)(aHi + row1 * PITCHA + col) = h2;
            *(__nv_bfloat162*)(aLo + row1 * PITCHA + col) = l2;
            if (v0) {
                atomicAdd(&g_mi[n0 * D + col], v00);
                atomicAdd(&g_mi[n0 * D + col + 1], v01);
            }
            if (v1) {
                atomicAdd(&g_mi[n1 * D + col], v10);
                atomicAdd(&g_mi[n1 * D + col + 1], v11);
            }
            c[mt][nt][0] = c[mt][nt][1] = c[mt][nt][2] = c[mt][nt][3] = 0.f;
        }
    }
    __syncthreads();

    // ============ LAYER 3 ============
    gemm_tile(c, aHi_addr, 24, cg, rg, lane);
    __syncthreads();
    #pragma unroll
    for (int mt = 0; mt < 4; mt++) {
        float p0 = 0.f, p1 = 0.f;
        #pragma unroll
        for (int nt = 0; nt < 4; nt++) {
            int col = cg * 32 + nt * 8 + kq;
            float b0 = s_bc1[col], b1 = s_bc1[col + 1];
            float w0 = s_wc2[col], w1 = s_wc2[col + 1];
            p0 = fmaf(silu(c[mt][nt][0] + b0), w0, p0);
            p0 = fmaf(silu(c[mt][nt][1] + b1), w1, p0);
            p1 = fmaf(silu(c[mt][nt][2] + b0), w0, p1);
            p1 = fmaf(silu(c[mt][nt][3] + b1), w1, p1);
        }
        p0 += __shfl_xor_sync(0xffffffffu, p0, 1);
        p0 += __shfl_xor_sync(0xffffffffu, p0, 2);
        p1 += __shfl_xor_sync(0xffffffffu, p1, 1);
        p1 += __shfl_xor_sync(0xffffffffu, p1, 2);
        if ((lane & 3) == 0) {
            int row0 = rg * 64 + mt * 16 + q;
            s_wp[row0 * 4 + cg]       = p0;
            s_wp[(row0 + 8) * 4 + cg] = p1;
        }
    }
    __syncthreads();

    if (t < 128 && (e0 + t) < N_EDGES) {
        float w = s_wp[t * 4] + s_wp[t * 4 + 1] + s_wp[t * 4 + 2] + s_wp[t * 4 + 3] + bc2[0];
        int rr = s_r[t];
        atomicAdd(&coord_out[rr * 3 + 0], s_diff[t * 3 + 0] * w);
        atomicAdd(&coord_out[rr * 3 + 1], s_diff[t * 3 + 1] * w);
        atomicAdd(&coord_out[rr * 3 + 2], s_diff[t * 3 + 2] * w);
    }
}

// ---------------------------------------------------------------------------
// node_post: HMMA version. 128 nodes/block. [h,m_i]@Wn1 -> silu -> @Wn2.
__global__ __launch_bounds__(256, 2) void node_post_kernel(
    const float* __restrict__ h,
    const float* __restrict__ bn1, const float* __restrict__ bn2,
    float* __restrict__ h_out)
{
    extern __shared__ __align__(16) char smem[];
    __nv_bfloat16* aHi = (__nv_bfloat16*)smem;
    __nv_bfloat16* aLo = aHi + PLANE;
    float* s_bn1 = (float*)(smem + 69632);
    float* s_bn2 = s_bn1 + 128;

    int t = threadIdx.x;
    int lane = t & 31, wid = t >> 5;
    int cg = wid & 3, rg = wid >> 2;
    int n0 = blockIdx.x * 128;
    uint32_t aHi_addr = smem_u32(aHi);

    if (t < 128) { s_bn1[t] = bn1[t]; s_bn2[t] = bn2[t]; }

    float c[4][4][4];
    #pragma unroll
    for (int mt = 0; mt < 4; mt++)
        #pragma unroll
        for (int nt = 0; nt < 4; nt++)
            #pragma unroll
            for (int j = 0; j < 4; j++) c[mt][nt][j] = 0.f;

    int q = lane >> 2;
    int kq = 2 * (lane & 3);

    auto stage_rows = [&](const float* base) {
        int r = t >> 1;
        int node = n0 + r; if (node >= N_NODES) node = N_NODES - 1;
        int ch = (t & 1) * 64;
        const float* src = base + node * D + ch;
        __nv_bfloat16* ph = aHi + r * PITCHA + ch;
        __nv_bfloat16* pl = aLo + r * PITCHA + ch;
        #pragma unroll
        for (int j = 0; j < 16; j++) {
            float4 v = *(const float4*)(src + 4 * j);
            __nv_bfloat162 h2a, l2a, h2b, l2b;
            split_pair(v.x, v.y, h2a, l2a);
            split_pair(v.z, v.w, h2b, l2b);
            *(__nv_bfloat162*)(ph + 4 * j)     = h2a;
            *(__nv_bfloat162*)(ph + 4 * j + 2) = h2b;
            *(__nv_bfloat162*)(pl + 4 * j)     = l2a;
            *(__nv_bfloat162*)(pl + 4 * j + 2) = l2b;
        }
    };

    stage_rows(h);
    __syncthreads();
    gemm_tile(c, aHi_addr, 32, cg, rg, lane);
    __syncthreads();
    stage_rows(g_mi);
    __syncthreads();
    gemm_tile(c, aHi_addr, 40, cg, rg, lane);
    __syncthreads();

    // epilogue: silu(C + bn1) -> plane
    #pragma unroll
    for (int mt = 0; mt < 4; mt++) {
        int row0 = rg * 64 + mt * 16 + q;
        int row1 = row0 + 8;
        #pragma unroll
        for (int nt = 0; nt < 4; nt++) {
            int col = cg * 32 + nt * 8 + kq;
            float b0 = s_bn1[col], b1 = s_bn1[col + 1];
            float v00 = silu(c[mt][nt][0] + b0);
            float v01 = silu(c[mt][nt][1] + b1);
            float v10 = silu(c[mt][nt][2] + b0);
            float v11 = silu(c[mt][nt][3] + b1);
            __nv_bfloat162 h2, l2;
            split_pair(v00, v01, h2, l2);
            *(__nv_bfloat162*)(aHi + row0 * PITCHA + col) = h2;
            *(__nv_bfloat162*)(aLo + row0 * PITCHA + col) = l2;
            split_pair(v10, v11, h2, l2);
            *(__nv_bfloat162*)(aHi + row1 * PITCHA + col) = h2;
            *(__nv_bfloat162*)(aLo + row1 * PITCHA + col) = l2;
            c[mt][nt][0] = c[mt][nt][1] = c[mt][nt][2] = c[mt][nt][3] = 0.f;
        }
    }
    __syncthreads();

    gemm_tile(c, aHi_addr, 48, cg, rg, lane);

    // final: h_out = C + bn2
    #pragma unroll
    for (int mt = 0; mt < 4; mt++) {
        int row0 = rg * 64 + mt * 16 + q;
        int row1 = row0 + 8;
        bool v0 = (n0 + row0) < N_NODES, v1 = (n0 + row1) < N_NODES;
        #pragma unroll
        for (int nt = 0; nt < 4; nt++) {
            int col = cg * 32 + nt * 8 + kq;
            float b0 = s_bn2[col], b1 = s_bn2[col + 1];
            if (v0) {
                float2 o = make_float2(c[mt][nt][0] + b0, c[mt][nt][1] + b1);
                *(float2*)&h_out[(n0 + row0) * D + col] = o;
            }
            if (v1) {
                float2 o = make_float2(c[mt][nt][2] + b0, c[mt][nt][3] + b1);
                *(float2*)&h_out[(n0 + row1) * D + col] = o;
            }
        }
    }
}

// ---------------------------------------------------------------------------
// node_pre: f32x2 SIMT (verified; small share of runtime)
__device__ __forceinline__ void mlp_layer(
    const float* __restrict__ W, const float* __restrict__ bias,
    const float (*xT)[PITCH], int xbase, int K,
    int g, int eg, ull acc[4][4])
{
    float4 b4 = *reinterpret_cast<const float4*>(bias + 4 * g);
    {
        ull b0 = dup2(b4.x), b1 = dup2(b4.y), b2 = dup2(b4.z), b3 = dup2(b4.w);
        #pragma unroll
        for (int p = 0; p < 4; p++) { acc[0][p] = b0; acc[1][p] = b1; acc[2][p] = b2; acc[3][p] = b3; }
    }
    #pragma unroll 4
    for (int k = 0; k < K; k++) {
        float4 w = *reinterpret_cast<const float4*>(W + k * D + 4 * g);
        ull w0 = dup2(w.x), w1 = dup2(w.y), w2 = dup2(w.z), w3 = dup2(w.w);
        const float* xr = xT[xbase + k] + 8 * eg;
        ulonglong2 xa = *reinterpret_cast<const ulonglong2*>(xr);
        ulonglong2 xb = *reinterpret_cast<const ulonglong2*>(xr + 4);
        fma2(acc[0][0], xa.x, w0); fma2(acc[0][1], xa.y, w0);
        fma2(acc[0][2], xb.x, w0); fma2(acc[0][3], xb.y, w0);
        fma2(acc[1][0], xa.x, w1); fma2(acc[1][1], xa.y, w1);
        fma2(acc[1][2], xb.x, w1); fma2(acc[1][3], xb.y, w1);
        fma2(acc[2][0], xa.x, w2); fma2(acc[2][1], xa.y, w2);
        fma2(acc[2][2], xb.x, w2); fma2(acc[2][3], xb.y, w2);
        fma2(acc[3][0], xa.x, w3); fma2(acc[3][1], xa.y, w3);
        fma2(acc[3][2], xb.x, w3); fma2(acc[3][3], xb.y, w3);
    }
}

__global__ __launch_bounds__(128) void node_pre_kernel(
    const float* __restrict__ h, const float* __restrict__ coord,
    const float* __restrict__ vel,
    const float* __restrict__ Wv1, const float* __restrict__ bv1,
    const float* __restrict__ Wv2, const float* __restrict__ bv2,
    float* __restrict__ coord_out)
{
    __shared__ __align__(16) float s_xT[D][PITCH];
    __shared__ float s_vw[NPB];
    int t = threadIdx.x;
    int g = t & 31, eg = t >> 5;
    int n0 = blockIdx.x * NPB;

    #pragma unroll 4
    for (int e = 0; e < NPB; e++) {
        int n = n0 + e; if (n >= N_NODES) n = N_NODES - 1;
        s_xT[t][e] = h[n * D + t];
    }
    __syncthreads();

    ull acc[4][4];
    mlp_layer(Wv1, bv1, s_xT, 0, D, g, eg, acc);

    float4 wv = *reinterpret_cast<const float4*>(Wv2 + 4 * g);
    float wc[4] = {wv.x, wv.y, wv.z, wv.w};
    float ps[8];
    #pragma unroll
    for (int i = 0; i < 8; i++) ps[i] = 0.f;
    #pragma unroll
    for (int f = 0; f < 4; f++) {
        #pragma unroll
        for (int p = 0; p < 4; p++) {
            float2 v = unpack2(acc[f][p]);
            ps[2 * p]     = fmaf(silu(v.x), wc[f], ps[2 * p]);
            ps[2 * p + 1] = fmaf(silu(v.y), wc[f], ps[2 * p + 1]);
        }
    }
    #pragma unroll
    for (int off = 16; off > 0; off >>= 1) {
        #pragma unroll
        for (int i = 0; i < 8; i++)
            ps[i] += __shfl_down_sync(0xffffffffu, ps[i], off);
    }
    if (g == 0) {
        float b = bv2[0];
        #pragma unroll
        for (int i = 0; i < 8; i++) s_vw[8 * eg + i] = ps[i] + b;
    }
    __syncthreads();
    if (t < NPB * 3) {
        int e = t / 3, i = t % 3;
        int n = n0 + e;
        if (n < N_NODES) {
            int idx = n * 3 + i;
            coord_out[idx] = coord[idx] + vel[idx] * s_vw[e];
        }
    }
}

// ---------------------------------------------------------------------------
extern "C" void kernel_launch(void* const* d_in, const int* in_sizes, int n_in,
                              void* d_out, int out_size)
{
    const float* h     = (const float*)d_in[0];
    const float* coord = (const float*)d_in[1];
    const float* vel   = (const float*)d_in[2];
    const int*   ei    = (const int*)  d_in[3];
    const float* We1 = (const float*)d_in[4];  const float* be1 = (const float*)d_in[5];
    const float* We2 = (const float*)d_in[6];  const float* be2 = (const float*)d_in[7];
    const float* Wc1 = (const float*)d_in[8];  const float* bc1 = (const float*)d_in[9];
    const float* Wc2 = (const float*)d_in[10]; const float* bc2 = (const float*)d_in[11];
    const float* Wv1 = (const float*)d_in[12]; const float* bv1 = (const float*)d_in[13];
    const float* Wv2 = (const float*)d_in[14]; const float* bv2 = (const float*)d_in[15];
    const float* Wn1 = (const float*)d_in[16]; const float* bn1 = (const float*)d_in[17];
    const float* Wn2 = (const float*)d_in[18]; const float* bn2 = (const float*)d_in[19];

    float* h_out     = (float*)d_out;                  // [N, 128]
    float* coord_out = (float*)d_out + N_NODES * D;    // [N, 3]

    cudaFuncSetAttribute(edge_kernel, cudaFuncAttributeMaxDynamicSharedMemorySize, EDGE_SMEM);
    cudaFuncSetAttribute(node_post_kernel, cudaFuncAttributeMaxDynamicSharedMemorySize, EDGE_SMEM);

    int edge_blocks = (N_EDGES + 127) / 128;
    int npost_blocks = (N_NODES + 127) / 128;
    int npre_blocks = (N_NODES + NPB - 1) / NPB;

    zero_mi_kernel<<<(N_NODES * D / 4 + 255) / 256, 256>>>();
    prep_bimg_kernel<<<(56 * 16 * 32 + 255) / 256, 256>>>(We1, We2, Wc1, Wn1, Wn2);
    node_pre_kernel<<<npre_blocks, 128>>>(h, coord, vel, Wv1, bv1, Wv2, bv2, coord_out);
    edge_kernel<<<edge_blocks, 256, EDGE_SMEM>>>(h, coord, ei,
                                                 be1, be2, bc1, Wc2, bc2, We1, coord_out);
    node_post_kernel<<<npost_blocks, 256, EDGE_SMEM>>>(h, bn1, bn2, h_out);
}

// round 11
// speedup vs baseline: 4.8943x; 1.2553x over previous
#include <cuda_runtime.h>
#include <cuda_bf16.h>
#include <cstdint>
#include <cstring>

#define N_NODES 50000
#define N_EDGES 500000
#define D 128
#define NPB   32
#define PITCH 36     // node_pre transposed smem pitch (floats)

#define PITCHA 136   // HMMA activation plane pitch (bf16 elements)
#define PLANE  (128 * PITCHA)

// ---------------- scratch (static device globals: allowed) ----------------
__device__ float g_mi[N_NODES * D];
__device__ float g_pa[N_NODES * D];   // h @ We1[0:128)   + be1
__device__ float g_pb[N_NODES * D];   // h @ We1[128:256)
// fragment-ordered weight image: 56 ktile-slots x 16 ntiles x 32 lanes x uint4
// slots 0-7 We1[0:128), 8-15 We1[128:256), 16-23 We2, 24-31 Wc1,
// slots 32-39 Wn1[0:128), 40-47 Wn1[128:256), 48-55 Wn2
__device__ uint4 g_bimg[56 * 16 * 32];

typedef unsigned long long ull;

__device__ __forceinline__ float silu(float x) { return x / (1.0f + __expf(-x)); }

__device__ __forceinline__ ull dup2(float v) {
    ull r; asm("mov.b64 %0, {%1, %1};" : "=l"(r) : "f"(v)); return r;
}
__device__ __forceinline__ void fma2(ull& acc, ull a, ull b) {
    asm("fma.rn.f32x2 %0, %1, %2, %0;" : "+l"(acc) : "l"(a), "l"(b));
}
__device__ __forceinline__ float2 unpack2(ull v) {
    float2 f; asm("mov.b64 {%0, %1}, %2;" : "=f"(f.x), "=f"(f.y) : "l"(v)); return f;
}

__device__ __forceinline__ uint32_t bf2_as_u32(__nv_bfloat162 v) {
    uint32_t u; memcpy(&u, &v, 4); return u;
}
__device__ __forceinline__ uint32_t smem_u32(const void* p) {
    uint32_t a;
    asm("{ .reg .u64 t; cvta.to.shared.u64 t, %1; cvt.u32.u64 %0, t; }" : "=r"(a) : "l"(p));
    return a;
}

__device__ __forceinline__ void mma_bf16(
    float* c, uint32_t a0, uint32_t a1, uint32_t a2, uint32_t a3,
    uint32_t b0, uint32_t b1)
{
    asm volatile(
        "mma.sync.aligned.m16n8k16.row.col.f32.bf16.bf16.f32 "
        "{%0,%1,%2,%3}, {%4,%5,%6,%7}, {%8,%9}, {%0,%1,%2,%3};"
        : "+f"(c[0]), "+f"(c[1]), "+f"(c[2]), "+f"(c[3])
        : "r"(a0), "r"(a1), "r"(a2), "r"(a3), "r"(b0), "r"(b1));
}

__device__ __forceinline__ void ldsm_x4(
    uint32_t& r0, uint32_t& r1, uint32_t& r2, uint32_t& r3, uint32_t addr)
{
    asm volatile("ldmatrix.sync.aligned.m8n8.x4.shared.b16 {%0,%1,%2,%3}, [%4];"
                 : "=r"(r0), "=r"(r1), "=r"(r2), "=r"(r3) : "r"(addr));
}

__device__ __forceinline__ void split_pair(
    float x, float y, __nv_bfloat162& hi, __nv_bfloat162& lo)
{
    hi = __floats2bfloat162_rn(x, y);
    lo = __floats2bfloat162_rn(x - __low2float(hi), y - __high2float(hi));
}

// ---------------------------------------------------------------------------
__global__ void zero_mi_kernel() {
    int i = blockIdx.x * blockDim.x + threadIdx.x;
    if (i < N_NODES * D / 4)
        reinterpret_cast<float4*>(g_mi)[i] = make_float4(0.f, 0.f, 0.f, 0.f);
}

// ---------------------------------------------------------------------------
__global__ void prep_bimg_kernel(
    const float* __restrict__ We1, const float* __restrict__ We2,
    const float* __restrict__ Wc1, const float* __restrict__ Wn1,
    const float* __restrict__ Wn2)
{
    int idx = blockIdx.x * 256 + threadIdx.x;
    if (idx >= 56 * 16 * 32) return;
    int lane = idx & 31;
    int nt = (idx >> 5) & 15;
    int s = idx >> 9;
    int col = nt * 8 + (lane >> 2);
    int kloc = 2 * (lane & 3);
    const float* W; int kr;
    if (s < 8)       { W = We1; kr = s * 16 + kloc; }
    else if (s < 16) { W = We1; kr = 128 + (s - 8) * 16 + kloc; }
    else if (s < 24) { W = We2; kr = (s - 16) * 16 + kloc; }
    else if (s < 32) { W = Wc1; kr = (s - 24) * 16 + kloc; }
    else if (s < 40) { W = Wn1; kr = (s - 32) * 16 + kloc; }
    else if (s < 48) { W = Wn1; kr = 128 + (s - 40) * 16 + kloc; }
    else             { W = Wn2; kr = (s - 48) * 16 + kloc; }
    float f00 = W[kr * D + col];
    float f01 = W[(kr + 1) * D + col];
    float f10 = W[(kr + 8) * D + col];
    float f11 = W[(kr + 9) * D + col];
    __nv_bfloat162 h0, l0, h1, l1;
    split_pair(f00, f01, h0, l0);
    split_pair(f10, f11, h1, l1);
    uint4 v;
    v.x = bf2_as_u32(h0); v.y = bf2_as_u32(h1);
    v.z = bf2_as_u32(l0); v.w = bf2_as_u32(l1);
    g_bimg[idx] = v;
}

// ---------------------------------------------------------------------------
// software-pipelined 128x128x128 warp-tile GEMM step (3-pass hi/lo bf16)
__device__ __forceinline__ void gemm_tile(
    float (&c)[4][4][4], uint32_t aHi_addr, int base,
    int cg, int rg, int lane)
{
    int lrow = lane & 15;
    int lcol = (lane >> 4) * 8;
    const uint4* bp = g_bimg + (base * 16 + cg * 4) * 32 + lane;
    uint4 b[4], bn[4];
    #pragma unroll
    for (int nt = 0; nt < 4; nt++) b[nt] = __ldg(bp + nt * 32);
    uint32_t abase = aHi_addr + (uint32_t)(((rg * 64 + lrow) * PITCHA + lcol) * 2);
    uint32_t ah[2][4], al[2][4];
    ldsm_x4(ah[0][0], ah[0][1], ah[0][2], ah[0][3], abase);
    ldsm_x4(al[0][0], al[0][1], al[0][2], al[0][3], abase + PLANE * 2);
    #pragma unroll
    for (int kt = 0; kt < 8; kt++) {
        if (kt < 7) {
            #pragma unroll
            for (int nt = 0; nt < 4; nt++) bn[nt] = __ldg(bp + 16 * 32 + nt * 32);
        }
        #pragma unroll
        for (int mt = 0; mt < 4; mt++) {
            int cur = mt & 1, nxt = 1 - cur;
            if (mt < 3) {
                uint32_t addr = abase + (uint32_t)((((mt + 1) * 16) * PITCHA + kt * 16) * 2);
                ldsm_x4(ah[nxt][0], ah[nxt][1], ah[nxt][2], ah[nxt][3], addr);
                ldsm_x4(al[nxt][0], al[nxt][1], al[nxt][2], al[nxt][3], addr + PLANE * 2);
            } else if (kt < 7) {
                uint32_t addr = abase + (uint32_t)(((kt + 1) * 16) * 2);
                ldsm_x4(ah[nxt][0], ah[nxt][1], ah[nxt][2], ah[nxt][3], addr);
                ldsm_x4(al[nxt][0], al[nxt][1], al[nxt][2], al[nxt][3], addr + PLANE * 2);
            }
            #pragma unroll
            for (int nt = 0; nt < 4; nt++) {
                mma_bf16(c[mt][nt], ah[cur][0], ah[cur][1], ah[cur][2], ah[cur][3], b[nt].x, b[nt].y);
                mma_bf16(c[mt][nt], ah[cur][0], ah[cur][1], ah[cur][2], ah[cur][3], b[nt].z, b[nt].w);
                mma_bf16(c[mt][nt], al[cur][0], al[cur][1], al[cur][2], al[cur][3], b[nt].x, b[nt].y);
            }
        }
        #pragma unroll
        for (int nt = 0; nt < 4; nt++) b[nt] = bn[nt];
        bp += 16 * 32;
    }
}

#define EDGE_SMEM 75776

// ---------------------------------------------------------------------------
// pab_kernel: P_A = h @ We1[0:128) + be1, P_B = h @ We1[128:256)  (per node)
__global__ __launch_bounds__(256, 2) void pab_kernel(
    const float* __restrict__ h, const float* __restrict__ be1)
{
    extern __shared__ __align__(16) char smem[];
    __nv_bfloat16* aHi = (__nv_bfloat16*)smem;
    __nv_bfloat16* aLo = aHi + PLANE;
    float* s_be1 = (float*)(smem + 69632);

    int t = threadIdx.x;
    int lane = t & 31, wid = t >> 5;
    int cg = wid & 3, rg = wid >> 2;
    int n0 = blockIdx.x * 128;
    uint32_t aHi_addr = smem_u32(aHi);

    if (t < 128) s_be1[t] = be1[t];

    // stage h rows (hi/lo)
    {
        int r = t >> 1;
        int node = n0 + r; if (node >= N_NODES) node = N_NODES - 1;
        int ch = (t & 1) * 64;
        const float* src = h + node * D + ch;
        __nv_bfloat16* ph = aHi + r * PITCHA + ch;
        __nv_bfloat16* pl = aLo + r * PITCHA + ch;
        #pragma unroll
        for (int j = 0; j < 16; j++) {
            float4 v = *(const float4*)(src + 4 * j);
            __nv_bfloat162 h2a, l2a, h2b, l2b;
            split_pair(v.x, v.y, h2a, l2a);
            split_pair(v.z, v.w, h2b, l2b);
            *(__nv_bfloat162*)(ph + 4 * j)     = h2a;
            *(__nv_bfloat162*)(ph + 4 * j + 2) = h2b;
            *(__nv_bfloat162*)(pl + 4 * j)     = l2a;
            *(__nv_bfloat162*)(pl + 4 * j + 2) = l2b;
        }
    }
    __syncthreads();

    float c[4][4][4];
    #pragma unroll
    for (int mt = 0; mt < 4; mt++)
        #pragma unroll
        for (int nt = 0; nt < 4; nt++)
            #pragma unroll
            for (int j = 0; j < 4; j++) c[mt][nt][j] = 0.f;

    int q = lane >> 2;
    int kq = 2 * (lane & 3);

    gemm_tile(c, aHi_addr, 0, cg, rg, lane);
    #pragma unroll
    for (int mt = 0; mt < 4; mt++) {
        int row0 = rg * 64 + mt * 16 + q;
        int row1 = row0 + 8;
        bool v0 = (n0 + row0) < N_NODES, v1 = (n0 + row1) < N_NODES;
        #pragma unroll
        for (int nt = 0; nt < 4; nt++) {
            int col = cg * 32 + nt * 8 + kq;
            float b0 = s_be1[col], b1 = s_be1[col + 1];
            if (v0) *(float2*)&g_pa[(n0 + row0) * D + col] =
                make_float2(c[mt][nt][0] + b0, c[mt][nt][1] + b1);
            if (v1) *(float2*)&g_pa[(n0 + row1) * D + col] =
                make_float2(c[mt][nt][2] + b0, c[mt][nt][3] + b1);
            c[mt][nt][0] = c[mt][nt][1] = c[mt][nt][2] = c[mt][nt][3] = 0.f;
        }
    }
    // plane unchanged; no sync needed
    gemm_tile(c, aHi_addr, 8, cg, rg, lane);
    #pragma unroll
    for (int mt = 0; mt < 4; mt++) {
        int row0 = rg * 64 + mt * 16 + q;
        int row1 = row0 + 8;
        bool v0 = (n0 + row0) < N_NODES, v1 = (n0 + row1) < N_NODES;
        #pragma unroll
        for (int nt = 0; nt < 4; nt++) {
            int col = cg * 32 + nt * 8 + kq;
            if (v0) *(float2*)&g_pb[(n0 + row0) * D + col] =
                make_float2(c[mt][nt][0], c[mt][nt][1]);
            if (v1) *(float2*)&g_pb[(n0 + row1) * D + col] =
                make_float2(c[mt][nt][2], c[mt][nt][3]);
        }
    }
}

// ---------------------------------------------------------------------------
// edge kernel: act1 via gather of P_A[r]+P_B[c]+rad*w256, then 2 GEMM layers
__global__ __launch_bounds__(256, 2) void edge_kernel(
    const float* __restrict__ coord,
    const int* __restrict__ ei,
    const float* __restrict__ be2,
    const float* __restrict__ bc1,
    const float* __restrict__ Wc2, const float* __restrict__ bc2,
    const float* __restrict__ We1,
    float* __restrict__ coord_out)
{
    extern __shared__ __align__(16) char smem[];
    __nv_bfloat16* aHi = (__nv_bfloat16*)smem;              // 34816 B
    __nv_bfloat16* aLo = aHi + PLANE;                       // 34816 B
    float* s_be2  = (float*)(smem + 69632);
    float* s_bc1  = s_be2 + 128;
    float* s_wc2  = s_bc1 + 128;
    float* s_w256 = s_wc2 + 128;
    int*   s_r    = (int*)(smem + 72192);
    int*   s_c    = (int*)(smem + 72704);
    float* s_rad  = (float*)(smem + 73216);
    float* s_diff = (float*)(smem + 73728);
    float* s_wp   = (float*)smem;   // L3 partials alias plane after last GEMM

    int t = threadIdx.x;
    int lane = t & 31, wid = t >> 5;
    int cg = wid & 3, rg = wid >> 2;
    int e0 = blockIdx.x * 128;

    uint32_t aHi_addr = smem_u32(aHi);

    if (t < 128) {
        s_be2[t] = be2[t]; s_bc1[t] = bc1[t];
        s_wc2[t] = Wc2[t]; s_w256[t] = We1[256 * D + t];
        int e = e0 + t;
        int cl = (e < N_EDGES) ? e : (N_EDGES - 1);
        s_r[t] = ei[cl];
        s_c[t] = ei[N_EDGES + cl];
    }
    __syncthreads();
    if (t < 128) {
        int r = s_r[t], c = s_c[t];
        float dx = coord[r * 3 + 0] - coord[c * 3 + 0];
        float dy = coord[r * 3 + 1] - coord[c * 3 + 1];
        float dz = coord[r * 3 + 2] - coord[c * 3 + 2];
        float rad = dx * dx + dy * dy + dz * dz;
        float inv = 1.0f / (sqrtf(rad) + 1e-8f);
        s_rad[t] = rad;
        s_diff[t * 3 + 0] = dx * inv;
        s_diff[t * 3 + 1] = dy * inv;
        s_diff[t * 3 + 2] = dz * inv;
    }
    __syncthreads();

    // ---- gather + act1: silu(P_A[r] + P_B[c] + rad*w256) -> plane (hi/lo) ----
    {
        int row = t >> 1;
        int ch = (t & 1) * 64;
        const float* pa = g_pa + (size_t)s_r[row] * D + ch;
        const float* pb = g_pb + (size_t)s_c[row] * D + ch;
        float rad = s_rad[row];
        __nv_bfloat16* ph = aHi + row * PITCHA + ch;
        __nv_bfloat16* pl = aLo + row * PITCHA + ch;
        #pragma unroll
        for (int j = 0; j < 16; j++) {
            float4 a = *(const float4*)(pa + 4 * j);
            float4 b = *(const float4*)(pb + 4 * j);
            float4 w = *(const float4*)(s_w256 + ch + 4 * j);
            float v0 = silu(a.x + b.x + rad * w.x);
            float v1 = silu(a.y + b.y + rad * w.y);
            float v2 = silu(a.z + b.z + rad * w.z);
            float v3 = silu(a.w + b.w + rad * w.w);
            __nv_bfloat162 h2a, l2a, h2b, l2b;
            split_pair(v0, v1, h2a, l2a);
            split_pair(v2, v3, h2b, l2b);
            *(__nv_bfloat162*)(ph + 4 * j)     = h2a;
            *(__nv_bfloat162*)(ph + 4 * j + 2) = h2b;
            *(__nv_bfloat162*)(pl + 4 * j)     = l2a;
            *(__nv_bfloat162*)(pl + 4 * j + 2) = l2b;
        }
    }
    __syncthreads();

    float c[4][4][4];
    #pragma unroll
    for (int mt = 0; mt < 4; mt++)
        #pragma unroll
        for (int nt = 0; nt < 4; nt++)
            #pragma unroll
            for (int j = 0; j < 4; j++) c[mt][nt][j] = 0.f;

    int q = lane >> 2;
    int kq = 2 * (lane & 3);

    // ============ LAYER 2: act1 @ We2 -> m_ij ============
    gemm_tile(c, aHi_addr, 16, cg, rg, lane);
    __syncthreads();
    #pragma unroll
    for (int mt = 0; mt < 4; mt++) {
        int row0 = rg * 64 + mt * 16 + q;
        int row1 = row0 + 8;
        bool v0 = (e0 + row0) < N_EDGES, v1 = (e0 + row1) < N_EDGES;
        int n0 = s_r[row0], n1 = s_r[row1];
        #pragma unroll
        for (int nt = 0; nt < 4; nt++) {
            int col = cg * 32 + nt * 8 + kq;
            float b0 = s_be2[col], b1 = s_be2[col + 1];
            float v00 = silu(c[mt][nt][0] + b0);
            float v01 = silu(c[mt][nt][1] + b1);
            float v10 = silu(c[mt][nt][2] + b0);
            float v11 = silu(c[mt][nt][3] + b1);
            __nv_bfloat162 h2, l2;
            split_pair(v00, v01, h2, l2);
            *(__nv_bfloat162*)(aHi + row0 * PITCHA + col) = h2;
            *(__nv_bfloat162*)(aLo + row0 * PITCHA + col) = l2;
            split_pair(v10, v11, h2, l2);
            *(__nv_bfloat162*)(aHi + row1 * PITCHA + col) = h2;
            *(__nv_bfloat162*)(aLo + row1 * PITCHA + col) = l2;
            if (v0) {
                atomicAdd(&g_mi[n0 * D + col], v00);
                atomicAdd(&g_mi[n0 * D + col + 1], v01);
            }
            if (v1) {
                atomicAdd(&g_mi[n1 * D + col], v10);
                atomicAdd(&g_mi[n1 * D + col + 1], v11);
            }
            c[mt][nt][0] = c[mt][nt][1] = c[mt][nt][2] = c[mt][nt][3] = 0.f;
        }
    }
    __syncthreads();

    // ============ LAYER 3: m_ij @ Wc1 -> per-edge weight ============
    gemm_tile(c, aHi_addr, 24, cg, rg, lane);
    __syncthreads();
    #pragma unroll
    for (int mt = 0; mt < 4; mt++) {
        float p0 = 0.f, p1 = 0.f;
        #pragma unroll
        for (int nt = 0; nt < 4; nt++) {
            int col = cg * 32 + nt * 8 + kq;
            float b0 = s_bc1[col], b1 = s_bc1[col + 1];
            float w0 = s_wc2[col], w1 = s_wc2[col + 1];
            p0 = fmaf(silu(c[mt][nt][0] + b0), w0, p0);
            p0 = fmaf(silu(c[mt][nt][1] + b1), w1, p0);
            p1 = fmaf(silu(c[mt][nt][2] + b0), w0, p1);
            p1 = fmaf(silu(c[mt][nt][3] + b1), w1, p1);
        }
        p0 += __shfl_xor_sync(0xffffffffu, p0, 1);
        p0 += __shfl_xor_sync(0xffffffffu, p0, 2);
        p1 += __shfl_xor_sync(0xffffffffu, p1, 1);
        p1 += __shfl_xor_sync(0xffffffffu, p1, 2);
        if ((lane & 3) == 0) {
            int row0 = rg * 64 + mt * 16 + q;
            s_wp[row0 * 4 + cg]       = p0;
            s_wp[(row0 + 8) * 4 + cg] = p1;
        }
    }
    __syncthreads();

    if (t < 128 && (e0 + t) < N_EDGES) {
        float w = s_wp[t * 4] + s_wp[t * 4 + 1] + s_wp[t * 4 + 2] + s_wp[t * 4 + 3] + bc2[0];
        int rr = s_r[t];
        atomicAdd(&coord_out[rr * 3 + 0], s_diff[t * 3 + 0] * w);
        atomicAdd(&coord_out[rr * 3 + 1], s_diff[t * 3 + 1] * w);
        atomicAdd(&coord_out[rr * 3 + 2], s_diff[t * 3 + 2] * w);
    }
}

// ---------------------------------------------------------------------------
// node_post: HMMA. [h,m_i]@Wn1 -> silu -> @Wn2  (verified in R9)
__global__ __launch_bounds__(256, 2) void node_post_kernel(
    const float* __restrict__ h,
    const float* __restrict__ bn1, const float* __restrict__ bn2,
    float* __restrict__ h_out)
{
    extern __shared__ __align__(16) char smem[];
    __nv_bfloat16* aHi = (__nv_bfloat16*)smem;
    __nv_bfloat16* aLo = aHi + PLANE;
    float* s_bn1 = (float*)(smem + 69632);
    float* s_bn2 = s_bn1 + 128;

    int t = threadIdx.x;
    int lane = t & 31, wid = t >> 5;
    int cg = wid & 3, rg = wid >> 2;
    int n0 = blockIdx.x * 128;
    uint32_t aHi_addr = smem_u32(aHi);

    if (t < 128) { s_bn1[t] = bn1[t]; s_bn2[t] = bn2[t]; }

    float c[4][4][4];
    #pragma unroll
    for (int mt = 0; mt < 4; mt++)
        #pragma unroll
        for (int nt = 0; nt < 4; nt++)
            #pragma unroll
            for (int j = 0; j < 4; j++) c[mt][nt][j] = 0.f;

    int q = lane >> 2;
    int kq = 2 * (lane & 3);

    auto stage_rows = [&](const float* base) {
        int r = t >> 1;
        int node = n0 + r; if (node >= N_NODES) node = N_NODES - 1;
        int ch = (t & 1) * 64;
        const float* src = base + node * D + ch;
        __nv_bfloat16* ph = aHi + r * PITCHA + ch;
        __nv_bfloat16* pl = aLo + r * PITCHA + ch;
        #pragma unroll
        for (int j = 0; j < 16; j++) {
            float4 v = *(const float4*)(src + 4 * j);
            __nv_bfloat162 h2a, l2a, h2b, l2b;
            split_pair(v.x, v.y, h2a, l2a);
            split_pair(v.z, v.w, h2b, l2b);
            *(__nv_bfloat162*)(ph + 4 * j)     = h2a;
            *(__nv_bfloat162*)(ph + 4 * j + 2) = h2b;
            *(__nv_bfloat162*)(pl + 4 * j)     = l2a;
            *(__nv_bfloat162*)(pl + 4 * j + 2) = l2b;
        }
    };

    stage_rows(h);
    __syncthreads();
    gemm_tile(c, aHi_addr, 32, cg, rg, lane);
    __syncthreads();
    stage_rows(g_mi);
    __syncthreads();
    gemm_tile(c, aHi_addr, 40, cg, rg, lane);
    __syncthreads();

    #pragma unroll
    for (int mt = 0; mt < 4; mt++) {
        int row0 = rg * 64 + mt * 16 + q;
        int row1 = row0 + 8;
        #pragma unroll
        for (int nt = 0; nt < 4; nt++) {
            int col = cg * 32 + nt * 8 + kq;
            float b0 = s_bn1[col], b1 = s_bn1[col + 1];
            float v00 = silu(c[mt][nt][0] + b0);
            float v01 = silu(c[mt][nt][1] + b1);
            float v10 = silu(c[mt][nt][2] + b0);
            float v11 = silu(c[mt][nt][3] + b1);
            __nv_bfloat162 h2, l2;
            split_pair(v00, v01, h2, l2);
            *(__nv_bfloat162*)(aHi + row0 * PITCHA + col) = h2;
            *(__nv_bfloat162*)(aLo + row0 * PITCHA + col) = l2;
            split_pair(v10, v11, h2, l2);
            *(__nv_bfloat162*)(aHi + row1 * PITCHA + col) = h2;
            *(__nv_bfloat162*)(aLo + row1 * PITCHA + col) = l2;
            c[mt][nt][0] = c[mt][nt][1] = c[mt][nt][2] = c[mt][nt][3] = 0.f;
        }
    }
    __syncthreads();

    gemm_tile(c, aHi_addr, 48, cg, rg, lane);

    #pragma unroll
    for (int mt = 0; mt < 4; mt++) {
        int row0 = rg * 64 + mt * 16 + q;
        int row1 = row0 + 8;
        bool v0 = (n0 + row0) < N_NODES, v1 = (n0 + row1) < N_NODES;
        #pragma unroll
        for (int nt = 0; nt < 4; nt++) {
            int col = cg * 32 + nt * 8 + kq;
            float b0 = s_bn2[col], b1 = s_bn2[col + 1];
            if (v0) {
                float2 o = make_float2(c[mt][nt][0] + b0, c[mt][nt][1] + b1);
                *(float2*)&h_out[(n0 + row0) * D + col] = o;
            }
            if (v1) {
                float2 o = make_float2(c[mt][nt][2] + b0, c[mt][nt][3] + b1);
                *(float2*)&h_out[(n0 + row1) * D + col] = o;
            }
        }
    }
}

// ---------------------------------------------------------------------------
// node_pre: f32x2 SIMT (verified; small share of runtime)
__device__ __forceinline__ void mlp_layer(
    const float* __restrict__ W, const float* __restrict__ bias,
    const float (*xT)[PITCH], int xbase, int K,
    int g, int eg, ull acc[4][4])
{
    float4 b4 = *reinterpret_cast<const float4*>(bias + 4 * g);
    {
        ull b0 = dup2(b4.x), b1 = dup2(b4.y), b2 = dup2(b4.z), b3 = dup2(b4.w);
        #pragma unroll
        for (int p = 0; p < 4; p++) { acc[0][p] = b0; acc[1][p] = b1; acc[2][p] = b2; acc[3][p] = b3; }
    }
    #pragma unroll 4
    for (int k = 0; k < K; k++) {
        float4 w = *reinterpret_cast<const float4*>(W + k * D + 4 * g);
        ull w0 = dup2(w.x), w1 = dup2(w.y), w2 = dup2(w.z), w3 = dup2(w.w);
        const float* xr = xT[xbase + k] + 8 * eg;
        ulonglong2 xa = *reinterpret_cast<const ulonglong2*>(xr);
        ulonglong2 xb = *reinterpret_cast<const ulonglong2*>(xr + 4);
        fma2(acc[0][0], xa.x, w0); fma2(acc[0][1], xa.y, w0);
        fma2(acc[0][2], xb.x, w0); fma2(acc[0][3], xb.y, w0);
        fma2(acc[1][0], xa.x, w1); fma2(acc[1][1], xa.y, w1);
        fma2(acc[1][2], xb.x, w1); fma2(acc[1][3], xb.y, w1);
        fma2(acc[2][0], xa.x, w2); fma2(acc[2][1], xa.y, w2);
        fma2(acc[2][2], xb.x, w2); fma2(acc[2][3], xb.y, w2);
        fma2(acc[3][0], xa.x, w3); fma2(acc[3][1], xa.y, w3);
        fma2(acc[3][2], xb.x, w3); fma2(acc[3][3], xb.y, w3);
    }
}

__global__ __launch_bounds__(128) void node_pre_kernel(
    const float* __restrict__ h, const float* __restrict__ coord,
    const float* __restrict__ vel,
    const float* __restrict__ Wv1, const float* __restrict__ bv1,
    const float* __restrict__ Wv2, const float* __restrict__ bv2,
    float* __restrict__ coord_out)
{
    __shared__ __align__(16) float s_xT[D][PITCH];
    __shared__ float s_vw[NPB];
    int t = threadIdx.x;
    int g = t & 31, eg = t >> 5;
    int n0 = blockIdx.x * NPB;

    #pragma unroll 4
    for (int e = 0; e < NPB; e++) {
        int n = n0 + e; if (n >= N_NODES) n = N_NODES - 1;
        s_xT[t][e] = h[n * D + t];
    }
    __syncthreads();

    ull acc[4][4];
    mlp_layer(Wv1, bv1, s_xT, 0, D, g, eg, acc);

    float4 wv = *reinterpret_cast<const float4*>(Wv2 + 4 * g);
    float wc[4] = {wv.x, wv.y, wv.z, wv.w};
    float ps[8];
    #pragma unroll
    for (int i = 0; i < 8; i++) ps[i] = 0.f;
    #pragma unroll
    for (int f = 0; f < 4; f++) {
        #pragma unroll
        for (int p = 0; p < 4; p++) {
            float2 v = unpack2(acc[f][p]);
            ps[2 * p]     = fmaf(silu(v.x), wc[f], ps[2 * p]);
            ps[2 * p + 1] = fmaf(silu(v.y), wc[f], ps[2 * p + 1]);
        }
    }
    #pragma unroll
    for (int off = 16; off > 0; off >>= 1) {
        #pragma unroll
        for (int i = 0; i < 8; i++)
            ps[i] += __shfl_down_sync(0xffffffffu, ps[i], off);
    }
    if (g == 0) {
        float b = bv2[0];
        #pragma unroll
        for (int i = 0; i < 8; i++) s_vw[8 * eg + i] = ps[i] + b;
    }
    __syncthreads();
    if (t < NPB * 3) {
        int e = t / 3, i = t % 3;
        int n = n0 + e;
        if (n < N_NODES) {
            int idx = n * 3 + i;
            coord_out[idx] = coord[idx] + vel[idx] * s_vw[e];
        }
    }
}

// ---------------------------------------------------------------------------
extern "C" void kernel_launch(void* const* d_in, const int* in_sizes, int n_in,
                              void* d_out, int out_size)
{
    const float* h     = (const float*)d_in[0];
    const float* coord = (const float*)d_in[1];
    const float* vel   = (const float*)d_in[2];
    const int*   ei    = (const int*)  d_in[3];
    const float* We1 = (const float*)d_in[4];  const float* be1 = (const float*)d_in[5];
    const float* We2 = (const float*)d_in[6];  const float* be2 = (const float*)d_in[7];
    const float* Wc1 = (const float*)d_in[8];  const float* bc1 = (const float*)d_in[9];
    const float* Wc2 = (const float*)d_in[10]; const float* bc2 = (const float*)d_in[11];
    const float* Wv1 = (const float*)d_in[12]; const float* bv1 = (const float*)d_in[13];
    const float* Wv2 = (const float*)d_in[14]; const float* bv2 = (const float*)d_in[15];
    const float* Wn1 = (const float*)d_in[16]; const float* bn1 = (const float*)d_in[17];
    const float* Wn2 = (const float*)d_in[18]; const float* bn2 = (const float*)d_in[19];

    float* h_out     = (float*)d_out;                  // [N, 128]
    float* coord_out = (float*)d_out + N_NODES * D;    // [N, 3]

    cudaFuncSetAttribute(edge_kernel, cudaFuncAttributeMaxDynamicSharedMemorySize, EDGE_SMEM);
    cudaFuncSetAttribute(node_post_kernel, cudaFuncAttributeMaxDynamicSharedMemorySize, EDGE_SMEM);
    cudaFuncSetAttribute(pab_kernel, cudaFuncAttributeMaxDynamicSharedMemorySize, EDGE_SMEM);

    int edge_blocks = (N_EDGES + 127) / 128;
    int nblk128 = (N_NODES + 127) / 128;
    int npre_blocks = (N_NODES + NPB - 1) / NPB;

    zero_mi_kernel<<<(N_NODES * D / 4 + 255) / 256, 256>>>();
    prep_bimg_kernel<<<(56 * 16 * 32 + 255) / 256, 256>>>(We1, We2, Wc1, Wn1, Wn2);
    pab_kernel<<<nblk128, 256, EDGE_SMEM>>>(h, be1);
    node_pre_kernel<<<npre_blocks, 128>>>(h, coord, vel, Wv1, bv1, Wv2, bv2, coord_out);
    edge_kernel<<<edge_blocks, 256, EDGE_SMEM>>>(coord, ei,
                                                 be2, bc1, Wc2, bc2, We1, coord_out);
    node_post_kernel<<<nblk128, 256, EDGE_SMEM>>>(h, bn1, bn2, h_out);
}

// round 12
// speedup vs baseline: 5.2637x; 1.0755x over previous
#include <cuda_runtime.h>
#include <cuda_bf16.h>
#include <cstdint>
#include <cstring>

#define N_NODES 50000
#define N_EDGES 500000
#define D 128

#define PITCHA 136   // HMMA activation plane pitch (bf16 elements)
#define PLANE  (128 * PITCHA)

// ---------------- scratch (static device globals: allowed) ----------------
__device__ float g_mi[N_NODES * D];
__device__ float g_pa[N_NODES * D];   // h @ We1[0:128)   + be1
__device__ float g_pb[N_NODES * D];   // h @ We1[128:256)
// fragment-ordered weight image: 64 ktile-slots x 16 ntiles x 32 lanes x uint4
// 0-7 We1[0:128), 8-15 We1[128:256), 16-23 We2, 24-31 Wc1,
// 32-39 Wn1[0:128), 40-47 Wn1[128:256), 48-55 Wn2, 56-63 Wv1
__device__ uint4 g_bimg[64 * 16 * 32];

__device__ __forceinline__ float silu(float x) { return x / (1.0f + __expf(-x)); }

__device__ __forceinline__ uint32_t bf2_as_u32(__nv_bfloat162 v) {
    uint32_t u; memcpy(&u, &v, 4); return u;
}
__device__ __forceinline__ uint32_t smem_u32(const void* p) {
    uint32_t a;
    asm("{ .reg .u64 t; cvta.to.shared.u64 t, %1; cvt.u32.u64 %0, t; }" : "=r"(a) : "l"(p));
    return a;
}

__device__ __forceinline__ void mma_bf16(
    float* c, uint32_t a0, uint32_t a1, uint32_t a2, uint32_t a3,
    uint32_t b0, uint32_t b1)
{
    asm volatile(
        "mma.sync.aligned.m16n8k16.row.col.f32.bf16.bf16.f32 "
        "{%0,%1,%2,%3}, {%4,%5,%6,%7}, {%8,%9}, {%0,%1,%2,%3};"
        : "+f"(c[0]), "+f"(c[1]), "+f"(c[2]), "+f"(c[3])
        : "r"(a0), "r"(a1), "r"(a2), "r"(a3), "r"(b0), "r"(b1));
}

__device__ __forceinline__ void ldsm_x4(
    uint32_t& r0, uint32_t& r1, uint32_t& r2, uint32_t& r3, uint32_t addr)
{
    asm volatile("ldmatrix.sync.aligned.m8n8.x4.shared.b16 {%0,%1,%2,%3}, [%4];"
                 : "=r"(r0), "=r"(r1), "=r"(r2), "=r"(r3) : "r"(addr));
}

__device__ __forceinline__ void split_pair(
    float x, float y, __nv_bfloat162& hi, __nv_bfloat162& lo)
{
    hi = __floats2bfloat162_rn(x, y);
    lo = __floats2bfloat162_rn(x - __low2float(hi), y - __high2float(hi));
}

// ---------------------------------------------------------------------------
__global__ void zero_mi_kernel() {
    int i = blockIdx.x * blockDim.x + threadIdx.x;
    if (i < N_NODES * D / 4)
        reinterpret_cast<float4*>(g_mi)[i] = make_float4(0.f, 0.f, 0.f, 0.f);
}

// ---------------------------------------------------------------------------
__global__ void prep_bimg_kernel(
    const float* __restrict__ We1, const float* __restrict__ We2,
    const float* __restrict__ Wc1, const float* __restrict__ Wn1,
    const float* __restrict__ Wn2, const float* __restrict__ Wv1)
{
    int idx = blockIdx.x * 256 + threadIdx.x;
    if (idx >= 64 * 16 * 32) return;
    int lane = idx & 31;
    int nt = (idx >> 5) & 15;
    int s = idx >> 9;
    int col = nt * 8 + (lane >> 2);
    int kloc = 2 * (lane & 3);
    const float* W; int kr;
    if (s < 8)       { W = We1; kr = s * 16 + kloc; }
    else if (s < 16) { W = We1; kr = 128 + (s - 8) * 16 + kloc; }
    else if (s < 24) { W = We2; kr = (s - 16) * 16 + kloc; }
    else if (s < 32) { W = Wc1; kr = (s - 24) * 16 + kloc; }
    else if (s < 40) { W = Wn1; kr = (s - 32) * 16 + kloc; }
    else if (s < 48) { W = Wn1; kr = 128 + (s - 40) * 16 + kloc; }
    else if (s < 56) { W = Wn2; kr = (s - 48) * 16 + kloc; }
    else             { W = Wv1; kr = (s - 56) * 16 + kloc; }
    float f00 = W[kr * D + col];
    float f01 = W[(kr + 1) * D + col];
    float f10 = W[(kr + 8) * D + col];
    float f11 = W[(kr + 9) * D + col];
    __nv_bfloat162 h0, l0, h1, l1;
    split_pair(f00, f01, h0, l0);
    split_pair(f10, f11, h1, l1);
    uint4 v;
    v.x = bf2_as_u32(h0); v.y = bf2_as_u32(h1);
    v.z = bf2_as_u32(l0); v.w = bf2_as_u32(l1);
    g_bimg[idx] = v;
}

// ---------------------------------------------------------------------------
// software-pipelined 128x128x128 warp-tile GEMM step (3-pass hi/lo bf16)
__device__ __forceinline__ void gemm_tile(
    float (&c)[4][4][4], uint32_t aHi_addr, int base,
    int cg, int rg, int lane)
{
    int lrow = lane & 15;
    int lcol = (lane >> 4) * 8;
    const uint4* bp = g_bimg + (base * 16 + cg * 4) * 32 + lane;
    uint4 b[4], bn[4];
    #pragma unroll
    for (int nt = 0; nt < 4; nt++) b[nt] = __ldg(bp + nt * 32);
    uint32_t abase = aHi_addr + (uint32_t)(((rg * 64 + lrow) * PITCHA + lcol) * 2);
    uint32_t ah[2][4], al[2][4];
    ldsm_x4(ah[0][0], ah[0][1], ah[0][2], ah[0][3], abase);
    ldsm_x4(al[0][0], al[0][1], al[0][2], al[0][3], abase + PLANE * 2);
    #pragma unroll
    for (int kt = 0; kt < 8; kt++) {
        if (kt < 7) {
            #pragma unroll
            for (int nt = 0; nt < 4; nt++) bn[nt] = __ldg(bp + 16 * 32 + nt * 32);
        }
        #pragma unroll
        for (int mt = 0; mt < 4; mt++) {
            int cur = mt & 1, nxt = 1 - cur;
            if (mt < 3) {
                uint32_t addr = abase + (uint32_t)((((mt + 1) * 16) * PITCHA + kt * 16) * 2);
                ldsm_x4(ah[nxt][0], ah[nxt][1], ah[nxt][2], ah[nxt][3], addr);
                ldsm_x4(al[nxt][0], al[nxt][1], al[nxt][2], al[nxt][3], addr + PLANE * 2);
            } else if (kt < 7) {
                uint32_t addr = abase + (uint32_t)(((kt + 1) * 16) * 2);
                ldsm_x4(ah[nxt][0], ah[nxt][1], ah[nxt][2], ah[nxt][3], addr);
                ldsm_x4(al[nxt][0], al[nxt][1], al[nxt][2], al[nxt][3], addr + PLANE * 2);
            }
            #pragma unroll
            for (int nt = 0; nt < 4; nt++) {
                mma_bf16(c[mt][nt], ah[cur][0], ah[cur][1], ah[cur][2], ah[cur][3], b[nt].x, b[nt].y);
                mma_bf16(c[mt][nt], ah[cur][0], ah[cur][1], ah[cur][2], ah[cur][3], b[nt].z, b[nt].w);
                mma_bf16(c[mt][nt], al[cur][0], al[cur][1], al[cur][2], al[cur][3], b[nt].x, b[nt].y);
            }
        }
        #pragma unroll
        for (int nt = 0; nt < 4; nt++) b[nt] = bn[nt];
        bp += 16 * 32;
    }
}

#define EDGE_SMEM 75776

// ---------------------------------------------------------------------------
// pab_kernel: per node, from one staged h tile:
//   P_A = h @ We1[0:128) + be1 ; P_B = h @ We1[128:256)
//   vw  = silu(h @ Wv1 + bv1) . Wv2 + bv2 ;  coord_out = coord + vel * vw
__global__ __launch_bounds__(256, 2) void pab_kernel(
    const float* __restrict__ h, const float* __restrict__ be1,
    const float* __restrict__ coord, const float* __restrict__ vel,
    const float* __restrict__ bv1, const float* __restrict__ Wv2,
    const float* __restrict__ bv2,
    float* __restrict__ coord_out)
{
    extern __shared__ __align__(16) char smem[];
    __nv_bfloat16* aHi = (__nv_bfloat16*)smem;
    __nv_bfloat16* aLo = aHi + PLANE;
    float* s_be1 = (float*)(smem + 69632);
    float* s_bv1 = s_be1 + 128;
    float* s_wv2 = s_bv1 + 128;
    float* s_wp  = (float*)smem;   // partials alias plane after last GEMM

    int t = threadIdx.x;
    int lane = t & 31, wid = t >> 5;
    int cg = wid & 3, rg = wid >> 2;
    int n0 = blockIdx.x * 128;
    uint32_t aHi_addr = smem_u32(aHi);

    if (t < 128) { s_be1[t] = be1[t]; s_bv1[t] = bv1[t]; s_wv2[t] = Wv2[t]; }

    // stage h rows (hi/lo)
    {
        int r = t >> 1;
        int node = n0 + r; if (node >= N_NODES) node = N_NODES - 1;
        int ch = (t & 1) * 64;
        const float* src = h + node * D + ch;
        __nv_bfloat16* ph = aHi + r * PITCHA + ch;
        __nv_bfloat16* pl = aLo + r * PITCHA + ch;
        #pragma unroll
        for (int j = 0; j < 16; j++) {
            float4 v = *(const float4*)(src + 4 * j);
            __nv_bfloat162 h2a, l2a, h2b, l2b;
            split_pair(v.x, v.y, h2a, l2a);
            split_pair(v.z, v.w, h2b, l2b);
            *(__nv_bfloat162*)(ph + 4 * j)     = h2a;
            *(__nv_bfloat162*)(ph + 4 * j + 2) = h2b;
            *(__nv_bfloat162*)(pl + 4 * j)     = l2a;
            *(__nv_bfloat162*)(pl + 4 * j + 2) = l2b;
        }
    }
    __syncthreads();

    float c[4][4][4];
    #pragma unroll
    for (int mt = 0; mt < 4; mt++)
        #pragma unroll
        for (int nt = 0; nt < 4; nt++)
            #pragma unroll
            for (int j = 0; j < 4; j++) c[mt][nt][j] = 0.f;

    int q = lane >> 2;
    int kq = 2 * (lane & 3);

    // ---- P_A ----
    gemm_tile(c, aHi_addr, 0, cg, rg, lane);
    #pragma unroll
    for (int mt = 0; mt < 4; mt++) {
        int row0 = rg * 64 + mt * 16 + q;
        int row1 = row0 + 8;
        bool v0 = (n0 + row0) < N_NODES, v1 = (n0 + row1) < N_NODES;
        #pragma unroll
        for (int nt = 0; nt < 4; nt++) {
            int col = cg * 32 + nt * 8 + kq;
            float b0 = s_be1[col], b1 = s_be1[col + 1];
            if (v0) *(float2*)&g_pa[(n0 + row0) * D + col] =
                make_float2(c[mt][nt][0] + b0, c[mt][nt][1] + b1);
            if (v1) *(float2*)&g_pa[(n0 + row1) * D + col] =
                make_float2(c[mt][nt][2] + b0, c[mt][nt][3] + b1);
            c[mt][nt][0] = c[mt][nt][1] = c[mt][nt][2] = c[mt][nt][3] = 0.f;
        }
    }
    // ---- P_B ---- (plane unchanged)
    gemm_tile(c, aHi_addr, 8, cg, rg, lane);
    #pragma unroll
    for (int mt = 0; mt < 4; mt++) {
        int row0 = rg * 64 + mt * 16 + q;
        int row1 = row0 + 8;
        bool v0 = (n0 + row0) < N_NODES, v1 = (n0 + row1) < N_NODES;
        #pragma unroll
        for (int nt = 0; nt < 4; nt++) {
            int col = cg * 32 + nt * 8 + kq;
            if (v0) *(float2*)&g_pb[(n0 + row0) * D + col] =
                make_float2(c[mt][nt][0], c[mt][nt][1]);
            if (v1) *(float2*)&g_pb[(n0 + row1) * D + col] =
                make_float2(c[mt][nt][2], c[mt][nt][3]);
            c[mt][nt][0] = c[mt][nt][1] = c[mt][nt][2] = c[mt][nt][3] = 0.f;
        }
    }
    // ---- vel weights ----
    gemm_tile(c, aHi_addr, 56, cg, rg, lane);
    __syncthreads();   // everyone done reading plane; s_wp may alias it
    #pragma unroll
    for (int mt = 0; mt < 4; mt++) {
        float p0 = 0.f, p1 = 0.f;
        #pragma unroll
        for (int nt = 0; nt < 4; nt++) {
            int col = cg * 32 + nt * 8 + kq;
            float b0 = s_bv1[col], b1 = s_bv1[col + 1];
            float w0 = s_wv2[col], w1 = s_wv2[col + 1];
            p0 = fmaf(silu(c[mt][nt][0] + b0), w0, p0);
            p0 = fmaf(silu(c[mt][nt][1] + b1), w1, p0);
            p1 = fmaf(silu(c[mt][nt][2] + b0), w0, p1);
            p1 = fmaf(silu(c[mt][nt][3] + b1), w1, p1);
        }
        p0 += __shfl_xor_sync(0xffffffffu, p0, 1);
        p0 += __shfl_xor_sync(0xffffffffu, p0, 2);
        p1 += __shfl_xor_sync(0xffffffffu, p1, 1);
        p1 += __shfl_xor_sync(0xffffffffu, p1, 2);
        if ((lane & 3) == 0) {
            int row0 = rg * 64 + mt * 16 + q;
            s_wp[row0 * 4 + cg]       = p0;
            s_wp[(row0 + 8) * 4 + cg] = p1;
        }
    }
    __syncthreads();
    if (t < 128 && (n0 + t) < N_NODES) {
        float vw = s_wp[t * 4] + s_wp[t * 4 + 1] + s_wp[t * 4 + 2] + s_wp[t * 4 + 3] + bv2[0];
        int n = n0 + t;
        #pragma unroll
        for (int i = 0; i < 3; i++)
            coord_out[n * 3 + i] = coord[n * 3 + i] + vel[n * 3 + i] * vw;
    }
}

// ---------------------------------------------------------------------------
// edge kernel: act1 via gather of P_A[r]+P_B[c]+rad*w256, then 2 GEMM layers
__global__ __launch_bounds__(256, 2) void edge_kernel(
    const float* __restrict__ coord,
    const int* __restrict__ ei,
    const float* __restrict__ be2,
    const float* __restrict__ bc1,
    const float* __restrict__ Wc2, const float* __restrict__ bc2,
    const float* __restrict__ We1,
    float* __restrict__ coord_out)
{
    extern __shared__ __align__(16) char smem[];
    __nv_bfloat16* aHi = (__nv_bfloat16*)smem;              // 34816 B
    __nv_bfloat16* aLo = aHi + PLANE;                       // 34816 B
    float* s_be2  = (float*)(smem + 69632);
    float* s_bc1  = s_be2 + 128;
    float* s_wc2  = s_bc1 + 128;
    float* s_w256 = s_wc2 + 128;
    int*   s_r    = (int*)(smem + 72192);
    int*   s_c    = (int*)(smem + 72704);
    float* s_rad  = (float*)(smem + 73216);
    float* s_diff = (float*)(smem + 73728);
    float* s_wp   = (float*)smem;   // L3 partials alias plane after last GEMM

    int t = threadIdx.x;
    int lane = t & 31, wid = t >> 5;
    int cg = wid & 3, rg = wid >> 2;
    int e0 = blockIdx.x * 128;

    uint32_t aHi_addr = smem_u32(aHi);

    // single-sync prologue: indices + geometry in registers, biases in parallel
    if (t < 128) {
        s_be2[t] = be2[t]; s_bc1[t] = bc1[t];
        s_wc2[t] = Wc2[t]; s_w256[t] = We1[256 * D + t];
        int e = e0 + t;
        int cl = (e < N_EDGES) ? e : (N_EDGES - 1);
        int r = ei[cl], c = ei[N_EDGES + cl];
        s_r[t] = r; s_c[t] = c;
        float dx = coord[r * 3 + 0] - coord[c * 3 + 0];
        float dy = coord[r * 3 + 1] - coord[c * 3 + 1];
        float dz = coord[r * 3 + 2] - coord[c * 3 + 2];
        float rad = dx * dx + dy * dy + dz * dz;
        float inv = 1.0f / (sqrtf(rad) + 1e-8f);
        s_rad[t] = rad;
        s_diff[t * 3 + 0] = dx * inv;
        s_diff[t * 3 + 1] = dy * inv;
        s_diff[t * 3 + 2] = dz * inv;
    }
    __syncthreads();

    // ---- gather + act1: silu(P_A[r] + P_B[c] + rad*w256) -> plane (hi/lo) ----
    {
        int row = t >> 1;
        int ch = (t & 1) * 64;
        const float* pa = g_pa + (size_t)s_r[row] * D + ch;
        const float* pb = g_pb + (size_t)s_c[row] * D + ch;
        float rad = s_rad[row];
        __nv_bfloat16* ph = aHi + row * PITCHA + ch;
        __nv_bfloat16* pl = aLo + row * PITCHA + ch;
        #pragma unroll
        for (int j = 0; j < 16; j++) {
            float4 a = *(const float4*)(pa + 4 * j);
            float4 b = *(const float4*)(pb + 4 * j);
            float4 w = *(const float4*)(s_w256 + ch + 4 * j);
            float v0 = silu(a.x + b.x + rad * w.x);
            float v1 = silu(a.y + b.y + rad * w.y);
            float v2 = silu(a.z + b.z + rad * w.z);
            float v3 = silu(a.w + b.w + rad * w.w);
            __nv_bfloat162 h2a, l2a, h2b, l2b;
            split_pair(v0, v1, h2a, l2a);
            split_pair(v2, v3, h2b, l2b);
            *(__nv_bfloat162*)(ph + 4 * j)     = h2a;
            *(__nv_bfloat162*)(ph + 4 * j + 2) = h2b;
            *(__nv_bfloat162*)(pl + 4 * j)     = l2a;
            *(__nv_bfloat162*)(pl + 4 * j + 2) = l2b;
        }
    }
    __syncthreads();

    float c[4][4][4];
    #pragma unroll
    for (int mt = 0; mt < 4; mt++)
        #pragma unroll
        for (int nt = 0; nt < 4; nt++)
            #pragma unroll
            for (int j = 0; j < 4; j++) c[mt][nt][j] = 0.f;

    int q = lane >> 2;
    int kq = 2 * (lane & 3);

    // ============ LAYER 2: act1 @ We2 -> m_ij ============
    gemm_tile(c, aHi_addr, 16, cg, rg, lane);
    __syncthreads();
    #pragma unroll
    for (int mt = 0; mt < 4; mt++) {
        int row0 = rg * 64 + mt * 16 + q;
        int row1 = row0 + 8;
        bool v0 = (e0 + row0) < N_EDGES, v1 = (e0 + row1) < N_EDGES;
        int n0 = s_r[row0], n1 = s_r[row1];
        #pragma unroll
        for (int nt = 0; nt < 4; nt++) {
            int col = cg * 32 + nt * 8 + kq;
            float b0 = s_be2[col], b1 = s_be2[col + 1];
            float v00 = silu(c[mt][nt][0] + b0);
            float v01 = silu(c[mt][nt][1] + b1);
            float v10 = silu(c[mt][nt][2] + b0);
            float v11 = silu(c[mt][nt][3] + b1);
            __nv_bfloat162 h2, l2;
            split_pair(v00, v01, h2, l2);
            *(__nv_bfloat162*)(aHi + row0 * PITCHA + col) = h2;
            *(__nv_bfloat162*)(aLo + row0 * PITCHA + col) = l2;
            split_pair(v10, v11, h2, l2);
            *(__nv_bfloat162*)(aHi + row1 * PITCHA + col) = h2;
            *(__nv_bfloat162*)(aLo + row1 * PITCHA + col) = l2;
            if (v0) {
                atomicAdd(&g_mi[n0 * D + col], v00);
                atomicAdd(&g_mi[n0 * D + col + 1], v01);
            }
            if (v1) {
                atomicAdd(&g_mi[n1 * D + col], v10);
                atomicAdd(&g_mi[n1 * D + col + 1], v11);
            }
            c[mt][nt][0] = c[mt][nt][1] = c[mt][nt][2] = c[mt][nt][3] = 0.f;
        }
    }
    __syncthreads();

    // ============ LAYER 3: m_ij @ Wc1 -> per-edge weight ============
    gemm_tile(c, aHi_addr, 24, cg, rg, lane);
    __syncthreads();
    #pragma unroll
    for (int mt = 0; mt < 4; mt++) {
        float p0 = 0.f, p1 = 0.f;
        #pragma unroll
        for (int nt = 0; nt < 4; nt++) {
            int col = cg * 32 + nt * 8 + kq;
            float b0 = s_bc1[col], b1 = s_bc1[col + 1];
            float w0 = s_wc2[col], w1 = s_wc2[col + 1];
            p0 = fmaf(silu(c[mt][nt][0] + b0), w0, p0);
            p0 = fmaf(silu(c[mt][nt][1] + b1), w1, p0);
            p1 = fmaf(silu(c[mt][nt][2] + b0), w0, p1);
            p1 = fmaf(silu(c[mt][nt][3] + b1), w1, p1);
        }
        p0 += __shfl_xor_sync(0xffffffffu, p0, 1);
        p0 += __shfl_xor_sync(0xffffffffu, p0, 2);
        p1 += __shfl_xor_sync(0xffffffffu, p1, 1);
        p1 += __shfl_xor_sync(0xffffffffu, p1, 2);
        if ((lane & 3) == 0) {
            int row0 = rg * 64 + mt * 16 + q;
            s_wp[row0 * 4 + cg]       = p0;
            s_wp[(row0 + 8) * 4 + cg] = p1;
        }
    }
    __syncthreads();

    if (t < 128 && (e0 + t) < N_EDGES) {
        float w = s_wp[t * 4] + s_wp[t * 4 + 1] + s_wp[t * 4 + 2] + s_wp[t * 4 + 3] + bc2[0];
        int rr = s_r[t];
        atomicAdd(&coord_out[rr * 3 + 0], s_diff[t * 3 + 0] * w);
        atomicAdd(&coord_out[rr * 3 + 1], s_diff[t * 3 + 1] * w);
        atomicAdd(&coord_out[rr * 3 + 2], s_diff[t * 3 + 2] * w);
    }
}

// ---------------------------------------------------------------------------
// node_post: HMMA. [h,m_i]@Wn1 -> silu -> @Wn2  (verified in R9/R10)
__global__ __launch_bounds__(256, 2) void node_post_kernel(
    const float* __restrict__ h,
    const float* __restrict__ bn1, const float* __restrict__ bn2,
    float* __restrict__ h_out)
{
    extern __shared__ __align__(16) char smem[];
    __nv_bfloat16* aHi = (__nv_bfloat16*)smem;
    __nv_bfloat16* aLo = aHi + PLANE;
    float* s_bn1 = (float*)(smem + 69632);
    float* s_bn2 = s_bn1 + 128;

    int t = threadIdx.x;
    int lane = t & 31, wid = t >> 5;
    int cg = wid & 3, rg = wid >> 2;
    int n0 = blockIdx.x * 128;
    uint32_t aHi_addr = smem_u32(aHi);

    if (t < 128) { s_bn1[t] = bn1[t]; s_bn2[t] = bn2[t]; }

    float c[4][4][4];
    #pragma unroll
    for (int mt = 0; mt < 4; mt++)
        #pragma unroll
        for (int nt = 0; nt < 4; nt++)
            #pragma unroll
            for (int j = 0; j < 4; j++) c[mt][nt][j] = 0.f;

    int q = lane >> 2;
    int kq = 2 * (lane & 3);

    auto stage_rows = [&](const float* base) {
        int r = t >> 1;
        int node = n0 + r; if (node >= N_NODES) node = N_NODES - 1;
        int ch = (t & 1) * 64;
        const float* src = base + node * D + ch;
        __nv_bfloat16* ph = aHi + r * PITCHA + ch;
        __nv_bfloat16* pl = aLo + r * PITCHA + ch;
        #pragma unroll
        for (int j = 0; j < 16; j++) {
            float4 v = *(const float4*)(src + 4 * j);
            __nv_bfloat162 h2a, l2a, h2b, l2b;
            split_pair(v.x, v.y, h2a, l2a);
            split_pair(v.z, v.w, h2b, l2b);
            *(__nv_bfloat162*)(ph + 4 * j)     = h2a;
            *(__nv_bfloat162*)(ph + 4 * j + 2) = h2b;
            *(__nv_bfloat162*)(pl + 4 * j)     = l2a;
            *(__nv_bfloat162*)(pl + 4 * j + 2) = l2b;
        }
    };

    stage_rows(h);
    __syncthreads();
    gemm_tile(c, aHi_addr, 32, cg, rg, lane);
    __syncthreads();
    stage_rows(g_mi);
    __syncthreads();
    gemm_tile(c, aHi_addr, 40, cg, rg, lane);
    __syncthreads();

    #pragma unroll
    for (int mt = 0; mt < 4; mt++) {
        int row0 = rg * 64 + mt * 16 + q;
        int row1 = row0 + 8;
        #pragma unroll
        for (int nt = 0; nt < 4; nt++) {
            int col = cg * 32 + nt * 8 + kq;
            float b0 = s_bn1[col], b1 = s_bn1[col + 1];
            float v00 = silu(c[mt][nt][0] + b0);
            float v01 = silu(c[mt][nt][1] + b1);
            float v10 = silu(c[mt][nt][2] + b0);
            float v11 = silu(c[mt][nt][3] + b1);
            __nv_bfloat162 h2, l2;
            split_pair(v00, v01, h2, l2);
            *(__nv_bfloat162*)(aHi + row0 * PITCHA + col) = h2;
            *(__nv_bfloat162*)(aLo + row0 * PITCHA + col) = l2;
            split_pair(v10, v11, h2, l2);
            *(__nv_bfloat162*)(aHi + row1 * PITCHA + col) = h2;
            *(__nv_bfloat162*)(aLo + row1 * PITCHA + col) = l2;
            c[mt][nt][0] = c[mt][nt][1] = c[mt][nt][2] = c[mt][nt][3] = 0.f;
        }
    }
    __syncthreads();

    gemm_tile(c, aHi_addr, 48, cg, rg, lane);

    #pragma unroll
    for (int mt = 0; mt < 4; mt++) {
        int row0 = rg * 64 + mt * 16 + q;
        int row1 = row0 + 8;
        bool v0 = (n0 + row0) < N_NODES, v1 = (n0 + row1) < N_NODES;
        #pragma unroll
        for (int nt = 0; nt < 4; nt++) {
            int col = cg * 32 + nt * 8 + kq;
            float b0 = s_bn2[col], b1 = s_bn2[col + 1];
            if (v0) {
                float2 o = make_float2(c[mt][nt][0] + b0, c[mt][nt][1] + b1);
                *(float2*)&h_out[(n0 + row0) * D + col] = o;
            }
            if (v1) {
                float2 o = make_float2(c[mt][nt][2] + b0, c[mt][nt][3] + b1);
                *(float2*)&h_out[(n0 + row1) * D + col] = o;
            }
        }
    }
}

// ---------------------------------------------------------------------------
extern "C" void kernel_launch(void* const* d_in, const int* in_sizes, int n_in,
                              void* d_out, int out_size)
{
    const float* h     = (const float*)d_in[0];
    const float* coord = (const float*)d_in[1];
    const float* vel   = (const float*)d_in[2];
    const int*   ei    = (const int*)  d_in[3];
    const float* We1 = (const float*)d_in[4];  const float* be1 = (const float*)d_in[5];
    const float* We2 = (const float*)d_in[6];  const float* be2 = (const float*)d_in[7];
    const float* Wc1 = (const float*)d_in[8];  const float* bc1 = (const float*)d_in[9];
    const float* Wc2 = (const float*)d_in[10]; const float* bc2 = (const float*)d_in[11];
    const float* Wv1 = (const float*)d_in[12]; const float* bv1 = (const float*)d_in[13];
    const float* Wv2 = (const float*)d_in[14]; const float* bv2 = (const float*)d_in[15];
    const float* Wn1 = (const float*)d_in[16]; const float* bn1 = (const float*)d_in[17];
    const float* Wn2 = (const float*)d_in[18]; const float* bn2 = (const float*)d_in[19];

    float* h_out     = (float*)d_out;                  // [N, 128]
    float* coord_out = (float*)d_out + N_NODES * D;    // [N, 3]

    cudaFuncSetAttribute(edge_kernel, cudaFuncAttributeMaxDynamicSharedMemorySize, EDGE_SMEM);
    cudaFuncSetAttribute(node_post_kernel, cudaFuncAttributeMaxDynamicSharedMemorySize, EDGE_SMEM);
    cudaFuncSetAttribute(pab_kernel, cudaFuncAttributeMaxDynamicSharedMemorySize, EDGE_SMEM);

    int edge_blocks = (N_EDGES + 127) / 128;
    int nblk128 = (N_NODES + 127) / 128;

    zero_mi_kernel<<<(N_NODES * D / 4 + 255) / 256, 256>>>();
    prep_bimg_kernel<<<(64 * 16 * 32 + 255) / 256, 256>>>(We1, We2, Wc1, Wn1, Wn2, Wv1);
    pab_kernel<<<nblk128, 256, EDGE_SMEM>>>(h, be1, coord, vel, bv1, Wv2, bv2, coord_out);
    edge_kernel<<<edge_blocks, 256, EDGE_SMEM>>>(coord, ei,
                                                 be2, bc1, Wc2, bc2, We1, coord_out);
    node_post_kernel<<<nblk128, 256, EDGE_SMEM>>>(h, bn1, bn2, h_out);
}

// round 13
// speedup vs baseline: 5.2832x; 1.0037x over previous
#include <cuda_runtime.h>
#include <cuda_bf16.h>
#include <cstdint>
#include <cstring>

#define N_NODES 50000
#define N_EDGES 500000
#define D 128

#define PITCHA 136   // HMMA activation plane pitch (bf16 elements)
#define PLANE  (128 * PITCHA)

// ---------------- scratch (static device globals: allowed) ----------------
__device__ float g_mi[N_NODES * D];
__device__ float g_pa[N_NODES * D];   // h @ We1[0:128)   + be1
__device__ float g_pb[N_NODES * D];   // h @ We1[128:256)
// fragment-ordered weight image: 64 ktile-slots x 16 ntiles x 32 lanes x uint4
// 0-7 We1[0:128), 8-15 We1[128:256), 16-23 We2, 24-31 Wc1,
// 32-39 Wn1[0:128), 40-47 Wn1[128:256), 48-55 Wn2, 56-63 Wv1
__device__ uint4 g_bimg[64 * 16 * 32];

__device__ __forceinline__ float silu(float x) { return x / (1.0f + __expf(-x)); }

__device__ __forceinline__ uint32_t bf2_as_u32(__nv_bfloat162 v) {
    uint32_t u; memcpy(&u, &v, 4); return u;
}
__device__ __forceinline__ uint32_t smem_u32(const void* p) {
    uint32_t a;
    asm("{ .reg .u64 t; cvta.to.shared.u64 t, %1; cvt.u32.u64 %0, t; }" : "=r"(a) : "l"(p));
    return a;
}

__device__ __forceinline__ void mma_bf16(
    float* c, uint32_t a0, uint32_t a1, uint32_t a2, uint32_t a3,
    uint32_t b0, uint32_t b1)
{
    asm volatile(
        "mma.sync.aligned.m16n8k16.row.col.f32.bf16.bf16.f32 "
        "{%0,%1,%2,%3}, {%4,%5,%6,%7}, {%8,%9}, {%0,%1,%2,%3};"
        : "+f"(c[0]), "+f"(c[1]), "+f"(c[2]), "+f"(c[3])
        : "r"(a0), "r"(a1), "r"(a2), "r"(a3), "r"(b0), "r"(b1));
}

__device__ __forceinline__ void ldsm_x4(
    uint32_t& r0, uint32_t& r1, uint32_t& r2, uint32_t& r3, uint32_t addr)
{
    asm volatile("ldmatrix.sync.aligned.m8n8.x4.shared.b16 {%0,%1,%2,%3}, [%4];"
                 : "=r"(r0), "=r"(r1), "=r"(r2), "=r"(r3) : "r"(addr));
}

__device__ __forceinline__ void split_pair(
    float x, float y, __nv_bfloat162& hi, __nv_bfloat162& lo)
{
    hi = __floats2bfloat162_rn(x, y);
    lo = __floats2bfloat162_rn(x - __low2float(hi), y - __high2float(hi));
}

// packed f32 pair reduction (sm_90+ baseline): 8B-aligned dst required
__device__ __forceinline__ void red_add_v2(float* p, float a, float b) {
    asm volatile("red.global.add.v2.f32 [%0], {%1, %2};"
                 :: "l"(p), "f"(a), "f"(b) : "memory");
}

// ---------------------------------------------------------------------------
__global__ void zero_mi_kernel() {
    int i = blockIdx.x * blockDim.x + threadIdx.x;
    if (i < N_NODES * D / 4)
        reinterpret_cast<float4*>(g_mi)[i] = make_float4(0.f, 0.f, 0.f, 0.f);
}

// ---------------------------------------------------------------------------
__global__ void prep_bimg_kernel(
    const float* __restrict__ We1, const float* __restrict__ We2,
    const float* __restrict__ Wc1, const float* __restrict__ Wn1,
    const float* __restrict__ Wn2, const float* __restrict__ Wv1)
{
    int idx = blockIdx.x * 256 + threadIdx.x;
    if (idx >= 64 * 16 * 32) return;
    int lane = idx & 31;
    int nt = (idx >> 5) & 15;
    int s = idx >> 9;
    int col = nt * 8 + (lane >> 2);
    int kloc = 2 * (lane & 3);
    const float* W; int kr;
    if (s < 8)       { W = We1; kr = s * 16 + kloc; }
    else if (s < 16) { W = We1; kr = 128 + (s - 8) * 16 + kloc; }
    else if (s < 24) { W = We2; kr = (s - 16) * 16 + kloc; }
    else if (s < 32) { W = Wc1; kr = (s - 24) * 16 + kloc; }
    else if (s < 40) { W = Wn1; kr = (s - 32) * 16 + kloc; }
    else if (s < 48) { W = Wn1; kr = 128 + (s - 40) * 16 + kloc; }
    else if (s < 56) { W = Wn2; kr = (s - 48) * 16 + kloc; }
    else             { W = Wv1; kr = (s - 56) * 16 + kloc; }
    float f00 = W[kr * D + col];
    float f01 = W[(kr + 1) * D + col];
    float f10 = W[(kr + 8) * D + col];
    float f11 = W[(kr + 9) * D + col];
    __nv_bfloat162 h0, l0, h1, l1;
    split_pair(f00, f01, h0, l0);
    split_pair(f10, f11, h1, l1);
    uint4 v;
    v.x = bf2_as_u32(h0); v.y = bf2_as_u32(h1);
    v.z = bf2_as_u32(l0); v.w = bf2_as_u32(l1);
    g_bimg[idx] = v;
}

// ---------------------------------------------------------------------------
// software-pipelined 128x128x128 warp-tile GEMM step (3-pass hi/lo bf16)
__device__ __forceinline__ void gemm_tile(
    float (&c)[4][4][4], uint32_t aHi_addr, int base,
    int cg, int rg, int lane)
{
    int lrow = lane & 15;
    int lcol = (lane >> 4) * 8;
    const uint4* bp = g_bimg + (base * 16 + cg * 4) * 32 + lane;
    uint4 b[4], bn[4];
    #pragma unroll
    for (int nt = 0; nt < 4; nt++) b[nt] = __ldg(bp + nt * 32);
    uint32_t abase = aHi_addr + (uint32_t)(((rg * 64 + lrow) * PITCHA + lcol) * 2);
    uint32_t ah[2][4], al[2][4];
    ldsm_x4(ah[0][0], ah[0][1], ah[0][2], ah[0][3], abase);
    ldsm_x4(al[0][0], al[0][1], al[0][2], al[0][3], abase + PLANE * 2);
    #pragma unroll
    for (int kt = 0; kt < 8; kt++) {
        if (kt < 7) {
            #pragma unroll
            for (int nt = 0; nt < 4; nt++) bn[nt] = __ldg(bp + 16 * 32 + nt * 32);
        }
        #pragma unroll
        for (int mt = 0; mt < 4; mt++) {
            int cur = mt & 1, nxt = 1 - cur;
            if (mt < 3) {
                uint32_t addr = abase + (uint32_t)((((mt + 1) * 16) * PITCHA + kt * 16) * 2);
                ldsm_x4(ah[nxt][0], ah[nxt][1], ah[nxt][2], ah[nxt][3], addr);
                ldsm_x4(al[nxt][0], al[nxt][1], al[nxt][2], al[nxt][3], addr + PLANE * 2);
            } else if (kt < 7) {
                uint32_t addr = abase + (uint32_t)(((kt + 1) * 16) * 2);
                ldsm_x4(ah[nxt][0], ah[nxt][1], ah[nxt][2], ah[nxt][3], addr);
                ldsm_x4(al[nxt][0], al[nxt][1], al[nxt][2], al[nxt][3], addr + PLANE * 2);
            }
            #pragma unroll
            for (int nt = 0; nt < 4; nt++) {
                mma_bf16(c[mt][nt], ah[cur][0], ah[cur][1], ah[cur][2], ah[cur][3], b[nt].x, b[nt].y);
                mma_bf16(c[mt][nt], ah[cur][0], ah[cur][1], ah[cur][2], ah[cur][3], b[nt].z, b[nt].w);
                mma_bf16(c[mt][nt], al[cur][0], al[cur][1], al[cur][2], al[cur][3], b[nt].x, b[nt].y);
            }
        }
        #pragma unroll
        for (int nt = 0; nt < 4; nt++) b[nt] = bn[nt];
        bp += 16 * 32;
    }
}

#define EDGE_SMEM 75776

// ---------------------------------------------------------------------------
// pab_kernel (verified R11): P_A, P_B, vel weights + coord base
__global__ __launch_bounds__(256, 2) void pab_kernel(
    const float* __restrict__ h, const float* __restrict__ be1,
    const float* __restrict__ coord, const float* __restrict__ vel,
    const float* __restrict__ bv1, const float* __restrict__ Wv2,
    const float* __restrict__ bv2,
    float* __restrict__ coord_out)
{
    extern __shared__ __align__(16) char smem[];
    __nv_bfloat16* aHi = (__nv_bfloat16*)smem;
    __nv_bfloat16* aLo = aHi + PLANE;
    float* s_be1 = (float*)(smem + 69632);
    float* s_bv1 = s_be1 + 128;
    float* s_wv2 = s_bv1 + 128;
    float* s_wp  = (float*)smem;

    int t = threadIdx.x;
    int lane = t & 31, wid = t >> 5;
    int cg = wid & 3, rg = wid >> 2;
    int n0 = blockIdx.x * 128;
    uint32_t aHi_addr = smem_u32(aHi);

    if (t < 128) { s_be1[t] = be1[t]; s_bv1[t] = bv1[t]; s_wv2[t] = Wv2[t]; }

    {
        int r = t >> 1;
        int node = n0 + r; if (node >= N_NODES) node = N_NODES - 1;
        int ch = (t & 1) * 64;
        const float* src = h + node * D + ch;
        __nv_bfloat16* ph = aHi + r * PITCHA + ch;
        __nv_bfloat16* pl = aLo + r * PITCHA + ch;
        #pragma unroll
        for (int j = 0; j < 16; j++) {
            float4 v = *(const float4*)(src + 4 * j);
            __nv_bfloat162 h2a, l2a, h2b, l2b;
            split_pair(v.x, v.y, h2a, l2a);
            split_pair(v.z, v.w, h2b, l2b);
            *(__nv_bfloat162*)(ph + 4 * j)     = h2a;
            *(__nv_bfloat162*)(ph + 4 * j + 2) = h2b;
            *(__nv_bfloat162*)(pl + 4 * j)     = l2a;
            *(__nv_bfloat162*)(pl + 4 * j + 2) = l2b;
        }
    }
    __syncthreads();

    float c[4][4][4];
    #pragma unroll
    for (int mt = 0; mt < 4; mt++)
        #pragma unroll
        for (int nt = 0; nt < 4; nt++)
            #pragma unroll
            for (int j = 0; j < 4; j++) c[mt][nt][j] = 0.f;

    int q = lane >> 2;
    int kq = 2 * (lane & 3);

    gemm_tile(c, aHi_addr, 0, cg, rg, lane);
    #pragma unroll
    for (int mt = 0; mt < 4; mt++) {
        int row0 = rg * 64 + mt * 16 + q;
        int row1 = row0 + 8;
        bool v0 = (n0 + row0) < N_NODES, v1 = (n0 + row1) < N_NODES;
        #pragma unroll
        for (int nt = 0; nt < 4; nt++) {
            int col = cg * 32 + nt * 8 + kq;
            float b0 = s_be1[col], b1 = s_be1[col + 1];
            if (v0) *(float2*)&g_pa[(n0 + row0) * D + col] =
                make_float2(c[mt][nt][0] + b0, c[mt][nt][1] + b1);
            if (v1) *(float2*)&g_pa[(n0 + row1) * D + col] =
                make_float2(c[mt][nt][2] + b0, c[mt][nt][3] + b1);
            c[mt][nt][0] = c[mt][nt][1] = c[mt][nt][2] = c[mt][nt][3] = 0.f;
        }
    }
    gemm_tile(c, aHi_addr, 8, cg, rg, lane);
    #pragma unroll
    for (int mt = 0; mt < 4; mt++) {
        int row0 = rg * 64 + mt * 16 + q;
        int row1 = row0 + 8;
        bool v0 = (n0 + row0) < N_NODES, v1 = (n0 + row1) < N_NODES;
        #pragma unroll
        for (int nt = 0; nt < 4; nt++) {
            int col = cg * 32 + nt * 8 + kq;
            if (v0) *(float2*)&g_pb[(n0 + row0) * D + col] =
                make_float2(c[mt][nt][0], c[mt][nt][1]);
            if (v1) *(float2*)&g_pb[(n0 + row1) * D + col] =
                make_float2(c[mt][nt][2], c[mt][nt][3]);
            c[mt][nt][0] = c[mt][nt][1] = c[mt][nt][2] = c[mt][nt][3] = 0.f;
        }
    }
    gemm_tile(c, aHi_addr, 56, cg, rg, lane);
    __syncthreads();
    #pragma unroll
    for (int mt = 0; mt < 4; mt++) {
        float p0 = 0.f, p1 = 0.f;
        #pragma unroll
        for (int nt = 0; nt < 4; nt++) {
            int col = cg * 32 + nt * 8 + kq;
            float b0 = s_bv1[col], b1 = s_bv1[col + 1];
            float w0 = s_wv2[col], w1 = s_wv2[col + 1];
            p0 = fmaf(silu(c[mt][nt][0] + b0), w0, p0);
            p0 = fmaf(silu(c[mt][nt][1] + b1), w1, p0);
            p1 = fmaf(silu(c[mt][nt][2] + b0), w0, p1);
            p1 = fmaf(silu(c[mt][nt][3] + b1), w1, p1);
        }
        p0 += __shfl_xor_sync(0xffffffffu, p0, 1);
        p0 += __shfl_xor_sync(0xffffffffu, p0, 2);
        p1 += __shfl_xor_sync(0xffffffffu, p1, 1);
        p1 += __shfl_xor_sync(0xffffffffu, p1, 2);
        if ((lane & 3) == 0) {
            int row0 = rg * 64 + mt * 16 + q;
            s_wp[row0 * 4 + cg]       = p0;
            s_wp[(row0 + 8) * 4 + cg] = p1;
        }
    }
    __syncthreads();
    if (t < 128 && (n0 + t) < N_NODES) {
        float vw = s_wp[t * 4] + s_wp[t * 4 + 1] + s_wp[t * 4 + 2] + s_wp[t * 4 + 3] + bv2[0];
        int n = n0 + t;
        #pragma unroll
        for (int i = 0; i < 3; i++)
            coord_out[n * 3 + i] = coord[n * 3 + i] + vel[n * 3 + i] * vw;
    }
}

// ---------------------------------------------------------------------------
// edge kernel: fully per-thread gather (no prologue sync), v2 reductions
__global__ __launch_bounds__(256, 2) void edge_kernel(
    const float* __restrict__ coord,
    const int* __restrict__ ei,
    const float* __restrict__ be2,
    const float* __restrict__ bc1,
    const float* __restrict__ Wc2, const float* __restrict__ bc2,
    const float* __restrict__ We1,
    float* __restrict__ coord_out)
{
    extern __shared__ __align__(16) char smem[];
    __nv_bfloat16* aHi = (__nv_bfloat16*)smem;              // 34816 B
    __nv_bfloat16* aLo = aHi + PLANE;                       // 34816 B
    float* s_be2  = (float*)(smem + 69632);
    float* s_bc1  = s_be2 + 128;
    float* s_wc2  = s_bc1 + 128;
    int*   s_r    = (int*)(smem + 72192);
    float* s_diff = (float*)(smem + 73728);
    float* s_wp   = (float*)smem;   // L3 partials alias plane after last GEMM

    int t = threadIdx.x;
    int lane = t & 31, wid = t >> 5;
    int cg = wid & 3, rg = wid >> 2;
    int e0 = blockIdx.x * 128;

    uint32_t aHi_addr = smem_u32(aHi);

    // biases (overlap with gather, consumed only after first sync)
    if (t < 128) { s_be2[t] = be2[t]; s_bc1[t] = bc1[t]; s_wc2[t] = Wc2[t]; }

    // ---- per-thread gather + act1 (no sync needed before this) ----
    {
        int row = t >> 1;
        int ch = (t & 1) * 64;
        int e = e0 + row;
        int cl = (e < N_EDGES) ? e : (N_EDGES - 1);
        int r = ei[cl], cc = ei[N_EDGES + cl];

        float rad;
        if ((t & 1) == 0) {
            float dx = coord[r * 3 + 0] - coord[cc * 3 + 0];
            float dy = coord[r * 3 + 1] - coord[cc * 3 + 1];
            float dz = coord[r * 3 + 2] - coord[cc * 3 + 2];
            rad = dx * dx + dy * dy + dz * dz;
            float inv = 1.0f / (sqrtf(rad) + 1e-8f);
            s_r[row] = r;
            s_diff[row * 3 + 0] = dx * inv;
            s_diff[row * 3 + 1] = dy * inv;
            s_diff[row * 3 + 2] = dz * inv;
        }
        rad = __shfl_sync(0xffffffffu, rad, lane & ~1);

        const float* pa = g_pa + (size_t)r * D + ch;
        const float* pb = g_pb + (size_t)cc * D + ch;
        const float* w256 = We1 + 256 * D + ch;          // warp-uniform: L1 broadcast
        __nv_bfloat16* ph = aHi + row * PITCHA + ch;
        __nv_bfloat16* pl = aLo + row * PITCHA + ch;
        #pragma unroll
        for (int j = 0; j < 16; j++) {
            float4 a = *(const float4*)(pa + 4 * j);
            float4 b = *(const float4*)(pb + 4 * j);
            float4 w = *(const float4*)(w256 + 4 * j);
            float v0 = silu(a.x + b.x + rad * w.x);
            float v1 = silu(a.y + b.y + rad * w.y);
            float v2 = silu(a.z + b.z + rad * w.z);
            float v3 = silu(a.w + b.w + rad * w.w);
            __nv_bfloat162 h2a, l2a, h2b, l2b;
            split_pair(v0, v1, h2a, l2a);
            split_pair(v2, v3, h2b, l2b);
            *(__nv_bfloat162*)(ph + 4 * j)     = h2a;
            *(__nv_bfloat162*)(ph + 4 * j + 2) = h2b;
            *(__nv_bfloat162*)(pl + 4 * j)     = l2a;
            *(__nv_bfloat162*)(pl + 4 * j + 2) = l2b;
        }
    }
    __syncthreads();

    float c[4][4][4];
    #pragma unroll
    for (int mt = 0; mt < 4; mt++)
        #pragma unroll
        for (int nt = 0; nt < 4; nt++)
            #pragma unroll
            for (int j = 0; j < 4; j++) c[mt][nt][j] = 0.f;

    int q = lane >> 2;
    int kq = 2 * (lane & 3);

    // ============ LAYER 2: act1 @ We2 -> m_ij ============
    gemm_tile(c, aHi_addr, 16, cg, rg, lane);
    __syncthreads();
    #pragma unroll
    for (int mt = 0; mt < 4; mt++) {
        int row0 = rg * 64 + mt * 16 + q;
        int row1 = row0 + 8;
        bool v0 = (e0 + row0) < N_EDGES, v1 = (e0 + row1) < N_EDGES;
        int n0 = s_r[row0], n1 = s_r[row1];
        #pragma unroll
        for (int nt = 0; nt < 4; nt++) {
            int col = cg * 32 + nt * 8 + kq;
            float b0 = s_be2[col], b1 = s_be2[col + 1];
            float v00 = silu(c[mt][nt][0] + b0);
            float v01 = silu(c[mt][nt][1] + b1);
            float v10 = silu(c[mt][nt][2] + b0);
            float v11 = silu(c[mt][nt][3] + b1);
            __nv_bfloat162 h2, l2;
            split_pair(v00, v01, h2, l2);
            *(__nv_bfloat162*)(aHi + row0 * PITCHA + col) = h2;
            *(__nv_bfloat162*)(aLo + row0 * PITCHA + col) = l2;
            split_pair(v10, v11, h2, l2);
            *(__nv_bfloat162*)(aHi + row1 * PITCHA + col) = h2;
            *(__nv_bfloat162*)(aLo + row1 * PITCHA + col) = l2;
            if (v0) red_add_v2(&g_mi[n0 * D + col], v00, v01);
            if (v1) red_add_v2(&g_mi[n1 * D + col], v10, v11);
            c[mt][nt][0] = c[mt][nt][1] = c[mt][nt][2] = c[mt][nt][3] = 0.f;
        }
    }
    __syncthreads();

    // ============ LAYER 3: m_ij @ Wc1 -> per-edge weight ============
    gemm_tile(c, aHi_addr, 24, cg, rg, lane);
    __syncthreads();
    #pragma unroll
    for (int mt = 0; mt < 4; mt++) {
        float p0 = 0.f, p1 = 0.f;
        #pragma unroll
        for (int nt = 0; nt < 4; nt++) {
            int col = cg * 32 + nt * 8 + kq;
            float b0 = s_bc1[col], b1 = s_bc1[col + 1];
            float w0 = s_wc2[col], w1 = s_wc2[col + 1];
            p0 = fmaf(silu(c[mt][nt][0] + b0), w0, p0);
            p0 = fmaf(silu(c[mt][nt][1] + b1), w1, p0);
            p1 = fmaf(silu(c[mt][nt][2] + b0), w0, p1);
            p1 = fmaf(silu(c[mt][nt][3] + b1), w1, p1);
        }
        p0 += __shfl_xor_sync(0xffffffffu, p0, 1);
        p0 += __shfl_xor_sync(0xffffffffu, p0, 2);
        p1 += __shfl_xor_sync(0xffffffffu, p1, 1);
        p1 += __shfl_xor_sync(0xffffffffu, p1, 2);
        if ((lane & 3) == 0) {
            int row0 = rg * 64 + mt * 16 + q;
            s_wp[row0 * 4 + cg]       = p0;
            s_wp[(row0 + 8) * 4 + cg] = p1;
        }
    }
    __syncthreads();

    if (t < 128 && (e0 + t) < N_EDGES) {
        float w = s_wp[t * 4] + s_wp[t * 4 + 1] + s_wp[t * 4 + 2] + s_wp[t * 4 + 3] + bc2[0];
        int rr = s_r[t];
        atomicAdd(&coord_out[rr * 3 + 0], s_diff[t * 3 + 0] * w);
        atomicAdd(&coord_out[rr * 3 + 1], s_diff[t * 3 + 1] * w);
        atomicAdd(&coord_out[rr * 3 + 2], s_diff[t * 3 + 2] * w);
    }
}

// ---------------------------------------------------------------------------
// node_post: HMMA. [h,m_i]@Wn1 -> silu -> @Wn2  (verified R9-R11)
__global__ __launch_bounds__(256, 2) void node_post_kernel(
    const float* __restrict__ h,
    const float* __restrict__ bn1, const float* __restrict__ bn2,
    float* __restrict__ h_out)
{
    extern __shared__ __align__(16) char smem[];
    __nv_bfloat16* aHi = (__nv_bfloat16*)smem;
    __nv_bfloat16* aLo = aHi + PLANE;
    float* s_bn1 = (float*)(smem + 69632);
    float* s_bn2 = s_bn1 + 128;

    int t = threadIdx.x;
    int lane = t & 31, wid = t >> 5;
    int cg = wid & 3, rg = wid >> 2;
    int n0 = blockIdx.x * 128;
    uint32_t aHi_addr = smem_u32(aHi);

    if (t < 128) { s_bn1[t] = bn1[t]; s_bn2[t] = bn2[t]; }

    float c[4][4][4];
    #pragma unroll
    for (int mt = 0; mt < 4; mt++)
        #pragma unroll
        for (int nt = 0; nt < 4; nt++)
            #pragma unroll
            for (int j = 0; j < 4; j++) c[mt][nt][j] = 0.f;

    int q = lane >> 2;
    int kq = 2 * (lane & 3);

    auto stage_rows = [&](const float* base) {
        int r = t >> 1;
        int node = n0 + r; if (node >= N_NODES) node = N_NODES - 1;
        int ch = (t & 1) * 64;
        const float* src = base + node * D + ch;
        __nv_bfloat16* ph = aHi + r * PITCHA + ch;
        __nv_bfloat16* pl = aLo + r * PITCHA + ch;
        #pragma unroll
        for (int j = 0; j < 16; j++) {
            float4 v = *(const float4*)(src + 4 * j);
            __nv_bfloat162 h2a, l2a, h2b, l2b;
            split_pair(v.x, v.y, h2a, l2a);
            split_pair(v.z, v.w, h2b, l2b);
            *(__nv_bfloat162*)(ph + 4 * j)     = h2a;
            *(__nv_bfloat162*)(ph + 4 * j + 2) = h2b;
            *(__nv_bfloat162*)(pl + 4 * j)     = l2a;
            *(__nv_bfloat162*)(pl + 4 * j + 2) = l2b;
        }
    };

    stage_rows(h);
    __syncthreads();
    gemm_tile(c, aHi_addr, 32, cg, rg, lane);
    __syncthreads();
    stage_rows(g_mi);
    __syncthreads();
    gemm_tile(c, aHi_addr, 40, cg, rg, lane);
    __syncthreads();

    #pragma unroll
    for (int mt = 0; mt < 4; mt++) {
        int row0 = rg * 64 + mt * 16 + q;
        int row1 = row0 + 8;
        #pragma unroll
        for (int nt = 0; nt < 4; nt++) {
            int col = cg * 32 + nt * 8 + kq;
            float b0 = s_bn1[col], b1 = s_bn1[col + 1];
            float v00 = silu(c[mt][nt][0] + b0);
            float v01 = silu(c[mt][nt][1] + b1);
            float v10 = silu(c[mt][nt][2] + b0);
            float v11 = silu(c[mt][nt][3] + b1);
            __nv_bfloat162 h2, l2;
            split_pair(v00, v01, h2, l2);
            *(__nv_bfloat162*)(aHi + row0 * PITCHA + col) = h2;
            *(__nv_bfloat162*)(aLo + row0 * PITCHA + col) = l2;
            split_pair(v10, v11, h2, l2);
            *(__nv_bfloat162*)(aHi + row1 * PITCHA + col) = h2;
            *(__nv_bfloat162*)(aLo + row1 * PITCHA + col) = l2;
            c[mt][nt][0] = c[mt][nt][1] = c[mt][nt][2] = c[mt][nt][3] = 0.f;
        }
    }
    __syncthreads();

    gemm_tile(c, aHi_addr, 48, cg, rg, lane);

    #pragma unroll
    for (int mt = 0; mt < 4; mt++) {
        int row0 = rg * 64 + mt * 16 + q;
        int row1 = row0 + 8;
        bool v0 = (n0 + row0) < N_NODES, v1 = (n0 + row1) < N_NODES;
        #pragma unroll
        for (int nt = 0; nt < 4; nt++) {
            int col = cg * 32 + nt * 8 + kq;
            float b0 = s_bn2[col], b1 = s_bn2[col + 1];
            if (v0) {
                float2 o = make_float2(c[mt][nt][0] + b0, c[mt][nt][1] + b1);
                *(float2*)&h_out[(n0 + row0) * D + col] = o;
            }
            if (v1) {
                float2 o = make_float2(c[mt][nt][2] + b0, c[mt][nt][3] + b1);
                *(float2*)&h_out[(n0 + row1) * D + col] = o;
            }
        }
    }
}

// ---------------------------------------------------------------------------
extern "C" void kernel_launch(void* const* d_in, const int* in_sizes, int n_in,
                              void* d_out, int out_size)
{
    const float* h     = (const float*)d_in[0];
    const float* coord = (const float*)d_in[1];
    const float* vel   = (const float*)d_in[2];
    const int*   ei    = (const int*)  d_in[3];
    const float* We1 = (const float*)d_in[4];  const float* be1 = (const float*)d_in[5];
    const float* We2 = (const float*)d_in[6];  const float* be2 = (const float*)d_in[7];
    const float* Wc1 = (const float*)d_in[8];  const float* bc1 = (const float*)d_in[9];
    const float* Wc2 = (const float*)d_in[10]; const float* bc2 = (const float*)d_in[11];
    const float* Wv1 = (const float*)d_in[12]; const float* bv1 = (const float*)d_in[13];
    const float* Wv2 = (const float*)d_in[14]; const float* bv2 = (const float*)d_in[15];
    const float* Wn1 = (const float*)d_in[16]; const float* bn1 = (const float*)d_in[17];
    const float* Wn2 = (const float*)d_in[18]; const float* bn2 = (const float*)d_in[19];

    float* h_out     = (float*)d_out;                  // [N, 128]
    float* coord_out = (float*)d_out + N_NODES * D;    // [N, 3]

    cudaFuncSetAttribute(edge_kernel, cudaFuncAttributeMaxDynamicSharedMemorySize, EDGE_SMEM);
    cudaFuncSetAttribute(node_post_kernel, cudaFuncAttributeMaxDynamicSharedMemorySize, EDGE_SMEM);
    cudaFuncSetAttribute(pab_kernel, cudaFuncAttributeMaxDynamicSharedMemorySize, EDGE_SMEM);

    int edge_blocks = (N_EDGES + 127) / 128;
    int nblk128 = (N_NODES + 127) / 128;

    zero_mi_kernel<<<(N_NODES * D / 4 + 255) / 256, 256>>>();
    prep_bimg_kernel<<<(64 * 16 * 32 + 255) / 256, 256>>>(We1, We2, Wc1, Wn1, Wn2, Wv1);
    pab_kernel<<<nblk128, 256, EDGE_SMEM>>>(h, be1, coord, vel, bv1, Wv2, bv2, coord_out);
    edge_kernel<<<edge_blocks, 256, EDGE_SMEM>>>(coord, ei,
                                                 be2, bc1, Wc2, bc2, We1, coord_out);
    node_post_kernel<<<nblk128, 256, EDGE_SMEM>>>(h, bn1, bn2, h_out);
}

// round 14
// speedup vs baseline: 5.6072x; 1.0613x over previous
#include <cuda_runtime.h>
#include <cuda_bf16.h>
#include <cstdint>
#include <cstring>

#define N_NODES 50000
#define N_EDGES 500000
#define D 128

#define PITCHA 136   // HMMA activation plane pitch (bf16 elements)
#define PLANE   (128 * PITCHA)
#define PLANE64 (64 * PITCHA)

// ---------------- scratch (static device globals: allowed) ----------------
__device__ float g_mi[N_NODES * D];
__device__ float g_pa[N_NODES * D];   // h @ We1[0:128)   + be1
__device__ float g_pb[N_NODES * D];   // h @ We1[128:256)
// fragment-ordered weight image: 64 ktile-slots x 16 ntiles x 32 lanes x uint4
// 0-7 We1[0:128), 8-15 We1[128:256), 16-23 We2, 24-31 Wc1,
// 32-39 Wn1[0:128), 40-47 Wn1[128:256), 48-55 Wn2, 56-63 Wv1
__device__ uint4 g_bimg[64 * 16 * 32];

__device__ __forceinline__ float silu(float x) { return x / (1.0f + __expf(-x)); }

__device__ __forceinline__ uint32_t bf2_as_u32(__nv_bfloat162 v) {
    uint32_t u; memcpy(&u, &v, 4); return u;
}
__device__ __forceinline__ uint32_t smem_u32(const void* p) {
    uint32_t a;
    asm("{ .reg .u64 t; cvta.to.shared.u64 t, %1; cvt.u32.u64 %0, t; }" : "=r"(a) : "l"(p));
    return a;
}

__device__ __forceinline__ void mma_bf16(
    float* c, uint32_t a0, uint32_t a1, uint32_t a2, uint32_t a3,
    uint32_t b0, uint32_t b1)
{
    asm volatile(
        "mma.sync.aligned.m16n8k16.row.col.f32.bf16.bf16.f32 "
        "{%0,%1,%2,%3}, {%4,%5,%6,%7}, {%8,%9}, {%0,%1,%2,%3};"
        : "+f"(c[0]), "+f"(c[1]), "+f"(c[2]), "+f"(c[3])
        : "r"(a0), "r"(a1), "r"(a2), "r"(a3), "r"(b0), "r"(b1));
}

__device__ __forceinline__ void ldsm_x4(
    uint32_t& r0, uint32_t& r1, uint32_t& r2, uint32_t& r3, uint32_t addr)
{
    asm volatile("ldmatrix.sync.aligned.m8n8.x4.shared.b16 {%0,%1,%2,%3}, [%4];"
                 : "=r"(r0), "=r"(r1), "=r"(r2), "=r"(r3) : "r"(addr));
}

__device__ __forceinline__ void split_pair(
    float x, float y, __nv_bfloat162& hi, __nv_bfloat162& lo)
{
    hi = __floats2bfloat162_rn(x, y);
    lo = __floats2bfloat162_rn(x - __low2float(hi), y - __high2float(hi));
}

// packed f32 pair reduction (sm_90+ baseline): 8B-aligned dst required
__device__ __forceinline__ void red_add_v2(float* p, float a, float b) {
    asm volatile("red.global.add.v2.f32 [%0], {%1, %2};"
                 :: "l"(p), "f"(a), "f"(b) : "memory");
}

// ---------------------------------------------------------------------------
__global__ void zero_mi_kernel() {
    int i = blockIdx.x * blockDim.x + threadIdx.x;
    if (i < N_NODES * D / 4)
        reinterpret_cast<float4*>(g_mi)[i] = make_float4(0.f, 0.f, 0.f, 0.f);
}

// ---------------------------------------------------------------------------
__global__ void prep_bimg_kernel(
    const float* __restrict__ We1, const float* __restrict__ We2,
    const float* __restrict__ Wc1, const float* __restrict__ Wn1,
    const float* __restrict__ Wn2, const float* __restrict__ Wv1)
{
    int idx = blockIdx.x * 256 + threadIdx.x;
    if (idx >= 64 * 16 * 32) return;
    int lane = idx & 31;
    int nt = (idx >> 5) & 15;
    int s = idx >> 9;
    int col = nt * 8 + (lane >> 2);
    int kloc = 2 * (lane & 3);
    const float* W; int kr;
    if (s < 8)       { W = We1; kr = s * 16 + kloc; }
    else if (s < 16) { W = We1; kr = 128 + (s - 8) * 16 + kloc; }
    else if (s < 24) { W = We2; kr = (s - 16) * 16 + kloc; }
    else if (s < 32) { W = Wc1; kr = (s - 24) * 16 + kloc; }
    else if (s < 40) { W = Wn1; kr = (s - 32) * 16 + kloc; }
    else if (s < 48) { W = Wn1; kr = 128 + (s - 40) * 16 + kloc; }
    else if (s < 56) { W = Wn2; kr = (s - 48) * 16 + kloc; }
    else             { W = Wv1; kr = (s - 56) * 16 + kloc; }
    float f00 = W[kr * D + col];
    float f01 = W[(kr + 1) * D + col];
    float f10 = W[(kr + 8) * D + col];
    float f11 = W[(kr + 9) * D + col];
    __nv_bfloat162 h0, l0, h1, l1;
    split_pair(f00, f01, h0, l0);
    split_pair(f10, f11, h1, l1);
    uint4 v;
    v.x = bf2_as_u32(h0); v.y = bf2_as_u32(h1);
    v.z = bf2_as_u32(l0); v.w = bf2_as_u32(l1);
    g_bimg[idx] = v;
}

// ---------------------------------------------------------------------------
// 128-row software-pipelined warp-tile GEMM (3-pass hi/lo bf16) — pab/node_post
__device__ __forceinline__ void gemm_tile(
    float (&c)[4][4][4], uint32_t aHi_addr, int base,
    int cg, int rg, int lane)
{
    int lrow = lane & 15;
    int lcol = (lane >> 4) * 8;
    const uint4* bp = g_bimg + (base * 16 + cg * 4) * 32 + lane;
    uint4 b[4], bn[4];
    #pragma unroll
    for (int nt = 0; nt < 4; nt++) b[nt] = __ldg(bp + nt * 32);
    uint32_t abase = aHi_addr + (uint32_t)(((rg * 64 + lrow) * PITCHA + lcol) * 2);
    uint32_t ah[2][4], al[2][4];
    ldsm_x4(ah[0][0], ah[0][1], ah[0][2], ah[0][3], abase);
    ldsm_x4(al[0][0], al[0][1], al[0][2], al[0][3], abase + PLANE * 2);
    #pragma unroll
    for (int kt = 0; kt < 8; kt++) {
        if (kt < 7) {
            #pragma unroll
            for (int nt = 0; nt < 4; nt++) bn[nt] = __ldg(bp + 16 * 32 + nt * 32);
        }
        #pragma unroll
        for (int mt = 0; mt < 4; mt++) {
            int cur = mt & 1, nxt = 1 - cur;
            if (mt < 3) {
                uint32_t addr = abase + (uint32_t)((((mt + 1) * 16) * PITCHA + kt * 16) * 2);
                ldsm_x4(ah[nxt][0], ah[nxt][1], ah[nxt][2], ah[nxt][3], addr);
                ldsm_x4(al[nxt][0], al[nxt][1], al[nxt][2], al[nxt][3], addr + PLANE * 2);
            } else if (kt < 7) {
                uint32_t addr = abase + (uint32_t)(((kt + 1) * 16) * 2);
                ldsm_x4(ah[nxt][0], ah[nxt][1], ah[nxt][2], ah[nxt][3], addr);
                ldsm_x4(al[nxt][0], al[nxt][1], al[nxt][2], al[nxt][3], addr + PLANE * 2);
            }
            #pragma unroll
            for (int nt = 0; nt < 4; nt++) {
                mma_bf16(c[mt][nt], ah[cur][0], ah[cur][1], ah[cur][2], ah[cur][3], b[nt].x, b[nt].y);
                mma_bf16(c[mt][nt], ah[cur][0], ah[cur][1], ah[cur][2], ah[cur][3], b[nt].z, b[nt].w);
                mma_bf16(c[mt][nt], al[cur][0], al[cur][1], al[cur][2], al[cur][3], b[nt].x, b[nt].y);
            }
        }
        #pragma unroll
        for (int nt = 0; nt < 4; nt++) b[nt] = bn[nt];
        bp += 16 * 32;
    }
}

// 64-row warp-tile GEMM (32 accumulators) — edge kernel, occupancy-optimized
__device__ __forceinline__ void gemm_tile64(
    float (&c)[2][4][4], uint32_t aHi_addr, int base,
    int cg, int rg, int lane)
{
    int lrow = lane & 15;
    int lcol = (lane >> 4) * 8;
    const uint4* bp = g_bimg + (base * 16 + cg * 4) * 32 + lane;
    uint32_t abase = aHi_addr + (uint32_t)(((rg * 32 + lrow) * PITCHA + lcol) * 2);
    #pragma unroll
    for (int kt = 0; kt < 8; kt++) {
        uint4 b[4];
        #pragma unroll
        for (int nt = 0; nt < 4; nt++) b[nt] = __ldg(bp + nt * 32);
        #pragma unroll
        for (int mt = 0; mt < 2; mt++) {
            uint32_t addr = abase + (uint32_t)(((mt * 16) * PITCHA + kt * 16) * 2);
            uint32_t ah0, ah1, ah2, ah3, al0, al1, al2, al3;
            ldsm_x4(ah0, ah1, ah2, ah3, addr);
            ldsm_x4(al0, al1, al2, al3, addr + PLANE64 * 2);
            #pragma unroll
            for (int nt = 0; nt < 4; nt++) {
                mma_bf16(c[mt][nt], ah0, ah1, ah2, ah3, b[nt].x, b[nt].y);
                mma_bf16(c[mt][nt], ah0, ah1, ah2, ah3, b[nt].z, b[nt].w);
                mma_bf16(c[mt][nt], al0, al1, al2, al3, b[nt].x, b[nt].y);
            }
        }
        bp += 16 * 32;
    }
}

#define BIG_SMEM  75776   // pab / node_post (128-row planes)
#define EDGE_SMEM 37632   // edge (64-row planes)

// ---------------------------------------------------------------------------
// pab_kernel (verified R11/R12): P_A, P_B, vel weights + coord base
__global__ __launch_bounds__(256, 2) void pab_kernel(
    const float* __restrict__ h, const float* __restrict__ be1,
    const float* __restrict__ coord, const float* __restrict__ vel,
    const float* __restrict__ bv1, const float* __restrict__ Wv2,
    const float* __restrict__ bv2,
    float* __restrict__ coord_out)
{
    extern __shared__ __align__(16) char smem[];
    __nv_bfloat16* aHi = (__nv_bfloat16*)smem;
    __nv_bfloat16* aLo = aHi + PLANE;
    float* s_be1 = (float*)(smem + 69632);
    float* s_bv1 = s_be1 + 128;
    float* s_wv2 = s_bv1 + 128;
    float* s_wp  = (float*)smem;

    int t = threadIdx.x;
    int lane = t & 31, wid = t >> 5;
    int cg = wid & 3, rg = wid >> 2;
    int n0 = blockIdx.x * 128;
    uint32_t aHi_addr = smem_u32(aHi);

    if (t < 128) { s_be1[t] = be1[t]; s_bv1[t] = bv1[t]; s_wv2[t] = Wv2[t]; }

    {
        int r = t >> 1;
        int node = n0 + r; if (node >= N_NODES) node = N_NODES - 1;
        int ch = (t & 1) * 64;
        const float* src = h + node * D + ch;
        __nv_bfloat16* ph = aHi + r * PITCHA + ch;
        __nv_bfloat16* pl = aLo + r * PITCHA + ch;
        #pragma unroll
        for (int j = 0; j < 16; j++) {
            float4 v = *(const float4*)(src + 4 * j);
            __nv_bfloat162 h2a, l2a, h2b, l2b;
            split_pair(v.x, v.y, h2a, l2a);
            split_pair(v.z, v.w, h2b, l2b);
            *(__nv_bfloat162*)(ph + 4 * j)     = h2a;
            *(__nv_bfloat162*)(ph + 4 * j + 2) = h2b;
            *(__nv_bfloat162*)(pl + 4 * j)     = l2a;
            *(__nv_bfloat162*)(pl + 4 * j + 2) = l2b;
        }
    }
    __syncthreads();

    float c[4][4][4];
    #pragma unroll
    for (int mt = 0; mt < 4; mt++)
        #pragma unroll
        for (int nt = 0; nt < 4; nt++)
            #pragma unroll
            for (int j = 0; j < 4; j++) c[mt][nt][j] = 0.f;

    int q = lane >> 2;
    int kq = 2 * (lane & 3);

    gemm_tile(c, aHi_addr, 0, cg, rg, lane);
    #pragma unroll
    for (int mt = 0; mt < 4; mt++) {
        int row0 = rg * 64 + mt * 16 + q;
        int row1 = row0 + 8;
        bool v0 = (n0 + row0) < N_NODES, v1 = (n0 + row1) < N_NODES;
        #pragma unroll
        for (int nt = 0; nt < 4; nt++) {
            int col = cg * 32 + nt * 8 + kq;
            float b0 = s_be1[col], b1 = s_be1[col + 1];
            if (v0) *(float2*)&g_pa[(n0 + row0) * D + col] =
                make_float2(c[mt][nt][0] + b0, c[mt][nt][1] + b1);
            if (v1) *(float2*)&g_pa[(n0 + row1) * D + col] =
                make_float2(c[mt][nt][2] + b0, c[mt][nt][3] + b1);
            c[mt][nt][0] = c[mt][nt][1] = c[mt][nt][2] = c[mt][nt][3] = 0.f;
        }
    }
    gemm_tile(c, aHi_addr, 8, cg, rg, lane);
    #pragma unroll
    for (int mt = 0; mt < 4; mt++) {
        int row0 = rg * 64 + mt * 16 + q;
        int row1 = row0 + 8;
        bool v0 = (n0 + row0) < N_NODES, v1 = (n0 + row1) < N_NODES;
        #pragma unroll
        for (int nt = 0; nt < 4; nt++) {
            int col = cg * 32 + nt * 8 + kq;
            if (v0) *(float2*)&g_pb[(n0 + row0) * D + col] =
                make_float2(c[mt][nt][0], c[mt][nt][1]);
            if (v1) *(float2*)&g_pb[(n0 + row1) * D + col] =
                make_float2(c[mt][nt][2], c[mt][nt][3]);
            c[mt][nt][0] = c[mt][nt][1] = c[mt][nt][2] = c[mt][nt][3] = 0.f;
        }
    }
    gemm_tile(c, aHi_addr, 56, cg, rg, lane);
    __syncthreads();
    #pragma unroll
    for (int mt = 0; mt < 4; mt++) {
        float p0 = 0.f, p1 = 0.f;
        #pragma unroll
        for (int nt = 0; nt < 4; nt++) {
            int col = cg * 32 + nt * 8 + kq;
            float b0 = s_bv1[col], b1 = s_bv1[col + 1];
            float w0 = s_wv2[col], w1 = s_wv2[col + 1];
            p0 = fmaf(silu(c[mt][nt][0] + b0), w0, p0);
            p0 = fmaf(silu(c[mt][nt][1] + b1), w1, p0);
            p1 = fmaf(silu(c[mt][nt][2] + b0), w0, p1);
            p1 = fmaf(silu(c[mt][nt][3] + b1), w1, p1);
        }
        p0 += __shfl_xor_sync(0xffffffffu, p0, 1);
        p0 += __shfl_xor_sync(0xffffffffu, p0, 2);
        p1 += __shfl_xor_sync(0xffffffffu, p1, 1);
        p1 += __shfl_xor_sync(0xffffffffu, p1, 2);
        if ((lane & 3) == 0) {
            int row0 = rg * 64 + mt * 16 + q;
            s_wp[row0 * 4 + cg]       = p0;
            s_wp[(row0 + 8) * 4 + cg] = p1;
        }
    }
    __syncthreads();
    if (t < 128 && (n0 + t) < N_NODES) {
        float vw = s_wp[t * 4] + s_wp[t * 4 + 1] + s_wp[t * 4 + 2] + s_wp[t * 4 + 3] + bv2[0];
        int n = n0 + t;
        #pragma unroll
        for (int i = 0; i < 3; i++)
            coord_out[n * 3 + i] = coord[n * 3 + i] + vel[n * 3 + i] * vw;
    }
}

// ---------------------------------------------------------------------------
// edge kernel: 64 edges/block, 32-acc warp tiles, 3 blocks/SM
__global__ __launch_bounds__(256, 3) void edge_kernel(
    const float* __restrict__ coord,
    const int* __restrict__ ei,
    const float* __restrict__ be2,
    const float* __restrict__ bc1,
    const float* __restrict__ Wc2, const float* __restrict__ bc2,
    const float* __restrict__ We1,
    float* __restrict__ coord_out)
{
    extern __shared__ __align__(16) char smem[];
    __nv_bfloat16* aHi = (__nv_bfloat16*)smem;              // 17408 B
    __nv_bfloat16* aLo = aHi + PLANE64;                     // 17408 B
    float* s_be2  = (float*)(smem + 34816);
    float* s_bc1  = s_be2 + 128;
    float* s_wc2  = s_bc1 + 128;
    int*   s_r    = (int*)(smem + 36352);    // 64 ints
    float* s_diff = (float*)(smem + 36608);  // 64*3 floats
    float* s_wp   = (float*)smem;            // L3 partials alias plane

    int t = threadIdx.x;
    int lane = t & 31, wid = t >> 5;
    int cg = wid & 3, rg = wid >> 2;        // rg in {0,1}
    int e0 = blockIdx.x * 64;

    uint32_t aHi_addr = smem_u32(aHi);

    if (t < 128) { s_be2[t] = be2[t]; s_bc1[t] = bc1[t]; s_wc2[t] = Wc2[t]; }

    // ---- per-thread gather + act1 (256 threads, 64 rows x 4 chunks of 32) ----
    {
        int row = t >> 2;
        int ch = (t & 3) * 32;
        int e = e0 + row;
        int cl = (e < N_EDGES) ? e : (N_EDGES - 1);
        int r = ei[cl], cc = ei[N_EDGES + cl];

        float rad;
        if ((t & 3) == 0) {
            float dx = coord[r * 3 + 0] - coord[cc * 3 + 0];
            float dy = coord[r * 3 + 1] - coord[cc * 3 + 1];
            float dz = coord[r * 3 + 2] - coord[cc * 3 + 2];
            rad = dx * dx + dy * dy + dz * dz;
            float inv = 1.0f / (sqrtf(rad) + 1e-8f);
            s_r[row] = r;
            s_diff[row * 3 + 0] = dx * inv;
            s_diff[row * 3 + 1] = dy * inv;
            s_diff[row * 3 + 2] = dz * inv;
        }
        rad = __shfl_sync(0xffffffffu, rad, lane & ~3);

        const float* pa = g_pa + (size_t)r * D + ch;
        const float* pb = g_pb + (size_t)cc * D + ch;
        const float* w256 = We1 + 256 * D + ch;
        __nv_bfloat16* ph = aHi + row * PITCHA + ch;
        __nv_bfloat16* pl = aLo + row * PITCHA + ch;
        #pragma unroll
        for (int j = 0; j < 8; j++) {
            float4 a = *(const float4*)(pa + 4 * j);
            float4 b = *(const float4*)(pb + 4 * j);
            float4 w = *(const float4*)(w256 + 4 * j);
            float v0 = silu(a.x + b.x + rad * w.x);
            float v1 = silu(a.y + b.y + rad * w.y);
            float v2 = silu(a.z + b.z + rad * w.z);
            float v3 = silu(a.w + b.w + rad * w.w);
            __nv_bfloat162 h2a, l2a, h2b, l2b;
            split_pair(v0, v1, h2a, l2a);
            split_pair(v2, v3, h2b, l2b);
            *(__nv_bfloat162*)(ph + 4 * j)     = h2a;
            *(__nv_bfloat162*)(ph + 4 * j + 2) = h2b;
            *(__nv_bfloat162*)(pl + 4 * j)     = l2a;
            *(__nv_bfloat162*)(pl + 4 * j + 2) = l2b;
        }
    }
    __syncthreads();

    float c[2][4][4];
    #pragma unroll
    for (int mt = 0; mt < 2; mt++)
        #pragma unroll
        for (int nt = 0; nt < 4; nt++)
            #pragma unroll
            for (int j = 0; j < 4; j++) c[mt][nt][j] = 0.f;

    int q = lane >> 2;
    int kq = 2 * (lane & 3);

    // ============ LAYER 2: act1 @ We2 -> m_ij ============
    gemm_tile64(c, aHi_addr, 16, cg, rg, lane);
    __syncthreads();
    #pragma unroll
    for (int mt = 0; mt < 2; mt++) {
        int row0 = rg * 32 + mt * 16 + q;
        int row1 = row0 + 8;
        bool v0 = (e0 + row0) < N_EDGES, v1 = (e0 + row1) < N_EDGES;
        int n0 = s_r[row0], n1 = s_r[row1];
        #pragma unroll
        for (int nt = 0; nt < 4; nt++) {
            int col = cg * 32 + nt * 8 + kq;
            float b0 = s_be2[col], b1 = s_be2[col + 1];
            float v00 = silu(c[mt][nt][0] + b0);
            float v01 = silu(c[mt][nt][1] + b1);
            float v10 = silu(c[mt][nt][2] + b0);
            float v11 = silu(c[mt][nt][3] + b1);
            __nv_bfloat162 h2, l2;
            split_pair(v00, v01, h2, l2);
            *(__nv_bfloat162*)(aHi + row0 * PITCHA + col) = h2;
            *(__nv_bfloat162*)(aLo + row0 * PITCHA + col) = l2;
            split_pair(v10, v11, h2, l2);
            *(__nv_bfloat162*)(aHi + row1 * PITCHA + col) = h2;
            *(__nv_bfloat162*)(aLo + row1 * PITCHA + col) = l2;
            if (v0) red_add_v2(&g_mi[n0 * D + col], v00, v01);
            if (v1) red_add_v2(&g_mi[n1 * D + col], v10, v11);
            c[mt][nt][0] = c[mt][nt][1] = c[mt][nt][2] = c[mt][nt][3] = 0.f;
        }
    }
    __syncthreads();

    // ============ LAYER 3: m_ij @ Wc1 -> per-edge weight ============
    gemm_tile64(c, aHi_addr, 24, cg, rg, lane);
    __syncthreads();
    #pragma unroll
    for (int mt = 0; mt < 2; mt++) {
        float p0 = 0.f, p1 = 0.f;
        #pragma unroll
        for (int nt = 0; nt < 4; nt++) {
            int col = cg * 32 + nt * 8 + kq;
            float b0 = s_bc1[col], b1 = s_bc1[col + 1];
            float w0 = s_wc2[col], w1 = s_wc2[col + 1];
            p0 = fmaf(silu(c[mt][nt][0] + b0), w0, p0);
            p0 = fmaf(silu(c[mt][nt][1] + b1), w1, p0);
            p1 = fmaf(silu(c[mt][nt][2] + b0), w0, p1);
            p1 = fmaf(silu(c[mt][nt][3] + b1), w1, p1);
        }
        p0 += __shfl_xor_sync(0xffffffffu, p0, 1);
        p0 += __shfl_xor_sync(0xffffffffu, p0, 2);
        p1 += __shfl_xor_sync(0xffffffffu, p1, 1);
        p1 += __shfl_xor_sync(0xffffffffu, p1, 2);
        if ((lane & 3) == 0) {
            int row0 = rg * 32 + mt * 16 + q;
            s_wp[row0 * 4 + cg]       = p0;
            s_wp[(row0 + 8) * 4 + cg] = p1;
        }
    }
    __syncthreads();

    if (t < 64 && (e0 + t) < N_EDGES) {
        float w = s_wp[t * 4] + s_wp[t * 4 + 1] + s_wp[t * 4 + 2] + s_wp[t * 4 + 3] + bc2[0];
        int rr = s_r[t];
        atomicAdd(&coord_out[rr * 3 + 0], s_diff[t * 3 + 0] * w);
        atomicAdd(&coord_out[rr * 3 + 1], s_diff[t * 3 + 1] * w);
        atomicAdd(&coord_out[rr * 3 + 2], s_diff[t * 3 + 2] * w);
    }
}

// ---------------------------------------------------------------------------
// node_post: HMMA. [h,m_i]@Wn1 -> silu -> @Wn2  (verified R9-R12)
__global__ __launch_bounds__(256, 2) void node_post_kernel(
    const float* __restrict__ h,
    const float* __restrict__ bn1, const float* __restrict__ bn2,
    float* __restrict__ h_out)
{
    extern __shared__ __align__(16) char smem[];
    __nv_bfloat16* aHi = (__nv_bfloat16*)smem;
    __nv_bfloat16* aLo = aHi + PLANE;
    float* s_bn1 = (float*)(smem + 69632);
    float* s_bn2 = s_bn1 + 128;

    int t = threadIdx.x;
    int lane = t & 31, wid = t >> 5;
    int cg = wid & 3, rg = wid >> 2;
    int n0 = blockIdx.x * 128;
    uint32_t aHi_addr = smem_u32(aHi);

    if (t < 128) { s_bn1[t] = bn1[t]; s_bn2[t] = bn2[t]; }

    float c[4][4][4];
    #pragma unroll
    for (int mt = 0; mt < 4; mt++)
        #pragma unroll
        for (int nt = 0; nt < 4; nt++)
            #pragma unroll
            for (int j = 0; j < 4; j++) c[mt][nt][j] = 0.f;

    int q = lane >> 2;
    int kq = 2 * (lane & 3);

    auto stage_rows = [&](const float* base) {
        int r = t >> 1;
        int node = n0 + r; if (node >= N_NODES) node = N_NODES - 1;
        int ch = (t & 1) * 64;
        const float* src = base + node * D + ch;
        __nv_bfloat16* ph = aHi + r * PITCHA + ch;
        __nv_bfloat16* pl = aLo + r * PITCHA + ch;
        #pragma unroll
        for (int j = 0; j < 16; j++) {
            float4 v = *(const float4*)(src + 4 * j);
            __nv_bfloat162 h2a, l2a, h2b, l2b;
            split_pair(v.x, v.y, h2a, l2a);
            split_pair(v.z, v.w, h2b, l2b);
            *(__nv_bfloat162*)(ph + 4 * j)     = h2a;
            *(__nv_bfloat162*)(ph + 4 * j + 2) = h2b;
            *(__nv_bfloat162*)(pl + 4 * j)     = l2a;
            *(__nv_bfloat162*)(pl + 4 * j + 2) = l2b;
        }
    };

    stage_rows(h);
    __syncthreads();
    gemm_tile(c, aHi_addr, 32, cg, rg, lane);
    __syncthreads();
    stage_rows(g_mi);
    __syncthreads();
    gemm_tile(c, aHi_addr, 40, cg, rg, lane);
    __syncthreads();

    #pragma unroll
    for (int mt = 0; mt < 4; mt++) {
        int row0 = rg * 64 + mt * 16 + q;
        int row1 = row0 + 8;
        #pragma unroll
        for (int nt = 0; nt < 4; nt++) {
            int col = cg * 32 + nt * 8 + kq;
            float b0 = s_bn1[col], b1 = s_bn1[col + 1];
            float v00 = silu(c[mt][nt][0] + b0);
            float v01 = silu(c[mt][nt][1] + b1);
            float v10 = silu(c[mt][nt][2] + b0);
            float v11 = silu(c[mt][nt][3] + b1);
            __nv_bfloat162 h2, l2;
            split_pair(v00, v01, h2, l2);
            *(__nv_bfloat162*)(aHi + row0 * PITCHA + col) = h2;
            *(__nv_bfloat162*)(aLo + row0 * PITCHA + col) = l2;
            split_pair(v10, v11, h2, l2);
            *(__nv_bfloat162*)(aHi + row1 * PITCHA + col) = h2;
            *(__nv_bfloat162*)(aLo + row1 * PITCHA + col) = l2;
            c[mt][nt][0] = c[mt][nt][1] = c[mt][nt][2] = c[mt][nt][3] = 0.f;
        }
    }
    __syncthreads();

    gemm_tile(c, aHi_addr, 48, cg, rg, lane);

    #pragma unroll
    for (int mt = 0; mt < 4; mt++) {
        int row0 = rg * 64 + mt * 16 + q;
        int row1 = row0 + 8;
        bool v0 = (n0 + row0) < N_NODES, v1 = (n0 + row1) < N_NODES;
        #pragma unroll
        for (int nt = 0; nt < 4; nt++) {
            int col = cg * 32 + nt * 8 + kq;
            float b0 = s_bn2[col], b1 = s_bn2[col + 1];
            if (v0) {
                float2 o = make_float2(c[mt][nt][0] + b0, c[mt][nt][1] + b1);
                *(float2*)&h_out[(n0 + row0) * D + col] = o;
            }
            if (v1) {
                float2 o = make_float2(c[mt][nt][2] + b0, c[mt][nt][3] + b1);
                *(float2*)&h_out[(n0 + row1) * D + col] = o;
            }
        }
    }
}

// ---------------------------------------------------------------------------
extern "C" void kernel_launch(void* const* d_in, const int* in_sizes, int n_in,
                              void* d_out, int out_size)
{
    const float* h     = (const float*)d_in[0];
    const float* coord = (const float*)d_in[1];
    const float* vel   = (const float*)d_in[2];
    const int*   ei    = (const int*)  d_in[3];
    const float* We1 = (const float*)d_in[4];  const float* be1 = (const float*)d_in[5];
    const float* We2 = (const float*)d_in[6];  const float* be2 = (const float*)d_in[7];
    const float* Wc1 = (const float*)d_in[8];  const float* bc1 = (const float*)d_in[9];
    const float* Wc2 = (const float*)d_in[10]; const float* bc2 = (const float*)d_in[11];
    const float* Wv1 = (const float*)d_in[12]; const float* bv1 = (const float*)d_in[13];
    const float* Wv2 = (const float*)d_in[14]; const float* bv2 = (const float*)d_in[15];
    const float* Wn1 = (const float*)d_in[16]; const float* bn1 = (const float*)d_in[17];
    const float* Wn2 = (const float*)d_in[18]; const float* bn2 = (const float*)d_in[19];

    float* h_out     = (float*)d_out;                  // [N, 128]
    float* coord_out = (float*)d_out + N_NODES * D;    // [N, 3]

    cudaFuncSetAttribute(edge_kernel, cudaFuncAttributeMaxDynamicSharedMemorySize, EDGE_SMEM);
    cudaFuncSetAttribute(node_post_kernel, cudaFuncAttributeMaxDynamicSharedMemorySize, BIG_SMEM);
    cudaFuncSetAttribute(pab_kernel, cudaFuncAttributeMaxDynamicSharedMemorySize, BIG_SMEM);

    int edge_blocks = (N_EDGES + 63) / 64;
    int nblk128 = (N_NODES + 127) / 128;

    zero_mi_kernel<<<(N_NODES * D / 4 + 255) / 256, 256>>>();
    prep_bimg_kernel<<<(64 * 16 * 32 + 255) / 256, 256>>>(We1, We2, Wc1, Wn1, Wn2, Wv1);
    pab_kernel<<<nblk128, 256, BIG_SMEM>>>(h, be1, coord, vel, bv1, Wv2, bv2, coord_out);
    edge_kernel<<<edge_blocks, 256, EDGE_SMEM>>>(coord, ei,
                                                 be2, bc1, Wc2, bc2, We1, coord_out);
    node_post_kernel<<<nblk128, 256, BIG_SMEM>>>(h, bn1, bn2, h_out);
}